// round 1
// baseline (speedup 1.0000x reference)
#include <cuda_runtime.h>

#define HD   128
#define HD4  32
#define MAXN 50000
#define MAXE 800000

// ---------------- scratch (static device globals; no runtime alloc) ----------
static __device__ float  g_B[6][(size_t)MAXN * HD];   // 6 ping-pong N x 128 buffers
static __device__ float4 g_eanode[MAXN];              // (top0, top1, bot0, bot1)
static __device__ float  g_att0[MAXE];
static __device__ float  g_att1[MAXE];
static __device__ float  g_degu[MAXN];                // unweighted dinv
static __device__ float  g_degc[MAXN];
static __device__ float  g_dego[MAXN];
static __device__ float  g_sum[HD];
static __device__ float  g_sq[HD];
static __device__ float  g_Wf[HD * HD];               // folded weight (also used [128,10])
static __device__ float  g_bfold[HD];                 // folded bias

// ---------------- BN statistics ---------------------------------------------
__global__ void k_zero_stats() {
    int t = threadIdx.x;
    if (t < HD) { g_sum[t] = 0.f; g_sq[t] = 0.f; }
}

__global__ void k_stats(const float* __restrict__ X, int N) {
    __shared__ float ss[HD], sq[HD];
    int t = threadIdx.x;
    if (t < HD) { ss[t] = 0.f; sq[t] = 0.f; }
    __syncthreads();
    int total  = N * HD4;
    int stride = blockDim.x * gridDim.x;           // multiple of 32
    int idx    = blockIdx.x * blockDim.x + t;
    int fb     = (idx & 31) * 4;                   // fixed feature base per thread
    float a0=0,a1=0,a2=0,a3=0,q0=0,q1=0,q2=0,q3=0;
    for (; idx < total; idx += stride) {
        float4 v = ((const float4*)X)[idx];
        a0 += v.x; q0 += v.x * v.x;
        a1 += v.y; q1 += v.y * v.y;
        a2 += v.z; q2 += v.z * v.z;
        a3 += v.w; q3 += v.w * v.w;
    }
    atomicAdd(&ss[fb+0], a0); atomicAdd(&sq[fb+0], q0);
    atomicAdd(&ss[fb+1], a1); atomicAdd(&sq[fb+1], q1);
    atomicAdd(&ss[fb+2], a2); atomicAdd(&sq[fb+2], q2);
    atomicAdd(&ss[fb+3], a3); atomicAdd(&sq[fb+3], q3);
    __syncthreads();
    if (t < HD) { atomicAdd(&g_sum[t], ss[t]); atomicAdd(&g_sq[t], sq[t]); }
}

// Fold BN into weights: Wf[k,j] = rstd[k]*W[k,j];
// bf[j] = b[j] + sum_k (1e-4 - mu[k]*rstd[k]) * W[k,j]
__global__ void k_fold(const float* __restrict__ W, const float* __restrict__ b,
                       int Jc, float invN) {
    __shared__ float scale[HD], shift[HD];
    int t = threadIdx.x;   // launched with exactly 128 threads
    {
        float mu  = g_sum[t] * invN;
        float var = fmaxf(g_sq[t] * invN - mu * mu, 0.f);
        float rs  = rsqrtf(var + 1e-5f);
        scale[t]  = rs;
        shift[t]  = 1e-4f - mu * rs;
    }
    __syncthreads();
    for (int j = t; j < Jc; j += HD) {
        float acc = b ? b[j] : 0.f;
        for (int k = 0; k < HD; k++) {
            float w = W[k * Jc + j];
            g_Wf[k * Jc + j] = scale[k] * w;
            acc += shift[k] * w;
        }
        g_bfold[j] = acc;
    }
}

// ---------------- GEMM: Y = act(X @ g_Wf + g_bfold), [N,128]x[128,128] -------
__global__ void __launch_bounds__(256) k_gemm(const float* __restrict__ X,
                                              float* __restrict__ Y,
                                              int N, int do_relu) {
    extern __shared__ float sm[];
    float* Ws = sm;              // 128*128 floats
    float* Hs = sm + HD * HD;    // 64*128 floats
    int t = threadIdx.x;
    int w = t >> 5, l = t & 31;
    for (int i = t; i < HD * HD4; i += 256)
        ((float4*)Ws)[i] = ((const float4*)g_Wf)[i];
    int rowBase = blockIdx.x * 64;
    for (int i = t; i < 64 * HD4; i += 256) {
        int r = i >> 5, c = i & 31;
        int gr = rowBase + r;
        float4 v = make_float4(0.f, 0.f, 0.f, 0.f);
        if (gr < N) v = ((const float4*)X)[gr * HD4 + c];
        ((float4*)Hs)[i] = v;
    }
    __syncthreads();
    float acc[8][4];
#pragma unroll
    for (int r = 0; r < 8; r++) { acc[r][0]=0.f; acc[r][1]=0.f; acc[r][2]=0.f; acc[r][3]=0.f; }
    const float* hrow = Hs + (w * 8) * HD;
#pragma unroll 8
    for (int k = 0; k < HD; k++) {
        float4 wv = ((float4*)Ws)[k * HD4 + l];
#pragma unroll
        for (int r = 0; r < 8; r++) {
            float hv = hrow[r * HD + k];
            acc[r][0] += hv * wv.x;
            acc[r][1] += hv * wv.y;
            acc[r][2] += hv * wv.z;
            acc[r][3] += hv * wv.w;
        }
    }
    float4 bb = ((const float4*)g_bfold)[l];
#pragma unroll
    for (int r = 0; r < 8; r++) {
        int gr = rowBase + w * 8 + r;
        if (gr < N) {
            float4 o;
            o.x = acc[r][0] + bb.x; o.y = acc[r][1] + bb.y;
            o.z = acc[r][2] + bb.z; o.w = acc[r][3] + bb.w;
            if (do_relu) {
                o.x = fmaxf(o.x, 0.f); o.y = fmaxf(o.y, 0.f);
                o.z = fmaxf(o.z, 0.f); o.w = fmaxf(o.w, 0.f);
            }
            ((float4*)Y)[gr * HD4 + l] = o;
        }
    }
}

// ---------------- degree / aggregation helpers ------------------------------
__global__ void k_fill(float* p, float v, int n) {
    int i = blockIdx.x * blockDim.x + threadIdx.x;
    if (i < n) p[i] = v;
}

__global__ void k_deg_unw(const int* __restrict__ row, int E, float* deg) {
    int e = blockIdx.x * blockDim.x + threadIdx.x;
    if (e < E) atomicAdd(&deg[row[e]], 1.f);
}

__global__ void k_rsqrt(float* p, int n) {
    int i = blockIdx.x * blockDim.x + threadIdx.x;
    if (i < n) p[i] = rsqrtf(p[i]);
}

// out[i,:] = lin[i,:] * dinv[i]^2   (self-loop term, also initializes out)
__global__ void k_selfinit(const float* __restrict__ lin,
                           const float* __restrict__ dinv,
                           float* __restrict__ out, int N) {
    int idx = blockIdx.x * blockDim.x + threadIdx.x;
    if (idx >= N * HD4) return;
    int i = idx >> 5;
    float d = dinv[i];
    float s = d * d;
    float4 v = ((const float4*)lin)[idx];
    v.x *= s; v.y *= s; v.z *= s; v.w *= s;
    ((float4*)out)[idx] = v;
}

// out[col[e],:] += lin[row[e],:] * dinv[row]*w*dinv[col]  -- warp per edge
__global__ void k_edge_agg(const float* __restrict__ lin, float* __restrict__ out,
                           const int* __restrict__ row, const int* __restrict__ col,
                           const float* __restrict__ dinv,
                           const float* __restrict__ ew, int E) {
    int gw = (blockIdx.x * blockDim.x + threadIdx.x) >> 5;
    int l  = threadIdx.x & 31;
    if (gw >= E) return;
    int r = row[gw], c = col[gw];
    float wgt = ew ? ew[gw] : 1.f;
    float nrm = dinv[r] * wgt * dinv[c];
    float4 v  = ((const float4*)lin)[r * HD4 + l];
    float* o  = out + c * HD + l * 4;
    atomicAdd(o + 0, v.x * nrm);
    atomicAdd(o + 1, v.y * nrm);
    atomicAdd(o + 2, v.z * nrm);
    atomicAdd(o + 3, v.w * nrm);
}

__global__ void k_bias_relu(const float* __restrict__ in, float* __restrict__ out,
                            const float* __restrict__ b, int N) {
    int idx = blockIdx.x * blockDim.x + threadIdx.x;
    if (idx >= N * HD4) return;
    float4 v  = ((const float4*)in)[idx];
    float4 bb = ((const float4*)b)[idx & 31];
    v.x = fmaxf(v.x + bb.x, 0.f); v.y = fmaxf(v.y + bb.y, 0.f);
    v.z = fmaxf(v.z + bb.z, 0.f); v.w = fmaxf(v.w + bb.w, 0.f);
    ((float4*)out)[idx] = v;
}

// ---------------- attention --------------------------------------------------
// per node: 6 dots of h with [W_na | W_ea_top | W_ea_bot]; node softmax splits
// h into xc/xo; ea projections stored for the edge kernel.
__global__ void k_att_node(const float* __restrict__ h,
                           const float* __restrict__ Wna, const float* __restrict__ bna,
                           const float* __restrict__ Wea,
                           float* __restrict__ xc, float* __restrict__ xo, int N) {
    __shared__ float Wc[HD * 6];
    int t = threadIdx.x;
    for (int i = t; i < HD * 6; i += blockDim.x) {
        int k = i / 6, j = i % 6;
        float v;
        if (j < 2)      v = Wna[k * 2 + j];
        else if (j < 4) v = Wea[k * 2 + (j - 2)];
        else            v = Wea[(HD + k) * 2 + (j - 4)];
        Wc[i] = v;
    }
    __syncthreads();
    int warps = (blockDim.x * gridDim.x) >> 5;
    int gw = (blockIdx.x * blockDim.x + t) >> 5;
    int l  = t & 31;
    float b0 = bna[0], b1 = bna[1];
    for (int i = gw; i < N; i += warps) {
        float4 hv = ((const float4*)h)[i * HD4 + l];
        float p[6];
#pragma unroll
        for (int j = 0; j < 6; j++) {
            p[j] = hv.x * Wc[(4*l+0)*6 + j] + hv.y * Wc[(4*l+1)*6 + j]
                 + hv.z * Wc[(4*l+2)*6 + j] + hv.w * Wc[(4*l+3)*6 + j];
        }
#pragma unroll
        for (int off = 16; off; off >>= 1)
#pragma unroll
            for (int j = 0; j < 6; j++)
                p[j] += __shfl_xor_sync(0xffffffffu, p[j], off);
        float l0 = p[0] + b0, l1 = p[1] + b1;
        float m  = fmaxf(l0, l1);
        float e0 = expf(l0 - m), e1 = expf(l1 - m);
        float inv = 1.f / (e0 + e1);
        float a0 = e0 * inv, a1 = e1 * inv;
        ((float4*)xc)[i * HD4 + l] = make_float4(hv.x*a0, hv.y*a0, hv.z*a0, hv.w*a0);
        ((float4*)xo)[i * HD4 + l] = make_float4(hv.x*a1, hv.y*a1, hv.z*a1, hv.w*a1);
        if (l == 0) g_eanode[i] = make_float4(p[2], p[3], p[4], p[5]);
    }
}

__global__ void k_att_edge(const int* __restrict__ row, const int* __restrict__ col,
                           const float* __restrict__ bea, int E) {
    int e = blockIdx.x * blockDim.x + threadIdx.x;
    if (e >= E) return;
    int r = row[e], c = col[e];
    float4 tr = g_eanode[r], tc = g_eanode[c];
    float l0 = tr.x + tc.z + bea[0];
    float l1 = tr.y + tc.w + bea[1];
    float m  = fmaxf(l0, l1);
    float e0 = expf(l0 - m), e1 = expf(l1 - m);
    float inv = 1.f / (e0 + e1);
    float a0 = e0 * inv, a1 = e1 * inv;
    g_att0[e] = a0;
    g_att1[e] = a1;
    atomicAdd(&g_degc[r], a0);
    atomicAdd(&g_dego[r], a1);
}

// z[i,:] = xc[perm[i],:] + xo[i,:]
__global__ void k_permadd(const float* __restrict__ xc, const float* __restrict__ xo,
                          const int* __restrict__ perm, float* __restrict__ z, int N) {
    int idx = blockIdx.x * blockDim.x + threadIdx.x;
    if (idx >= N * HD4) return;
    int i = idx >> 5, l = idx & 31;
    int p = perm[i];
    float4 a = ((const float4*)xc)[p * HD4 + l];
    float4 b = ((const float4*)xo)[idx];
    a.x += b.x; a.y += b.y; a.z += b.z; a.w += b.w;
    ((float4*)z)[idx] = a;
}

// ---------------- [N,128]x[128,10] + log_softmax (warp per row) --------------
__global__ void k_gemm2_lsm(const float* __restrict__ Z, float* __restrict__ out, int N) {
    __shared__ float Ws[HD * 10];
    __shared__ float bs[10];
    int t = threadIdx.x;
    for (int i = t; i < HD * 10; i += blockDim.x) Ws[i] = g_Wf[i];
    if (t < 10) bs[t] = g_bfold[t];
    __syncthreads();
    int warps = (blockDim.x * gridDim.x) >> 5;
    int gw = (blockIdx.x * blockDim.x + t) >> 5;
    int l  = t & 31;
    for (int i = gw; i < N; i += warps) {
        float4 z = ((const float4*)Z)[i * HD4 + l];
        float p[10];
#pragma unroll
        for (int j = 0; j < 10; j++) {
            p[j] = z.x * Ws[(4*l+0)*10 + j] + z.y * Ws[(4*l+1)*10 + j]
                 + z.z * Ws[(4*l+2)*10 + j] + z.w * Ws[(4*l+3)*10 + j];
        }
#pragma unroll
        for (int off = 16; off; off >>= 1)
#pragma unroll
            for (int j = 0; j < 10; j++)
                p[j] += __shfl_xor_sync(0xffffffffu, p[j], off);
        float m = -1e30f;
#pragma unroll
        for (int j = 0; j < 10; j++) { p[j] += bs[j]; m = fmaxf(m, p[j]); }
        float s = 0.f;
#pragma unroll
        for (int j = 0; j < 10; j++) s += expf(p[j] - m);
        float lse = m + logf(s);
        if (l < 10) out[i * 10 + l] = p[l] - lse;
    }
}

// ---------------- host orchestration -----------------------------------------
extern "C" void kernel_launch(void* const* d_in, const int* in_sizes, int n_in,
                              void* d_out, int out_size) {
    const float* x      = (const float*)d_in[0];
    const int*   ei     = (const int*)  d_in[1];
    const int*   perm   = (const int*)  d_in[2];
    const float* W_feat = (const float*)d_in[3];
    const float* b_feat = (const float*)d_in[4];
    const float* W_convs= (const float*)d_in[5];
    const float* b_convs= (const float*)d_in[6];
    const float* W_ea   = (const float*)d_in[7];
    const float* b_ea   = (const float*)d_in[8];
    const float* W_na   = (const float*)d_in[9];
    const float* b_na   = (const float*)d_in[10];
    const float* W_ctx  = (const float*)d_in[11];
    const float* b_ctx  = (const float*)d_in[12];
    const float* W_obj  = (const float*)d_in[13];
    const float* b_obj  = (const float*)d_in[14];
    const float* W_fc1  = (const float*)d_in[15];
    const float* b_fc1  = (const float*)d_in[16];
    const float* W_fc2  = (const float*)d_in[17];
    const float* b_fc2  = (const float*)d_in[18];

    int N = in_sizes[0] / HD;
    int E = in_sizes[1] / 2;
    const int* row = ei;
    const int* col = ei + E;
    float* out = (float*)d_out;

    float* Bbase = nullptr;
    cudaGetSymbolAddress((void**)&Bbase, g_B);
    float* B0 = Bbase + 0 * (size_t)MAXN * HD;
    float* B1 = Bbase + 1 * (size_t)MAXN * HD;
    float* B2 = Bbase + 2 * (size_t)MAXN * HD;
    float* B3 = Bbase + 3 * (size_t)MAXN * HD;
    float* B4 = Bbase + 4 * (size_t)MAXN * HD;
    float* B5 = Bbase + 5 * (size_t)MAXN * HD;
    float *att0p, *att1p, *degup, *degcp, *degop;
    cudaGetSymbolAddress((void**)&att0p, g_att0);
    cudaGetSymbolAddress((void**)&att1p, g_att1);
    cudaGetSymbolAddress((void**)&degup, g_degu);
    cudaGetSymbolAddress((void**)&degcp, g_degc);
    cudaGetSymbolAddress((void**)&degop, g_dego);

    const size_t gemm_smem = (size_t)(HD * HD + 64 * HD) * sizeof(float);
    cudaFuncSetAttribute(k_gemm, cudaFuncAttributeMaxDynamicSharedMemorySize,
                         (int)gemm_smem);

    int gbGemm = (N + 63) / 64;
    int gbElem = (N * HD4 + 255) / 256;
    int gbN    = (N + 255) / 256;
    int gbE    = (E + 255) / 256;
    int gbE32  = ((E * 32) + 255) / 256;
    float invN = 1.f / (float)N;

    auto stats_fold = [&](const float* X, const float* W, const float* b, int Jc) {
        k_zero_stats<<<1, 128>>>();
        k_stats<<<512, 256>>>(X, N);
        k_fold<<<1, 128>>>(W, b, Jc, invN);
    };
    auto gemm = [&](const float* X, float* Y, int relu) {
        k_gemm<<<gbGemm, 256, gemm_smem>>>(X, Y, N, relu);
    };
    // one GCN conv: X -> Y  (LIN = B1 scratch), with given dinv & edge weights
    auto conv = [&](const float* X, float* Y, const float* W, const float* b,
                    const float* ew, const float* dinv) {
        stats_fold(X, W, nullptr, HD);
        gemm(X, B1, 0);
        k_selfinit<<<gbElem, 256>>>(B1, dinv, Y, N);
        k_edge_agg<<<gbE32, 256>>>(B1, Y, row, col, dinv, ew, E);
        k_bias_relu<<<gbElem, 256>>>(Y, Y, b, N);
    };
    auto readout = [&](const float* Z, int i, float* op) {
        stats_fold(Z, W_fc1 + (size_t)i * HD * HD, b_fc1 + i * HD, HD);
        gemm(Z, B0, 1);                                   // t = relu(bn(Z)@W1+b1)
        stats_fold(B0, W_fc2 + (size_t)i * HD * 10, b_fc2 + i * 10, 10);
        k_gemm2_lsm<<<512, 256>>>(B0, op, N);
    };

    // stage 0: h = relu(bn(x) @ W_feat + b_feat)
    stats_fold(x, W_feat, b_feat, HD);
    gemm(x, B2, 1);                                       // h = B2 (start so rotation ends at B2)

    // unweighted symmetric degree (shared by the 3 convs)
    k_fill<<<gbN, 256>>>(degup, 1.f, N);
    k_deg_unw<<<gbE, 256>>>(row, E, degup);
    k_rsqrt<<<gbN, 256>>>(degup, N);

    conv(B2, B0, W_convs + 0 * HD * HD, b_convs + 0 * HD, nullptr, degup);
    conv(B0, B2, W_convs + 1 * HD * HD, b_convs + 1 * HD, nullptr, degup);
    conv(B2, B0, W_convs + 2 * HD * HD, b_convs + 2 * HD, nullptr, degup);
    // h = B0

    // attention: xc = B2, xo = B3 ; per-node ea projections into g_eanode
    k_att_node<<<512, 256>>>(B0, W_na, b_na, W_ea, B2, B3, N);
    k_fill<<<gbN, 256>>>(degcp, 1.f, N);
    k_fill<<<gbN, 256>>>(degop, 1.f, N);
    k_att_edge<<<gbE, 256>>>(row, col, b_ea, E);
    k_rsqrt<<<gbN, 256>>>(degcp, N);
    k_rsqrt<<<gbN, 256>>>(degop, N);

    // weighted convs: xc2 = B4, xo2 = B5
    conv(B2, B4, W_ctx, b_ctx, att0p, degcp);
    conv(B3, B5, W_obj, b_obj, att1p, degop);

    // readouts
    readout(B4, 0, out);                // xc_logis
    readout(B5, 1, out + (size_t)N * 10); // xo_logis
    k_permadd<<<gbElem, 256>>>(B4, B5, perm, B1, N);
    readout(B1, 2, out + (size_t)2 * N * 10); // xco_logis
}

// round 2
// speedup vs baseline: 1.0606x; 1.0606x over previous
#include <cuda_runtime.h>

#define HD   128
#define HD4  32
#define MAXN 50000
#define MAXE 800000
#define XS   132   // smem stride (words) for X tile (pad -> conflict-free A frags)
#define WSD  136   // smem stride (words) for W tile (pad -> conflict-free B frags)
#define NSLOT 12

// ---------------- scratch (static device globals; no runtime alloc) ----------
static __device__ float  g_B[6][(size_t)MAXN * HD];
static __device__ float4 g_eanode[MAXN];
static __device__ float  g_att0[MAXE];
static __device__ float  g_att1[MAXE];
static __device__ float  g_degu[MAXN];
static __device__ float  g_degc[MAXN];
static __device__ float  g_dego[MAXN];
static __device__ float  g_ssum[NSLOT * HD];
static __device__ float  g_ssq [NSLOT * HD];
static __device__ float  g_Wf[HD * HD];
static __device__ float  g_bfold[HD];

__device__ __forceinline__ unsigned f2tf(float f) {
    unsigned r; asm("cvt.rna.tf32.f32 %0, %1;" : "=r"(r) : "f"(f)); return r;
}

__device__ __forceinline__ void mma_tf32(float* c, const unsigned* a, const unsigned* b) {
    asm volatile(
        "mma.sync.aligned.m16n8k8.row.col.f32.tf32.tf32.f32 "
        "{%0,%1,%2,%3}, {%4,%5,%6,%7}, {%8,%9}, {%0,%1,%2,%3};"
        : "+f"(c[0]), "+f"(c[1]), "+f"(c[2]), "+f"(c[3])
        : "r"(a[0]), "r"(a[1]), "r"(a[2]), "r"(a[3]), "r"(b[0]), "r"(b[1]));
}

// ---------------- stats slots -------------------------------------------------
__global__ void k_zero_slots() {
    int i = blockIdx.x * blockDim.x + threadIdx.x;
    if (i < NSLOT * HD) { g_ssum[i] = 0.f; g_ssq[i] = 0.f; }
}

__global__ void k_stats(const float* __restrict__ X, int N,
                        float* __restrict__ sS, float* __restrict__ sQ) {
    __shared__ float ss[HD], sq[HD];
    int t = threadIdx.x;
    if (t < HD) { ss[t] = 0.f; sq[t] = 0.f; }
    __syncthreads();
    int total  = N * HD4;
    int stride = blockDim.x * gridDim.x;
    int idx    = blockIdx.x * blockDim.x + t;
    int fb     = (idx & 31) * 4;
    float a0=0,a1=0,a2=0,a3=0,q0=0,q1=0,q2=0,q3=0;
    for (; idx < total; idx += stride) {
        float4 v = ((const float4*)X)[idx];
        a0 += v.x; q0 += v.x * v.x;
        a1 += v.y; q1 += v.y * v.y;
        a2 += v.z; q2 += v.z * v.z;
        a3 += v.w; q3 += v.w * v.w;
    }
    atomicAdd(&ss[fb+0], a0); atomicAdd(&sq[fb+0], q0);
    atomicAdd(&ss[fb+1], a1); atomicAdd(&sq[fb+1], q1);
    atomicAdd(&ss[fb+2], a2); atomicAdd(&sq[fb+2], q2);
    atomicAdd(&ss[fb+3], a3); atomicAdd(&sq[fb+3], q3);
    __syncthreads();
    if (t < HD) { atomicAdd(&sS[t], ss[t]); atomicAdd(&sQ[t], sq[t]); }
}

// Fold BN into weights
__global__ void k_fold(const float* __restrict__ W, const float* __restrict__ b,
                       int Jc, float invN,
                       const float* __restrict__ sS, const float* __restrict__ sQ) {
    __shared__ float scale[HD], shift[HD];
    int t = threadIdx.x;   // 128 threads
    {
        float mu  = sS[t] * invN;
        float var = fmaxf(sQ[t] * invN - mu * mu, 0.f);
        float rs  = rsqrtf(var + 1e-5f);
        scale[t]  = rs;
        shift[t]  = 1e-4f - mu * rs;
    }
    __syncthreads();
    for (int j = t; j < Jc; j += HD) {
        float acc = b ? b[j] : 0.f;
        for (int k = 0; k < HD; k++) {
            float w = W[k * Jc + j];
            g_Wf[k * Jc + j] = scale[k] * w;
            acc += shift[k] * w;
        }
        g_bfold[j] = acc;
    }
}

// ---------------- tf32 tensor-core GEMM: Y = act(X @ g_Wf + g_bfold) ---------
__global__ void __launch_bounds__(256) k_gemm_tc(const float* __restrict__ X,
                                                 float* __restrict__ Y, int N,
                                                 int doRelu,
                                                 float* __restrict__ sS,
                                                 float* __restrict__ sQ) {
    extern __shared__ unsigned sh[];
    unsigned* Xs = sh;               // 128 x XS
    unsigned* Ws = sh + 128 * XS;    // 128 x WSD
    __shared__ float ssum[HD], ssq[HD];
    int t = threadIdx.x;
    if (t < HD) { ssum[t] = 0.f; ssq[t] = 0.f; }
    int base = blockIdx.x * 128;
    for (int i = t; i < 4096; i += 256) {
        int r = i >> 5, c = i & 31, gr = base + r;
        float4 v = make_float4(0.f, 0.f, 0.f, 0.f);
        if (gr < N) v = ((const float4*)X)[(size_t)gr * 32 + c];
        *(uint4*)&Xs[r * XS + c * 4] =
            make_uint4(f2tf(v.x), f2tf(v.y), f2tf(v.z), f2tf(v.w));
    }
    for (int i = t; i < 4096; i += 256) {
        int r = i >> 5, c = i & 31;
        float4 v = ((const float4*)g_Wf)[i];
        *(uint4*)&Ws[r * WSD + c * 4] =
            make_uint4(f2tf(v.x), f2tf(v.y), f2tf(v.z), f2tf(v.w));
    }
    __syncthreads();

    int lane = t & 31, g = lane >> 2, tg = lane & 3, w = t >> 5;
    int rwb = (w >> 1) * 32;   // warp row base within tile
    int cwb = (w & 1) * 64;    // warp col base

    float acc[2][8][4];
#pragma unroll
    for (int m = 0; m < 2; m++)
#pragma unroll
        for (int nt = 0; nt < 8; nt++)
#pragma unroll
            for (int j = 0; j < 4; j++) acc[m][nt][j] = 0.f;

#pragma unroll 4
    for (int k0 = 0; k0 < 128; k0 += 8) {
        unsigned a[2][4], b[8][2];
#pragma unroll
        for (int m = 0; m < 2; m++) {
            int r0 = rwb + m * 16 + g;
            a[m][0] = Xs[r0 * XS + k0 + tg];
            a[m][1] = Xs[(r0 + 8) * XS + k0 + tg];
            a[m][2] = Xs[r0 * XS + k0 + tg + 4];
            a[m][3] = Xs[(r0 + 8) * XS + k0 + tg + 4];
        }
#pragma unroll
        for (int nt = 0; nt < 8; nt++) {
            int cc = cwb + nt * 8 + g;
            b[nt][0] = Ws[(k0 + tg) * WSD + cc];
            b[nt][1] = Ws[(k0 + tg + 4) * WSD + cc];
        }
#pragma unroll
        for (int m = 0; m < 2; m++)
#pragma unroll
            for (int nt = 0; nt < 8; nt++)
                mma_tf32(acc[m][nt], a[m], b[nt]);
    }

    // epilogue: bias, relu, store, fused stats
    float ls[8][2], lq[8][2];
#pragma unroll
    for (int nt = 0; nt < 8; nt++) { ls[nt][0]=0.f; ls[nt][1]=0.f; lq[nt][0]=0.f; lq[nt][1]=0.f; }

#pragma unroll
    for (int nt = 0; nt < 8; nt++) {
        int col = cwb + nt * 8 + 2 * tg;
        float bx = g_bfold[col], by = g_bfold[col + 1];
#pragma unroll
        for (int m = 0; m < 2; m++) {
            int r0 = base + rwb + m * 16 + g;
            int r1 = r0 + 8;
            float y00 = acc[m][nt][0] + bx, y01 = acc[m][nt][1] + by;
            float y10 = acc[m][nt][2] + bx, y11 = acc[m][nt][3] + by;
            if (doRelu) {
                y00 = fmaxf(y00, 0.f); y01 = fmaxf(y01, 0.f);
                y10 = fmaxf(y10, 0.f); y11 = fmaxf(y11, 0.f);
            }
            if (r0 < N) {
                ((float2*)Y)[(size_t)r0 * 64 + (col >> 1)] = make_float2(y00, y01);
                ls[nt][0] += y00; lq[nt][0] += y00 * y00;
                ls[nt][1] += y01; lq[nt][1] += y01 * y01;
            }
            if (r1 < N) {
                ((float2*)Y)[(size_t)r1 * 64 + (col >> 1)] = make_float2(y10, y11);
                ls[nt][0] += y10; lq[nt][0] += y10 * y10;
                ls[nt][1] += y11; lq[nt][1] += y11 * y11;
            }
        }
    }

    if (sS) {
#pragma unroll
        for (int off = 4; off <= 16; off <<= 1)
#pragma unroll
            for (int nt = 0; nt < 8; nt++)
#pragma unroll
                for (int j = 0; j < 2; j++) {
                    ls[nt][j] += __shfl_xor_sync(0xffffffffu, ls[nt][j], off);
                    lq[nt][j] += __shfl_xor_sync(0xffffffffu, lq[nt][j], off);
                }
        if (g == 0) {
#pragma unroll
            for (int nt = 0; nt < 8; nt++)
#pragma unroll
                for (int j = 0; j < 2; j++) {
                    int col = cwb + nt * 8 + 2 * tg + j;
                    atomicAdd(&ssum[col], ls[nt][j]);
                    atomicAdd(&ssq[col],  lq[nt][j]);
                }
        }
        __syncthreads();
        if (t < HD) { atomicAdd(&sS[t], ssum[t]); atomicAdd(&sQ[t], ssq[t]); }
    }
}

// ---------------- degree helpers ---------------------------------------------
__global__ void k_fill(float* p, float v, int n) {
    int i = blockIdx.x * blockDim.x + threadIdx.x;
    if (i < n) p[i] = v;
}
__global__ void k_deg_unw(const int* __restrict__ row, int E, float* deg) {
    int e = blockIdx.x * blockDim.x + threadIdx.x;
    if (e < E) atomicAdd(&deg[row[e]], 1.f);
}
__global__ void k_rsqrt(float* p, int n) {
    int i = blockIdx.x * blockDim.x + threadIdx.x;
    if (i < n) p[i] = rsqrtf(p[i]);
}

// ---------------- edge aggregation --------------------------------------------
__global__ void k_edge_agg(const float* __restrict__ lin, float* __restrict__ out,
                           const int* __restrict__ row, const int* __restrict__ col,
                           const float* __restrict__ dinv, int E) {
    int gw = (blockIdx.x * blockDim.x + threadIdx.x) >> 5;
    int l  = threadIdx.x & 31;
    if (gw >= E) return;
    int r = row[gw], c = col[gw];
    float nrm = dinv[r] * dinv[c];
    float4 v  = ((const float4*)lin)[(size_t)r * HD4 + l];
    float* o  = out + (size_t)c * HD + l * 4;
    atomicAdd(o + 0, v.x * nrm);
    atomicAdd(o + 1, v.y * nrm);
    atomicAdd(o + 2, v.z * nrm);
    atomicAdd(o + 3, v.w * nrm);
}

// merged ctx/obj weighted aggregation (shared indices)
__global__ void k_edge_agg2(const float* __restrict__ linC, const float* __restrict__ linO,
                            float* __restrict__ outC, float* __restrict__ outO,
                            const int* __restrict__ row, const int* __restrict__ col,
                            const float* __restrict__ dc, const float* __restrict__ dd,
                            int E) {
    int gw = (blockIdx.x * blockDim.x + threadIdx.x) >> 5;
    int l  = threadIdx.x & 31;
    if (gw >= E) return;
    int r = row[gw], c = col[gw];
    float nc = dc[r] * g_att0[gw] * dc[c];
    float no = dd[r] * g_att1[gw] * dd[c];
    float4 vc = ((const float4*)linC)[(size_t)r * HD4 + l];
    float4 vo = ((const float4*)linO)[(size_t)r * HD4 + l];
    float* oc = outC + (size_t)c * HD + l * 4;
    float* oo = outO + (size_t)c * HD + l * 4;
    atomicAdd(oc + 0, vc.x * nc); atomicAdd(oc + 1, vc.y * nc);
    atomicAdd(oc + 2, vc.z * nc); atomicAdd(oc + 3, vc.w * nc);
    atomicAdd(oo + 0, vo.x * no); atomicAdd(oo + 1, vo.y * no);
    atomicAdd(oo + 2, vo.z * no); atomicAdd(oo + 3, vo.w * no);
}

// out = relu(agg + lin*dinv^2 + b); fused BN stats of output (optional)
__global__ void k_bias_relu_stats(float* __restrict__ out, const float* __restrict__ lin,
                                  const float* __restrict__ dinv,
                                  const float* __restrict__ b, int N,
                                  float* __restrict__ sS, float* __restrict__ sQ) {
    __shared__ float ssum[HD], ssq[HD];
    int t = threadIdx.x;
    if (t < HD) { ssum[t] = 0.f; ssq[t] = 0.f; }
    __syncthreads();
    int total  = N * HD4;
    int stride = blockDim.x * gridDim.x;
    int idx    = blockIdx.x * blockDim.x + t;
    int fb     = (idx & 31) * 4;
    float4 bb  = ((const float4*)b)[idx & 31];
    float a0=0,a1=0,a2=0,a3=0,q0=0,q1=0,q2=0,q3=0;
    for (; idx < total; idx += stride) {
        int i = idx >> 5;
        float d = dinv[i]; float s = d * d;
        float4 v = ((const float4*)out)[idx];
        float4 u = ((const float4*)lin)[idx];
        v.x = fmaxf(v.x + u.x * s + bb.x, 0.f);
        v.y = fmaxf(v.y + u.y * s + bb.y, 0.f);
        v.z = fmaxf(v.z + u.z * s + bb.z, 0.f);
        v.w = fmaxf(v.w + u.w * s + bb.w, 0.f);
        ((float4*)out)[idx] = v;
        a0 += v.x; q0 += v.x*v.x; a1 += v.y; q1 += v.y*v.y;
        a2 += v.z; q2 += v.z*v.z; a3 += v.w; q3 += v.w*v.w;
    }
    if (sS) {
        atomicAdd(&ssum[fb+0], a0); atomicAdd(&ssq[fb+0], q0);
        atomicAdd(&ssum[fb+1], a1); atomicAdd(&ssq[fb+1], q1);
        atomicAdd(&ssum[fb+2], a2); atomicAdd(&ssq[fb+2], q2);
        atomicAdd(&ssum[fb+3], a3); atomicAdd(&ssq[fb+3], q3);
        __syncthreads();
        if (t < HD) { atomicAdd(&sS[t], ssum[t]); atomicAdd(&sQ[t], ssq[t]); }
    }
}

// ---------------- attention ----------------------------------------------------
__global__ void k_att_node(const float* __restrict__ h,
                           const float* __restrict__ Wna, const float* __restrict__ bna,
                           const float* __restrict__ Wea,
                           float* __restrict__ xc, float* __restrict__ xo, int N,
                           float* sSc, float* sQc, float* sSo, float* sQo) {
    __shared__ float Wc[HD * 6];
    __shared__ float red[4][HD];
    int t = threadIdx.x;
    for (int i = t; i < HD * 6; i += blockDim.x) {
        int k = i / 6, j = i % 6;
        float v;
        if (j < 2)      v = Wna[k * 2 + j];
        else if (j < 4) v = Wea[k * 2 + (j - 2)];
        else            v = Wea[(HD + k) * 2 + (j - 4)];
        Wc[i] = v;
    }
    for (int i = t; i < 4 * HD; i += blockDim.x) ((float*)red)[i] = 0.f;
    __syncthreads();
    int warps = (blockDim.x * gridDim.x) >> 5;
    int gw = (blockIdx.x * blockDim.x + t) >> 5;
    int l  = t & 31;
    float b0 = bna[0], b1 = bna[1];
    float sc[4]={0,0,0,0}, qc[4]={0,0,0,0}, so[4]={0,0,0,0}, qo[4]={0,0,0,0};
    for (int i = gw; i < N; i += warps) {
        float4 hv = ((const float4*)h)[(size_t)i * HD4 + l];
        float p[6];
#pragma unroll
        for (int j = 0; j < 6; j++) {
            p[j] = hv.x * Wc[(4*l+0)*6 + j] + hv.y * Wc[(4*l+1)*6 + j]
                 + hv.z * Wc[(4*l+2)*6 + j] + hv.w * Wc[(4*l+3)*6 + j];
        }
#pragma unroll
        for (int off = 16; off; off >>= 1)
#pragma unroll
            for (int j = 0; j < 6; j++)
                p[j] += __shfl_xor_sync(0xffffffffu, p[j], off);
        float l0 = p[0] + b0, l1 = p[1] + b1;
        float m  = fmaxf(l0, l1);
        float e0 = expf(l0 - m), e1 = expf(l1 - m);
        float inv = 1.f / (e0 + e1);
        float a0 = e0 * inv, a1 = e1 * inv;
        float4 vc = make_float4(hv.x*a0, hv.y*a0, hv.z*a0, hv.w*a0);
        float4 vo = make_float4(hv.x*a1, hv.y*a1, hv.z*a1, hv.w*a1);
        ((float4*)xc)[(size_t)i * HD4 + l] = vc;
        ((float4*)xo)[(size_t)i * HD4 + l] = vo;
        sc[0]+=vc.x; qc[0]+=vc.x*vc.x; sc[1]+=vc.y; qc[1]+=vc.y*vc.y;
        sc[2]+=vc.z; qc[2]+=vc.z*vc.z; sc[3]+=vc.w; qc[3]+=vc.w*vc.w;
        so[0]+=vo.x; qo[0]+=vo.x*vo.x; so[1]+=vo.y; qo[1]+=vo.y*vo.y;
        so[2]+=vo.z; qo[2]+=vo.z*vo.z; so[3]+=vo.w; qo[3]+=vo.w*vo.w;
        if (l == 0) g_eanode[i] = make_float4(p[2], p[3], p[4], p[5]);
    }
#pragma unroll
    for (int j = 0; j < 4; j++) {
        atomicAdd(&red[0][l*4+j], sc[j]);
        atomicAdd(&red[1][l*4+j], qc[j]);
        atomicAdd(&red[2][l*4+j], so[j]);
        atomicAdd(&red[3][l*4+j], qo[j]);
    }
    __syncthreads();
    if (t < HD) {
        atomicAdd(&sSc[t], red[0][t]); atomicAdd(&sQc[t], red[1][t]);
        atomicAdd(&sSo[t], red[2][t]); atomicAdd(&sQo[t], red[3][t]);
    }
}

__global__ void k_att_edge(const int* __restrict__ row, const int* __restrict__ col,
                           const float* __restrict__ bea, int E) {
    int e = blockIdx.x * blockDim.x + threadIdx.x;
    if (e >= E) return;
    int r = row[e], c = col[e];
    float4 tr = g_eanode[r], tc = g_eanode[c];
    float l0 = tr.x + tc.z + bea[0];
    float l1 = tr.y + tc.w + bea[1];
    float m  = fmaxf(l0, l1);
    float e0 = expf(l0 - m), e1 = expf(l1 - m);
    float inv = 1.f / (e0 + e1);
    float a0 = e0 * inv, a1 = e1 * inv;
    g_att0[e] = a0; g_att1[e] = a1;
    atomicAdd(&g_degc[r], a0);
    atomicAdd(&g_dego[r], a1);
}

// z[i,:] = xc[perm[i],:] + xo[i,:]  (+ fused stats)
__global__ void k_permadd_stats(const float* __restrict__ xc, const float* __restrict__ xo,
                                const int* __restrict__ perm, float* __restrict__ z, int N,
                                float* __restrict__ sS, float* __restrict__ sQ) {
    __shared__ float ssum[HD], ssq[HD];
    int t = threadIdx.x;
    if (t < HD) { ssum[t] = 0.f; ssq[t] = 0.f; }
    __syncthreads();
    int total  = N * HD4;
    int stride = blockDim.x * gridDim.x;
    int idx    = blockIdx.x * blockDim.x + t;
    int fb     = (idx & 31) * 4;
    float a0=0,a1=0,a2=0,a3=0,q0=0,q1=0,q2=0,q3=0;
    for (; idx < total; idx += stride) {
        int i = idx >> 5, l = idx & 31;
        int p = perm[i];
        float4 a = ((const float4*)xc)[(size_t)p * HD4 + l];
        float4 b = ((const float4*)xo)[idx];
        a.x += b.x; a.y += b.y; a.z += b.z; a.w += b.w;
        ((float4*)z)[idx] = a;
        a0 += a.x; q0 += a.x*a.x; a1 += a.y; q1 += a.y*a.y;
        a2 += a.z; q2 += a.z*a.z; a3 += a.w; q3 += a.w*a.w;
    }
    atomicAdd(&ssum[fb+0], a0); atomicAdd(&ssq[fb+0], q0);
    atomicAdd(&ssum[fb+1], a1); atomicAdd(&ssq[fb+1], q1);
    atomicAdd(&ssum[fb+2], a2); atomicAdd(&ssq[fb+2], q2);
    atomicAdd(&ssum[fb+3], a3); atomicAdd(&ssq[fb+3], q3);
    __syncthreads();
    if (t < HD) { atomicAdd(&sS[t], ssum[t]); atomicAdd(&sQ[t], ssq[t]); }
}

// ---------------- [N,128]x[128,10] + log_softmax ------------------------------
__global__ void k_gemm2_lsm(const float* __restrict__ Z, float* __restrict__ out, int N) {
    __shared__ float Ws[HD * 10];
    __shared__ float bs[10];
    int t = threadIdx.x;
    for (int i = t; i < HD * 10; i += blockDim.x) Ws[i] = g_Wf[i];
    if (t < 10) bs[t] = g_bfold[t];
    __syncthreads();
    int warps = (blockDim.x * gridDim.x) >> 5;
    int gw = (blockIdx.x * blockDim.x + t) >> 5;
    int l  = t & 31;
    for (int i = gw; i < N; i += warps) {
        float4 z = ((const float4*)Z)[(size_t)i * HD4 + l];
        float p[10];
#pragma unroll
        for (int j = 0; j < 10; j++) {
            p[j] = z.x * Ws[(4*l+0)*10 + j] + z.y * Ws[(4*l+1)*10 + j]
                 + z.z * Ws[(4*l+2)*10 + j] + z.w * Ws[(4*l+3)*10 + j];
        }
#pragma unroll
        for (int off = 16; off; off >>= 1)
#pragma unroll
            for (int j = 0; j < 10; j++)
                p[j] += __shfl_xor_sync(0xffffffffu, p[j], off);
        float m = -1e30f;
#pragma unroll
        for (int j = 0; j < 10; j++) { p[j] += bs[j]; m = fmaxf(m, p[j]); }
        float s = 0.f;
#pragma unroll
        for (int j = 0; j < 10; j++) s += expf(p[j] - m);
        float lse = m + logf(s);
        if (l < 10) out[(size_t)i * 10 + l] = p[l] - lse;
    }
}

// ---------------- host orchestration -------------------------------------------
extern "C" void kernel_launch(void* const* d_in, const int* in_sizes, int n_in,
                              void* d_out, int out_size) {
    const float* x      = (const float*)d_in[0];
    const int*   ei     = (const int*)  d_in[1];
    const int*   perm   = (const int*)  d_in[2];
    const float* W_feat = (const float*)d_in[3];
    const float* b_feat = (const float*)d_in[4];
    const float* W_convs= (const float*)d_in[5];
    const float* b_convs= (const float*)d_in[6];
    const float* W_ea   = (const float*)d_in[7];
    const float* b_ea   = (const float*)d_in[8];
    const float* W_na   = (const float*)d_in[9];
    const float* b_na   = (const float*)d_in[10];
    const float* W_ctx  = (const float*)d_in[11];
    const float* b_ctx  = (const float*)d_in[12];
    const float* W_obj  = (const float*)d_in[13];
    const float* b_obj  = (const float*)d_in[14];
    const float* W_fc1  = (const float*)d_in[15];
    const float* b_fc1  = (const float*)d_in[16];
    const float* W_fc2  = (const float*)d_in[17];
    const float* b_fc2  = (const float*)d_in[18];

    int N = in_sizes[0] / HD;
    int E = in_sizes[1] / 2;
    const int* row = ei;
    const int* col = ei + E;
    float* out = (float*)d_out;

    float* Bbase = nullptr;
    cudaGetSymbolAddress((void**)&Bbase, g_B);
    float* B0 = Bbase + 0 * (size_t)MAXN * HD;
    float* B1 = Bbase + 1 * (size_t)MAXN * HD;
    float* B2 = Bbase + 2 * (size_t)MAXN * HD;
    float* B3 = Bbase + 3 * (size_t)MAXN * HD;
    float* B4 = Bbase + 4 * (size_t)MAXN * HD;
    float* B5 = Bbase + 5 * (size_t)MAXN * HD;
    float *degup, *degcp, *degop, *ssump, *ssqp;
    cudaGetSymbolAddress((void**)&degup, g_degu);
    cudaGetSymbolAddress((void**)&degcp, g_degc);
    cudaGetSymbolAddress((void**)&degop, g_dego);
    cudaGetSymbolAddress((void**)&ssump, g_ssum);
    cudaGetSymbolAddress((void**)&ssqp,  g_ssq);
    auto S = [&](int i) { return ssump + i * HD; };
    auto Q = [&](int i) { return ssqp  + i * HD; };

    const int gemm_smem = (128 * XS + 128 * WSD) * 4;
    cudaFuncSetAttribute(k_gemm_tc, cudaFuncAttributeMaxDynamicSharedMemorySize, gemm_smem);

    int gbGemm = (N + 127) / 128;
    int gbN    = (N + 255) / 256;
    int gbE    = (E + 255) / 256;
    int gbE32  = ((E * 32) + 255) / 256;
    size_t rowBytes = (size_t)N * HD * sizeof(float);
    float invN = 1.f / (float)N;

    auto fold = [&](const float* W, const float* b, int Jc, int slot) {
        k_fold<<<1, 128>>>(W, b, Jc, invN, S(slot), Q(slot));
    };
    auto gemm = [&](const float* X, float* Y, int relu, int slot) {
        k_gemm_tc<<<gbGemm, 256, gemm_smem>>>(X, Y, N, relu,
                                              slot >= 0 ? S(slot) : nullptr,
                                              slot >= 0 ? Q(slot) : nullptr);
    };

    k_zero_slots<<<(NSLOT * HD + 255) / 256, 256>>>();

    // stage 0: h = relu(bn(x) @ W_feat + b_feat)   -> B2, stats s1
    k_stats<<<512, 256>>>(x, N, S(0), Q(0));
    fold(W_feat, b_feat, HD, 0);
    gemm(x, B2, 1, 1);

    // unweighted degree
    k_fill<<<gbN, 256>>>(degup, 1.f, N);
    k_deg_unw<<<gbE, 256>>>(row, E, degup);
    k_rsqrt<<<gbN, 256>>>(degup, N);

    // conv1: B2 -> B0 (stats s2)
    fold(W_convs + 0 * HD * HD, nullptr, HD, 1);
    gemm(B2, B1, 0, -1);
    cudaMemsetAsync(B0, 0, rowBytes);
    k_edge_agg<<<gbE32, 256>>>(B1, B0, row, col, degup, E);
    k_bias_relu_stats<<<256, 256>>>(B0, B1, degup, b_convs + 0 * HD, N, S(2), Q(2));

    // conv2: B0 -> B2 (stats s3)
    fold(W_convs + 1 * HD * HD, nullptr, HD, 2);
    gemm(B0, B1, 0, -1);
    cudaMemsetAsync(B2, 0, rowBytes);
    k_edge_agg<<<gbE32, 256>>>(B1, B2, row, col, degup, E);
    k_bias_relu_stats<<<256, 256>>>(B2, B1, degup, b_convs + 1 * HD, N, S(3), Q(3));

    // conv3: B2 -> B0 (no stats needed)
    fold(W_convs + 2 * HD * HD, nullptr, HD, 3);
    gemm(B2, B1, 0, -1);
    cudaMemsetAsync(B0, 0, rowBytes);
    k_edge_agg<<<gbE32, 256>>>(B1, B0, row, col, degup, E);
    k_bias_relu_stats<<<256, 256>>>(B0, B1, degup, b_convs + 2 * HD, N, nullptr, nullptr);

    // attention: h=B0 -> xc=B2 (s4), xo=B3 (s5)
    k_att_node<<<256, 256>>>(B0, W_na, b_na, W_ea, B2, B3, N, S(4), Q(4), S(5), Q(5));
    k_fill<<<gbN, 256>>>(degcp, 1.f, N);
    k_fill<<<gbN, 256>>>(degop, 1.f, N);
    k_att_edge<<<gbE, 256>>>(row, col, b_ea, E);
    k_rsqrt<<<gbN, 256>>>(degcp, N);
    k_rsqrt<<<gbN, 256>>>(degop, N);

    // ctx conv: lin(B2)->B1 ; obj conv: lin(B3)->B2 ; merged edge pass
    fold(W_ctx, nullptr, HD, 4);
    gemm(B2, B1, 0, -1);
    fold(W_obj, nullptr, HD, 5);
    gemm(B3, B2, 0, -1);
    cudaMemsetAsync(B4, 0, rowBytes);
    cudaMemsetAsync(B5, 0, rowBytes);
    k_edge_agg2<<<gbE32, 256>>>(B1, B2, B4, B5, row, col, degcp, degop, E);
    k_bias_relu_stats<<<256, 256>>>(B4, B1, degcp, b_ctx, N, S(6), Q(6));
    k_bias_relu_stats<<<256, 256>>>(B5, B2, degop, b_obj, N, S(7), Q(7));

    // readout 0 (xc2=B4, stats s6 -> gemm stats s8)
    fold(W_fc1 + 0 * HD * HD, b_fc1 + 0 * HD, HD, 6);
    gemm(B4, B0, 1, 8);
    fold(W_fc2 + 0 * HD * 10, b_fc2 + 0 * 10, 10, 8);
    k_gemm2_lsm<<<512, 256>>>(B0, out, N);

    // readout 1 (xo2=B5, stats s7 -> gemm stats s9)
    fold(W_fc1 + 1 * HD * HD, b_fc1 + 1 * HD, HD, 7);
    gemm(B5, B3, 1, 9);
    fold(W_fc2 + 1 * HD * 10, b_fc2 + 1 * 10, 10, 9);
    k_gemm2_lsm<<<512, 256>>>(B3, out + (size_t)N * 10, N);

    // readout 2 (xc[perm]+xo -> B1, stats s11 -> gemm stats s10)
    k_permadd_stats<<<256, 256>>>(B4, B5, perm, B1, N, S(11), Q(11));
    fold(W_fc1 + 2 * HD * HD, b_fc1 + 2 * HD, HD, 11);
    gemm(B1, B0, 1, 10);
    fold(W_fc2 + 2 * HD * 10, b_fc2 + 2 * 10, 10, 10);
    k_gemm2_lsm<<<512, 256>>>(B0, out + (size_t)2 * N * 10, N);
}

// round 3
// speedup vs baseline: 2.4089x; 2.2713x over previous
#include <cuda_runtime.h>

#define HD   128
#define HD4  32
#define MAXN 50000
#define MAXE 800000
#define XS   132   // smem stride (words) for X tile
#define WSD  136   // smem stride (words) for W tile
#define NSLOT 12

// ---------------- scratch (static device globals; no runtime alloc) ----------
static __device__ float  g_B[6][(size_t)MAXN * HD];
static __device__ float4 g_eanode[MAXN];
static __device__ float  g_att0[MAXE];
static __device__ float  g_att1[MAXE];
static __device__ float  g_degu[MAXN];
static __device__ float  g_degc[MAXN];
static __device__ float  g_dego[MAXN];
static __device__ float  g_ssum[NSLOT * HD];
static __device__ float  g_ssq [NSLOT * HD];
static __device__ float  g_Wf[HD * HD];
static __device__ float  g_bfold[HD];
// CSR (in-edges grouped by destination)
static __device__ int    g_cnt[MAXN];
static __device__ int    g_rowptr[MAXN + 1];
static __device__ int    g_cursor[MAXN];
static __device__ int    g_er[MAXE];   // source node per CSR slot
static __device__ int    g_ee[MAXE];   // original edge id per CSR slot

__device__ __forceinline__ unsigned f2tf(float f) {
    unsigned r; asm("cvt.rna.tf32.f32 %0, %1;" : "=r"(r) : "f"(f)); return r;
}

__device__ __forceinline__ void mma_tf32(float* c, const unsigned* a, const unsigned* b) {
    asm volatile(
        "mma.sync.aligned.m16n8k8.row.col.f32.tf32.tf32.f32 "
        "{%0,%1,%2,%3}, {%4,%5,%6,%7}, {%8,%9}, {%0,%1,%2,%3};"
        : "+f"(c[0]), "+f"(c[1]), "+f"(c[2]), "+f"(c[3])
        : "r"(a[0]), "r"(a[1]), "r"(a[2]), "r"(a[3]), "r"(b[0]), "r"(b[1]));
}

// ---------------- stats slots -------------------------------------------------
__global__ void k_zero_slots() {
    int i = blockIdx.x * blockDim.x + threadIdx.x;
    if (i < NSLOT * HD) { g_ssum[i] = 0.f; g_ssq[i] = 0.f; }
}

__global__ void k_stats(const float* __restrict__ X, int N,
                        float* __restrict__ sS, float* __restrict__ sQ) {
    __shared__ float ss[HD], sq[HD];
    int t = threadIdx.x;
    if (t < HD) { ss[t] = 0.f; sq[t] = 0.f; }
    __syncthreads();
    int total  = N * HD4;
    int stride = blockDim.x * gridDim.x;
    int idx    = blockIdx.x * blockDim.x + t;
    int fb     = (idx & 31) * 4;
    float a0=0,a1=0,a2=0,a3=0,q0=0,q1=0,q2=0,q3=0;
    for (; idx < total; idx += stride) {
        float4 v = ((const float4*)X)[idx];
        a0 += v.x; q0 += v.x * v.x;
        a1 += v.y; q1 += v.y * v.y;
        a2 += v.z; q2 += v.z * v.z;
        a3 += v.w; q3 += v.w * v.w;
    }
    atomicAdd(&ss[fb+0], a0); atomicAdd(&sq[fb+0], q0);
    atomicAdd(&ss[fb+1], a1); atomicAdd(&sq[fb+1], q1);
    atomicAdd(&ss[fb+2], a2); atomicAdd(&sq[fb+2], q2);
    atomicAdd(&ss[fb+3], a3); atomicAdd(&sq[fb+3], q3);
    __syncthreads();
    if (t < HD) { atomicAdd(&sS[t], ss[t]); atomicAdd(&sQ[t], sq[t]); }
}

// Fold BN into weights
__global__ void k_fold(const float* __restrict__ W, const float* __restrict__ b,
                       int Jc, float invN,
                       const float* __restrict__ sS, const float* __restrict__ sQ) {
    __shared__ float scale[HD], shift[HD];
    int t = threadIdx.x;   // 128 threads
    {
        float mu  = sS[t] * invN;
        float var = fmaxf(sQ[t] * invN - mu * mu, 0.f);
        float rs  = rsqrtf(var + 1e-5f);
        scale[t]  = rs;
        shift[t]  = 1e-4f - mu * rs;
    }
    __syncthreads();
    for (int j = t; j < Jc; j += HD) {
        float acc = b ? b[j] : 0.f;
        for (int k = 0; k < HD; k++) {
            float w = W[k * Jc + j];
            g_Wf[k * Jc + j] = scale[k] * w;
            acc += shift[k] * w;
        }
        g_bfold[j] = acc;
    }
}

// ---------------- tf32 tensor-core GEMM (512 thr, 16 warps, frag dbl-buffer) --
__global__ void __launch_bounds__(512) k_gemm_tc(const float* __restrict__ X,
                                                 float* __restrict__ Y, int N,
                                                 int doRelu,
                                                 float* __restrict__ sS,
                                                 float* __restrict__ sQ) {
    extern __shared__ unsigned sh[];
    unsigned* Xs = sh;               // 128 x XS
    unsigned* Ws = sh + 128 * XS;    // 128 x WSD
    __shared__ float ssum[HD], ssq[HD];
    int t = threadIdx.x;
    if (t < HD) { ssum[t] = 0.f; ssq[t] = 0.f; }
    int base = blockIdx.x * 128;
#pragma unroll
    for (int i = t; i < 4096; i += 512) {
        int r = i >> 5, c = i & 31, gr = base + r;
        float4 v = make_float4(0.f, 0.f, 0.f, 0.f);
        if (gr < N) v = ((const float4*)X)[(size_t)gr * 32 + c];
        *(uint4*)&Xs[r * XS + c * 4] =
            make_uint4(f2tf(v.x), f2tf(v.y), f2tf(v.z), f2tf(v.w));
    }
#pragma unroll
    for (int i = t; i < 4096; i += 512) {
        int r = i >> 5, c = i & 31;
        float4 v = ((const float4*)g_Wf)[i];
        *(uint4*)&Ws[r * WSD + c * 4] =
            make_uint4(f2tf(v.x), f2tf(v.y), f2tf(v.z), f2tf(v.w));
    }
    __syncthreads();

    int lane = t & 31, g = lane >> 2, tg = lane & 3, w = t >> 5;
    int rwb = (w & 3) * 32;    // warp row base
    int cwb = (w >> 2) * 32;   // warp col base

    float acc[2][4][4];
#pragma unroll
    for (int m = 0; m < 2; m++)
#pragma unroll
        for (int nt = 0; nt < 4; nt++)
#pragma unroll
            for (int j = 0; j < 4; j++) acc[m][nt][j] = 0.f;

    unsigned aA[8], bA[8], aB[8], bB[8];

#define LDFRAG(K0, AA, BB)                                           \
    {                                                                \
        _Pragma("unroll")                                            \
        for (int m = 0; m < 2; m++) {                                \
            int r0 = rwb + m * 16 + g;                               \
            AA[m*4+0] = Xs[r0 * XS + (K0) + tg];                     \
            AA[m*4+1] = Xs[(r0 + 8) * XS + (K0) + tg];               \
            AA[m*4+2] = Xs[r0 * XS + (K0) + tg + 4];                 \
            AA[m*4+3] = Xs[(r0 + 8) * XS + (K0) + tg + 4];           \
        }                                                            \
        _Pragma("unroll")                                            \
        for (int nt = 0; nt < 4; nt++) {                             \
            int cc = cwb + nt * 8 + g;                               \
            BB[nt*2+0] = Ws[((K0) + tg) * WSD + cc];                 \
            BB[nt*2+1] = Ws[((K0) + tg + 4) * WSD + cc];             \
        }                                                            \
    }

    LDFRAG(0, aA, bA);
#pragma unroll
    for (int k = 0; k < 16; k += 2) {
        if (k + 1 < 16) LDFRAG((k + 1) * 8, aB, bB);
#pragma unroll
        for (int m = 0; m < 2; m++)
#pragma unroll
            for (int nt = 0; nt < 4; nt++)
                mma_tf32(acc[m][nt], aA + m * 4, bA + nt * 2);
        if (k + 2 < 16) LDFRAG((k + 2) * 8, aA, bA);
#pragma unroll
        for (int m = 0; m < 2; m++)
#pragma unroll
            for (int nt = 0; nt < 4; nt++)
                mma_tf32(acc[m][nt], aB + m * 4, bB + nt * 2);
    }
#undef LDFRAG

    // epilogue: bias, relu, store, fused stats
    float ls[4][2], lq[4][2];
#pragma unroll
    for (int nt = 0; nt < 4; nt++) { ls[nt][0]=0.f; ls[nt][1]=0.f; lq[nt][0]=0.f; lq[nt][1]=0.f; }

#pragma unroll
    for (int nt = 0; nt < 4; nt++) {
        int col = cwb + nt * 8 + 2 * tg;
        float bx = g_bfold[col], by = g_bfold[col + 1];
#pragma unroll
        for (int m = 0; m < 2; m++) {
            int r0 = base + rwb + m * 16 + g;
            int r1 = r0 + 8;
            float y00 = acc[m][nt][0] + bx, y01 = acc[m][nt][1] + by;
            float y10 = acc[m][nt][2] + bx, y11 = acc[m][nt][3] + by;
            if (doRelu) {
                y00 = fmaxf(y00, 0.f); y01 = fmaxf(y01, 0.f);
                y10 = fmaxf(y10, 0.f); y11 = fmaxf(y11, 0.f);
            }
            if (r0 < N) {
                ((float2*)Y)[(size_t)r0 * 64 + (col >> 1)] = make_float2(y00, y01);
                ls[nt][0] += y00; lq[nt][0] += y00 * y00;
                ls[nt][1] += y01; lq[nt][1] += y01 * y01;
            }
            if (r1 < N) {
                ((float2*)Y)[(size_t)r1 * 64 + (col >> 1)] = make_float2(y10, y11);
                ls[nt][0] += y10; lq[nt][0] += y10 * y10;
                ls[nt][1] += y11; lq[nt][1] += y11 * y11;
            }
        }
    }

    if (sS) {
#pragma unroll
        for (int off = 4; off <= 16; off <<= 1)
#pragma unroll
            for (int nt = 0; nt < 4; nt++)
#pragma unroll
                for (int j = 0; j < 2; j++) {
                    ls[nt][j] += __shfl_xor_sync(0xffffffffu, ls[nt][j], off);
                    lq[nt][j] += __shfl_xor_sync(0xffffffffu, lq[nt][j], off);
                }
        if (g == 0) {
#pragma unroll
            for (int nt = 0; nt < 4; nt++)
#pragma unroll
                for (int j = 0; j < 2; j++) {
                    int col = cwb + nt * 8 + 2 * tg + j;
                    atomicAdd(&ssum[col], ls[nt][j]);
                    atomicAdd(&ssq[col],  lq[nt][j]);
                }
        }
        __syncthreads();
        if (t < HD) { atomicAdd(&sS[t], ssum[t]); atomicAdd(&sQ[t], ssq[t]); }
    }
}

// ---------------- degree helpers ---------------------------------------------
__global__ void k_fill(float* p, float v, int n) {
    int i = blockIdx.x * blockDim.x + threadIdx.x;
    if (i < n) p[i] = v;
}
__global__ void k_deg_unw(const int* __restrict__ row, int E, float* deg) {
    int e = blockIdx.x * blockDim.x + threadIdx.x;
    if (e < E) atomicAdd(&deg[row[e]], 1.f);
}
__global__ void k_rsqrt(float* p, int n) {
    int i = blockIdx.x * blockDim.x + threadIdx.x;
    if (i < n) p[i] = rsqrtf(p[i]);
}

// ---------------- CSR build ----------------------------------------------------
__global__ void k_hist(const int* __restrict__ col, int E) {
    int e = blockIdx.x * blockDim.x + threadIdx.x;
    if (e < E) atomicAdd(&g_cnt[col[e]], 1);
}

__global__ void __launch_bounds__(1024) k_scan(int N) {
    __shared__ int wsum[32];
    __shared__ int carrySh;
    int t = threadIdx.x;
    if (t == 0) carrySh = 0;
    __syncthreads();
    for (int base = 0; base < N; base += 1024) {
        int idx = base + t;
        int v = (idx < N) ? g_cnt[idx] : 0;
        int x = v;
#pragma unroll
        for (int off = 1; off < 32; off <<= 1) {
            int y = __shfl_up_sync(0xffffffffu, x, off);
            if ((t & 31) >= off) x += y;
        }
        if ((t & 31) == 31) wsum[t >> 5] = x;
        __syncthreads();
        if (t < 32) {
            int y = wsum[t];
#pragma unroll
            for (int off = 1; off < 32; off <<= 1) {
                int z = __shfl_up_sync(0xffffffffu, y, off);
                if (t >= off) y += z;
            }
            wsum[t] = y;
        }
        __syncthreads();
        int winc = (t >= 32) ? wsum[(t >> 5) - 1] : 0;
        int incl = x + winc + carrySh;
        int excl = incl - v;
        if (idx < N) { g_rowptr[idx] = excl; g_cursor[idx] = excl; }
        __syncthreads();
        if (t == 1023) carrySh = incl;
        __syncthreads();
    }
    if (t == 0) g_rowptr[N] = carrySh;
}

__global__ void k_fillcsr(const int* __restrict__ row, const int* __restrict__ col, int E) {
    int e = blockIdx.x * blockDim.x + threadIdx.x;
    if (e >= E) return;
    int c = col[e];
    int p = atomicAdd(&g_cursor[c], 1);
    g_er[p] = row[e];
    g_ee[p] = e;
}

// ---------------- CSR gather conv epilogue ------------------------------------
// out[i] = relu( lin[i]*dinv[i]^2 + sum_in-edges lin[r]*dinv[r]*dinv[i] + b )
__global__ void __launch_bounds__(256) k_gather(const float* __restrict__ lin,
                                                float* __restrict__ out,
                                                const float* __restrict__ dinv,
                                                const float* __restrict__ b, int N,
                                                float* __restrict__ sS,
                                                float* __restrict__ sQ) {
    __shared__ float ssum[HD], ssq[HD];
    int t = threadIdx.x;
    if (t < HD) { ssum[t] = 0.f; ssq[t] = 0.f; }
    __syncthreads();
    int lane = t & 31;
    int warpId = (blockIdx.x * blockDim.x + t) >> 5;
    int nW = (blockDim.x * gridDim.x) >> 5;
    float4 bb = ((const float4*)b)[lane];
    float s0=0,s1=0,s2=0,s3=0,q0=0,q1=0,q2=0,q3=0;
    for (int i = warpId; i < N; i += nW) {
        int start = g_rowptr[i], end = g_rowptr[i + 1];
        float di = dinv[i];
        float4 acc = __ldg(&((const float4*)lin)[(size_t)i * HD4 + lane]);
        float sl = di * di;
        acc.x *= sl; acc.y *= sl; acc.z *= sl; acc.w *= sl;
        for (int j0 = start; j0 < end; j0 += 32) {
            int jj = j0 + lane;
            int r = 0; float dr = 0.f;
            if (jj < end) { r = g_er[jj]; dr = dinv[r]; }
            int cnt = min(32, end - j0);
            for (int k = 0; k < cnt; k++) {
                int   rr = __shfl_sync(0xffffffffu, r, k);
                float nn = __shfl_sync(0xffffffffu, dr, k) * di;
                float4 v = __ldg(&((const float4*)lin)[(size_t)rr * HD4 + lane]);
                acc.x += v.x * nn; acc.y += v.y * nn;
                acc.z += v.z * nn; acc.w += v.w * nn;
            }
        }
        acc.x = fmaxf(acc.x + bb.x, 0.f); acc.y = fmaxf(acc.y + bb.y, 0.f);
        acc.z = fmaxf(acc.z + bb.z, 0.f); acc.w = fmaxf(acc.w + bb.w, 0.f);
        ((float4*)out)[(size_t)i * HD4 + lane] = acc;
        s0 += acc.x; q0 += acc.x*acc.x; s1 += acc.y; q1 += acc.y*acc.y;
        s2 += acc.z; q2 += acc.z*acc.z; s3 += acc.w; q3 += acc.w*acc.w;
    }
    if (sS) {
        atomicAdd(&ssum[lane*4+0], s0); atomicAdd(&ssq[lane*4+0], q0);
        atomicAdd(&ssum[lane*4+1], s1); atomicAdd(&ssq[lane*4+1], q1);
        atomicAdd(&ssum[lane*4+2], s2); atomicAdd(&ssq[lane*4+2], q2);
        atomicAdd(&ssum[lane*4+3], s3); atomicAdd(&ssq[lane*4+3], q3);
        __syncthreads();
        if (t < HD) { atomicAdd(&sS[t], ssum[t]); atomicAdd(&sQ[t], ssq[t]); }
    }
}

// merged weighted ctx/obj gather
__global__ void __launch_bounds__(256) k_gather2(const float* __restrict__ linC,
                                                 const float* __restrict__ linO,
                                                 float* __restrict__ outC,
                                                 float* __restrict__ outO,
                                                 const float* __restrict__ dc,
                                                 const float* __restrict__ dd,
                                                 const float* __restrict__ bc,
                                                 const float* __restrict__ bo, int N,
                                                 float* sSc, float* sQc,
                                                 float* sSo, float* sQo) {
    __shared__ float red[4][HD];
    int t = threadIdx.x;
    for (int i = t; i < 4 * HD; i += blockDim.x) ((float*)red)[i] = 0.f;
    __syncthreads();
    int lane = t & 31;
    int warpId = (blockIdx.x * blockDim.x + t) >> 5;
    int nW = (blockDim.x * gridDim.x) >> 5;
    float4 bbc = ((const float4*)bc)[lane];
    float4 bbo = ((const float4*)bo)[lane];
    float sc[4]={0,0,0,0}, qc[4]={0,0,0,0}, so[4]={0,0,0,0}, qo[4]={0,0,0,0};
    for (int i = warpId; i < N; i += nW) {
        int start = g_rowptr[i], end = g_rowptr[i + 1];
        float dci = dc[i], doi = dd[i];
        float4 aC = __ldg(&((const float4*)linC)[(size_t)i * HD4 + lane]);
        float4 aO = __ldg(&((const float4*)linO)[(size_t)i * HD4 + lane]);
        float slc = dci * dci, slo = doi * doi;
        aC.x *= slc; aC.y *= slc; aC.z *= slc; aC.w *= slc;
        aO.x *= slo; aO.y *= slo; aO.z *= slo; aO.w *= slo;
        for (int j0 = start; j0 < end; j0 += 32) {
            int jj = j0 + lane;
            float wc = 0.f, wo = 0.f; int r = 0;
            if (jj < end) {
                r = g_er[jj];
                int e = g_ee[jj];
                wc = dc[r] * g_att0[e];
                wo = dd[r] * g_att1[e];
            }
            int cnt = min(32, end - j0);
            for (int k = 0; k < cnt; k++) {
                int   rr = __shfl_sync(0xffffffffu, r, k);
                float nc = __shfl_sync(0xffffffffu, wc, k) * dci;
                float no = __shfl_sync(0xffffffffu, wo, k) * doi;
                float4 vC = __ldg(&((const float4*)linC)[(size_t)rr * HD4 + lane]);
                float4 vO = __ldg(&((const float4*)linO)[(size_t)rr * HD4 + lane]);
                aC.x += vC.x * nc; aC.y += vC.y * nc; aC.z += vC.z * nc; aC.w += vC.w * nc;
                aO.x += vO.x * no; aO.y += vO.y * no; aO.z += vO.z * no; aO.w += vO.w * no;
            }
        }
        aC.x = fmaxf(aC.x + bbc.x, 0.f); aC.y = fmaxf(aC.y + bbc.y, 0.f);
        aC.z = fmaxf(aC.z + bbc.z, 0.f); aC.w = fmaxf(aC.w + bbc.w, 0.f);
        aO.x = fmaxf(aO.x + bbo.x, 0.f); aO.y = fmaxf(aO.y + bbo.y, 0.f);
        aO.z = fmaxf(aO.z + bbo.z, 0.f); aO.w = fmaxf(aO.w + bbo.w, 0.f);
        ((float4*)outC)[(size_t)i * HD4 + lane] = aC;
        ((float4*)outO)[(size_t)i * HD4 + lane] = aO;
        sc[0]+=aC.x; qc[0]+=aC.x*aC.x; sc[1]+=aC.y; qc[1]+=aC.y*aC.y;
        sc[2]+=aC.z; qc[2]+=aC.z*aC.z; sc[3]+=aC.w; qc[3]+=aC.w*aC.w;
        so[0]+=aO.x; qo[0]+=aO.x*aO.x; so[1]+=aO.y; qo[1]+=aO.y*aO.y;
        so[2]+=aO.z; qo[2]+=aO.z*aO.z; so[3]+=aO.w; qo[3]+=aO.w*aO.w;
    }
#pragma unroll
    for (int j = 0; j < 4; j++) {
        atomicAdd(&red[0][lane*4+j], sc[j]);
        atomicAdd(&red[1][lane*4+j], qc[j]);
        atomicAdd(&red[2][lane*4+j], so[j]);
        atomicAdd(&red[3][lane*4+j], qo[j]);
    }
    __syncthreads();
    if (t < HD) {
        atomicAdd(&sSc[t], red[0][t]); atomicAdd(&sQc[t], red[1][t]);
        atomicAdd(&sSo[t], red[2][t]); atomicAdd(&sQo[t], red[3][t]);
    }
}

// ---------------- attention ----------------------------------------------------
__global__ void k_att_node(const float* __restrict__ h,
                           const float* __restrict__ Wna, const float* __restrict__ bna,
                           const float* __restrict__ Wea,
                           float* __restrict__ xc, float* __restrict__ xo, int N,
                           float* sSc, float* sQc, float* sSo, float* sQo) {
    __shared__ float Wc[HD * 6];
    __shared__ float red[4][HD];
    int t = threadIdx.x;
    for (int i = t; i < HD * 6; i += blockDim.x) {
        int k = i / 6, j = i % 6;
        float v;
        if (j < 2)      v = Wna[k * 2 + j];
        else if (j < 4) v = Wea[k * 2 + (j - 2)];
        else            v = Wea[(HD + k) * 2 + (j - 4)];
        Wc[i] = v;
    }
    for (int i = t; i < 4 * HD; i += blockDim.x) ((float*)red)[i] = 0.f;
    __syncthreads();
    int warps = (blockDim.x * gridDim.x) >> 5;
    int gw = (blockIdx.x * blockDim.x + t) >> 5;
    int l  = t & 31;
    float b0 = bna[0], b1 = bna[1];
    float sc[4]={0,0,0,0}, qc[4]={0,0,0,0}, so[4]={0,0,0,0}, qo[4]={0,0,0,0};
    for (int i = gw; i < N; i += warps) {
        float4 hv = ((const float4*)h)[(size_t)i * HD4 + l];
        float p[6];
#pragma unroll
        for (int j = 0; j < 6; j++) {
            p[j] = hv.x * Wc[(4*l+0)*6 + j] + hv.y * Wc[(4*l+1)*6 + j]
                 + hv.z * Wc[(4*l+2)*6 + j] + hv.w * Wc[(4*l+3)*6 + j];
        }
#pragma unroll
        for (int off = 16; off; off >>= 1)
#pragma unroll
            for (int j = 0; j < 6; j++)
                p[j] += __shfl_xor_sync(0xffffffffu, p[j], off);
        float l0 = p[0] + b0, l1 = p[1] + b1;
        float m  = fmaxf(l0, l1);
        float e0 = expf(l0 - m), e1 = expf(l1 - m);
        float inv = 1.f / (e0 + e1);
        float a0 = e0 * inv, a1 = e1 * inv;
        float4 vc = make_float4(hv.x*a0, hv.y*a0, hv.z*a0, hv.w*a0);
        float4 vo = make_float4(hv.x*a1, hv.y*a1, hv.z*a1, hv.w*a1);
        ((float4*)xc)[(size_t)i * HD4 + l] = vc;
        ((float4*)xo)[(size_t)i * HD4 + l] = vo;
        sc[0]+=vc.x; qc[0]+=vc.x*vc.x; sc[1]+=vc.y; qc[1]+=vc.y*vc.y;
        sc[2]+=vc.z; qc[2]+=vc.z*vc.z; sc[3]+=vc.w; qc[3]+=vc.w*vc.w;
        so[0]+=vo.x; qo[0]+=vo.x*vo.x; so[1]+=vo.y; qo[1]+=vo.y*vo.y;
        so[2]+=vo.z; qo[2]+=vo.z*vo.z; so[3]+=vo.w; qo[3]+=vo.w*vo.w;
        if (l == 0) g_eanode[i] = make_float4(p[2], p[3], p[4], p[5]);
    }
#pragma unroll
    for (int j = 0; j < 4; j++) {
        atomicAdd(&red[0][l*4+j], sc[j]);
        atomicAdd(&red[1][l*4+j], qc[j]);
        atomicAdd(&red[2][l*4+j], so[j]);
        atomicAdd(&red[3][l*4+j], qo[j]);
    }
    __syncthreads();
    if (t < HD) {
        atomicAdd(&sSc[t], red[0][t]); atomicAdd(&sQc[t], red[1][t]);
        atomicAdd(&sSo[t], red[2][t]); atomicAdd(&sQo[t], red[3][t]);
    }
}

__global__ void k_att_edge(const int* __restrict__ row, const int* __restrict__ col,
                           const float* __restrict__ bea, int E) {
    int e = blockIdx.x * blockDim.x + threadIdx.x;
    if (e >= E) return;
    int r = row[e], c = col[e];
    float4 tr = g_eanode[r], tc = g_eanode[c];
    float l0 = tr.x + tc.z + bea[0];
    float l1 = tr.y + tc.w + bea[1];
    float m  = fmaxf(l0, l1);
    float e0 = expf(l0 - m), e1 = expf(l1 - m);
    float inv = 1.f / (e0 + e1);
    float a0 = e0 * inv, a1 = e1 * inv;
    g_att0[e] = a0; g_att1[e] = a1;
    atomicAdd(&g_degc[r], a0);
    atomicAdd(&g_dego[r], a1);
}

// z[i,:] = xc[perm[i],:] + xo[i,:]  (+ fused stats)
__global__ void k_permadd_stats(const float* __restrict__ xc, const float* __restrict__ xo,
                                const int* __restrict__ perm, float* __restrict__ z, int N,
                                float* __restrict__ sS, float* __restrict__ sQ) {
    __shared__ float ssum[HD], ssq[HD];
    int t = threadIdx.x;
    if (t < HD) { ssum[t] = 0.f; ssq[t] = 0.f; }
    __syncthreads();
    int total  = N * HD4;
    int stride = blockDim.x * gridDim.x;
    int idx    = blockIdx.x * blockDim.x + t;
    int fb     = (idx & 31) * 4;
    float a0=0,a1=0,a2=0,a3=0,q0=0,q1=0,q2=0,q3=0;
    for (; idx < total; idx += stride) {
        int i = idx >> 5, l = idx & 31;
        int p = perm[i];
        float4 a = ((const float4*)xc)[(size_t)p * HD4 + l];
        float4 b = ((const float4*)xo)[idx];
        a.x += b.x; a.y += b.y; a.z += b.z; a.w += b.w;
        ((float4*)z)[idx] = a;
        a0 += a.x; q0 += a.x*a.x; a1 += a.y; q1 += a.y*a.y;
        a2 += a.z; q2 += a.z*a.z; a3 += a.w; q3 += a.w*a.w;
    }
    atomicAdd(&ssum[fb+0], a0); atomicAdd(&ssq[fb+0], q0);
    atomicAdd(&ssum[fb+1], a1); atomicAdd(&ssq[fb+1], q1);
    atomicAdd(&ssum[fb+2], a2); atomicAdd(&ssq[fb+2], q2);
    atomicAdd(&ssum[fb+3], a3); atomicAdd(&ssq[fb+3], q3);
    __syncthreads();
    if (t < HD) { atomicAdd(&sS[t], ssum[t]); atomicAdd(&sQ[t], ssq[t]); }
}

// ---------------- [N,128]x[128,10] + log_softmax ------------------------------
__global__ void k_gemm2_lsm(const float* __restrict__ Z, float* __restrict__ out, int N) {
    __shared__ float Ws[HD * 10];
    __shared__ float bs[10];
    int t = threadIdx.x;
    for (int i = t; i < HD * 10; i += blockDim.x) Ws[i] = g_Wf[i];
    if (t < 10) bs[t] = g_bfold[t];
    __syncthreads();
    int warps = (blockDim.x * gridDim.x) >> 5;
    int gw = (blockIdx.x * blockDim.x + t) >> 5;
    int l  = t & 31;
    for (int i = gw; i < N; i += warps) {
        float4 z = ((const float4*)Z)[(size_t)i * HD4 + l];
        float p[10];
#pragma unroll
        for (int j = 0; j < 10; j++) {
            p[j] = z.x * Ws[(4*l+0)*10 + j] + z.y * Ws[(4*l+1)*10 + j]
                 + z.z * Ws[(4*l+2)*10 + j] + z.w * Ws[(4*l+3)*10 + j];
        }
#pragma unroll
        for (int off = 16; off; off >>= 1)
#pragma unroll
            for (int j = 0; j < 10; j++)
                p[j] += __shfl_xor_sync(0xffffffffu, p[j], off);
        float m = -1e30f;
#pragma unroll
        for (int j = 0; j < 10; j++) { p[j] += bs[j]; m = fmaxf(m, p[j]); }
        float s = 0.f;
#pragma unroll
        for (int j = 0; j < 10; j++) s += expf(p[j] - m);
        float lse = m + logf(s);
        if (l < 10) out[(size_t)i * 10 + l] = p[l] - lse;
    }
}

// ---------------- host orchestration -------------------------------------------
extern "C" void kernel_launch(void* const* d_in, const int* in_sizes, int n_in,
                              void* d_out, int out_size) {
    const float* x      = (const float*)d_in[0];
    const int*   ei     = (const int*)  d_in[1];
    const int*   perm   = (const int*)  d_in[2];
    const float* W_feat = (const float*)d_in[3];
    const float* b_feat = (const float*)d_in[4];
    const float* W_convs= (const float*)d_in[5];
    const float* b_convs= (const float*)d_in[6];
    const float* W_ea   = (const float*)d_in[7];
    const float* b_ea   = (const float*)d_in[8];
    const float* W_na   = (const float*)d_in[9];
    const float* b_na   = (const float*)d_in[10];
    const float* W_ctx  = (const float*)d_in[11];
    const float* b_ctx  = (const float*)d_in[12];
    const float* W_obj  = (const float*)d_in[13];
    const float* b_obj  = (const float*)d_in[14];
    const float* W_fc1  = (const float*)d_in[15];
    const float* b_fc1  = (const float*)d_in[16];
    const float* W_fc2  = (const float*)d_in[17];
    const float* b_fc2  = (const float*)d_in[18];

    int N = in_sizes[0] / HD;
    int E = in_sizes[1] / 2;
    const int* row = ei;
    const int* col = ei + E;
    float* out = (float*)d_out;

    float* Bbase = nullptr;
    cudaGetSymbolAddress((void**)&Bbase, g_B);
    float* B0 = Bbase + 0 * (size_t)MAXN * HD;
    float* B1 = Bbase + 1 * (size_t)MAXN * HD;
    float* B2 = Bbase + 2 * (size_t)MAXN * HD;
    float* B3 = Bbase + 3 * (size_t)MAXN * HD;
    float* B4 = Bbase + 4 * (size_t)MAXN * HD;
    float* B5 = Bbase + 5 * (size_t)MAXN * HD;
    float *degup, *degcp, *degop, *ssump, *ssqp;
    int* cntp;
    cudaGetSymbolAddress((void**)&degup, g_degu);
    cudaGetSymbolAddress((void**)&degcp, g_degc);
    cudaGetSymbolAddress((void**)&degop, g_dego);
    cudaGetSymbolAddress((void**)&ssump, g_ssum);
    cudaGetSymbolAddress((void**)&ssqp,  g_ssq);
    cudaGetSymbolAddress((void**)&cntp,  g_cnt);
    auto S = [&](int i) { return ssump + i * HD; };
    auto Q = [&](int i) { return ssqp  + i * HD; };

    const int gemm_smem = (128 * XS + 128 * WSD) * 4;
    cudaFuncSetAttribute(k_gemm_tc, cudaFuncAttributeMaxDynamicSharedMemorySize, gemm_smem);

    int gbGemm = (N + 127) / 128;
    int gbN    = (N + 255) / 256;
    int gbE    = (E + 255) / 256;
    float invN = 1.f / (float)N;

    auto fold = [&](const float* W, const float* b, int Jc, int slot) {
        k_fold<<<1, 128>>>(W, b, Jc, invN, S(slot), Q(slot));
    };
    auto gemm = [&](const float* X, float* Y, int relu, int slot) {
        k_gemm_tc<<<gbGemm, 512, gemm_smem>>>(X, Y, N, relu,
                                              slot >= 0 ? S(slot) : nullptr,
                                              slot >= 0 ? Q(slot) : nullptr);
    };

    k_zero_slots<<<(NSLOT * HD + 255) / 256, 256>>>();

    // ---- CSR build (in-edges grouped by destination), once per launch ----
    cudaMemsetAsync(cntp, 0, (size_t)N * sizeof(int));
    k_hist<<<gbE, 256>>>(col, E);
    k_scan<<<1, 1024>>>(N);
    k_fillcsr<<<gbE, 256>>>(row, col, E);

    // unweighted degree
    k_fill<<<gbN, 256>>>(degup, 1.f, N);
    k_deg_unw<<<gbE, 256>>>(row, E, degup);
    k_rsqrt<<<gbN, 256>>>(degup, N);

    // stage 0: h = relu(bn(x) @ W_feat + b_feat)   -> B2, stats slot1
    k_stats<<<512, 256>>>(x, N, S(0), Q(0));
    fold(W_feat, b_feat, HD, 0);
    gemm(x, B2, 1, 1);

    // conv1: B2 -> B0 (stats s2)
    fold(W_convs + 0 * HD * HD, nullptr, HD, 1);
    gemm(B2, B1, 0, -1);
    k_gather<<<1024, 256>>>(B1, B0, degup, b_convs + 0 * HD, N, S(2), Q(2));

    // conv2: B0 -> B2 (stats s3)
    fold(W_convs + 1 * HD * HD, nullptr, HD, 2);
    gemm(B0, B1, 0, -1);
    k_gather<<<1024, 256>>>(B1, B2, degup, b_convs + 1 * HD, N, S(3), Q(3));

    // conv3: B2 -> B0 (no stats)
    fold(W_convs + 2 * HD * HD, nullptr, HD, 3);
    gemm(B2, B1, 0, -1);
    k_gather<<<1024, 256>>>(B1, B0, degup, b_convs + 2 * HD, N, nullptr, nullptr);

    // attention: h=B0 -> xc=B2 (s4), xo=B3 (s5)
    k_att_node<<<256, 256>>>(B0, W_na, b_na, W_ea, B2, B3, N, S(4), Q(4), S(5), Q(5));
    k_fill<<<gbN, 256>>>(degcp, 1.f, N);
    k_fill<<<gbN, 256>>>(degop, 1.f, N);
    k_att_edge<<<gbE, 256>>>(row, col, b_ea, E);
    k_rsqrt<<<gbN, 256>>>(degcp, N);
    k_rsqrt<<<gbN, 256>>>(degop, N);

    // ctx conv lin -> B1 ; obj conv lin -> B2 ; merged weighted gather
    fold(W_ctx, nullptr, HD, 4);
    gemm(B2, B1, 0, -1);
    fold(W_obj, nullptr, HD, 5);
    gemm(B3, B2, 0, -1);
    k_gather2<<<1024, 256>>>(B1, B2, B4, B5, degcp, degop, b_ctx, b_obj, N,
                             S(6), Q(6), S(7), Q(7));

    // readout 0 (xc2=B4, s6 -> gemm stats s8)
    fold(W_fc1 + 0 * HD * HD, b_fc1 + 0 * HD, HD, 6);
    gemm(B4, B0, 1, 8);
    fold(W_fc2 + 0 * HD * 10, b_fc2 + 0 * 10, 10, 8);
    k_gemm2_lsm<<<512, 256>>>(B0, out, N);

    // readout 1 (xo2=B5, s7 -> gemm stats s9)
    fold(W_fc1 + 1 * HD * HD, b_fc1 + 1 * HD, HD, 7);
    gemm(B5, B3, 1, 9);
    fold(W_fc2 + 1 * HD * 10, b_fc2 + 1 * 10, 10, 9);
    k_gemm2_lsm<<<512, 256>>>(B3, out + (size_t)N * 10, N);

    // readout 2 (xc[perm]+xo -> B1, s11 -> gemm stats s10)
    k_permadd_stats<<<256, 256>>>(B4, B5, perm, B1, N, S(11), Q(11));
    fold(W_fc1 + 2 * HD * HD, b_fc1 + 2 * HD, HD, 11);
    gemm(B1, B0, 1, 10);
    fold(W_fc2 + 2 * HD * 10, b_fc2 + 2 * 10, 10, 10);
    k_gemm2_lsm<<<512, 256>>>(B0, out + (size_t)2 * N * 10, N);
}

// round 4
// speedup vs baseline: 3.2118x; 1.3333x over previous
#include <cuda_runtime.h>

#define HD   128
#define HD4  32
#define MAXN 50000
#define MAXE 800000
#define XS   132
#define WSD  136
#define NSLOT 12

// ---------------- scratch ------------------------------------------------------
static __device__ float  g_B[6][(size_t)MAXN * HD];
static __device__ float4 g_eanode[MAXN];
static __device__ float  g_att0[MAXE];
static __device__ float  g_att1[MAXE];
static __device__ float  g_degu[MAXN];
static __device__ float  g_degc[MAXN];
static __device__ float  g_dego[MAXN];
static __device__ float  g_ssum[NSLOT * HD];
static __device__ float  g_ssq [NSLOT * HD];
// CSR
static __device__ int    g_cnt[MAXN];     // in-degree (by col) for CSR
static __device__ int    g_dcnt[MAXN];    // out-degree (by row) for norm
static __device__ int    g_rowptr[MAXN + 1];
static __device__ int    g_cursor[MAXN];
static __device__ int    g_er[MAXE];
static __device__ int    g_ee[MAXE];
static __device__ int    g_bsum[64];
static __device__ int    g_boff[64];
static __device__ int    g_total;

struct GJob {
    const float* X; float* Y; const float* W; const float* b;
    const float* sSin; const float* sQin; float* sSout; float* sQout;
};
struct GJobs { GJob j[3]; };
struct LJob {
    const float* Z; float* out; const float* W; const float* b;
    const float* sSin; const float* sQin;
};
struct LJobs { LJob j[3]; };

__device__ __forceinline__ unsigned f2tf(float f) {
    unsigned r; asm("cvt.rna.tf32.f32 %0, %1;" : "=r"(r) : "f"(f)); return r;
}

__device__ __forceinline__ void mma_tf32(float* c, const unsigned* a, const unsigned* b) {
    asm volatile(
        "mma.sync.aligned.m16n8k8.row.col.f32.tf32.tf32.f32 "
        "{%0,%1,%2,%3}, {%4,%5,%6,%7}, {%8,%9}, {%0,%1,%2,%3};"
        : "+f"(c[0]), "+f"(c[1]), "+f"(c[2]), "+f"(c[3])
        : "r"(a[0]), "r"(a[1]), "r"(a[2]), "r"(a[3]), "r"(b[0]), "r"(b[1]));
}

// ---------------- misc small kernels -------------------------------------------
__global__ void k_zero_slots() {
    int i = blockIdx.x * blockDim.x + threadIdx.x;
    if (i < NSLOT * HD) { g_ssum[i] = 0.f; g_ssq[i] = 0.f; }
}

__global__ void k_stats(const float* __restrict__ X, int N,
                        float* __restrict__ sS, float* __restrict__ sQ) {
    __shared__ float ss[HD], sq[HD];
    int t = threadIdx.x;
    if (t < HD) { ss[t] = 0.f; sq[t] = 0.f; }
    __syncthreads();
    int total  = N * HD4;
    int stride = blockDim.x * gridDim.x;
    int idx    = blockIdx.x * blockDim.x + t;
    int fb     = (idx & 31) * 4;
    float a0=0,a1=0,a2=0,a3=0,q0=0,q1=0,q2=0,q3=0;
    for (; idx < total; idx += stride) {
        float4 v = ((const float4*)X)[idx];
        a0 += v.x; q0 += v.x * v.x;
        a1 += v.y; q1 += v.y * v.y;
        a2 += v.z; q2 += v.z * v.z;
        a3 += v.w; q3 += v.w * v.w;
    }
    atomicAdd(&ss[fb+0], a0); atomicAdd(&sq[fb+0], q0);
    atomicAdd(&ss[fb+1], a1); atomicAdd(&sq[fb+1], q1);
    atomicAdd(&ss[fb+2], a2); atomicAdd(&sq[fb+2], q2);
    atomicAdd(&ss[fb+3], a3); atomicAdd(&sq[fb+3], q3);
    __syncthreads();
    if (t < HD) { atomicAdd(&sS[t], ss[t]); atomicAdd(&sQ[t], sq[t]); }
}

// ---------------- tf32 GEMM with inline BN fold, batched via blockIdx.y --------
__global__ void __launch_bounds__(512) k_gemm_tc(GJobs jobs, int N, int doRelu,
                                                 float invN) {
    extern __shared__ unsigned sh[];
    unsigned* Xs = sh;
    unsigned* Ws = sh + 128 * XS;
    __shared__ float ssum[HD], ssq[HD], scaleSh[HD], tshSh[HD], biasSh[HD];
    __shared__ float bpart[4][HD];
    const GJob J = jobs.j[blockIdx.y];
    int t = threadIdx.x;
    if (t < HD) {
        ssum[t] = 0.f; ssq[t] = 0.f;
        float mu  = J.sSin[t] * invN;
        float var = fmaxf(J.sQin[t] * invN - mu * mu, 0.f);
        float rs  = rsqrtf(var + 1e-5f);
        scaleSh[t] = rs;
        tshSh[t]   = 1e-4f / rs - mu;   // shift/scale
        biasSh[t]  = J.b ? J.b[t] : 0.f;
    }
    __syncthreads();
    int base = blockIdx.x * 128;
#pragma unroll
    for (int i = t; i < 4096; i += 512) {
        int r = i >> 5, c = i & 31, gr = base + r;
        float4 v = make_float4(0.f, 0.f, 0.f, 0.f);
        if (gr < N) v = ((const float4*)J.X)[(size_t)gr * 32 + c];
        *(uint4*)&Xs[r * XS + c * 4] =
            make_uint4(f2tf(v.x), f2tf(v.y), f2tf(v.z), f2tf(v.w));
    }
#pragma unroll
    for (int i = t; i < 4096; i += 512) {
        int r = i >> 5, c = i & 31;
        float4 v = ((const float4*)J.W)[i];
        float s = scaleSh[r];
        *(uint4*)&Ws[r * WSD + c * 4] =
            make_uint4(f2tf(v.x * s), f2tf(v.y * s), f2tf(v.z * s), f2tf(v.w * s));
    }
    __syncthreads();

    // bias += shift . W  (using scaled tf32 W: shift*W = tsh * Ws)
    {
        int j = t & 127, q = t >> 7;
        float part = 0.f;
        int k0 = q * 32;
#pragma unroll
        for (int k = 0; k < 32; k++)
            part += tshSh[k0 + k] * __uint_as_float(Ws[(k0 + k) * WSD + j]);
        bpart[q][j] = part;
    }
    __syncthreads();
    if (t < HD) biasSh[t] += bpart[0][t] + bpart[1][t] + bpart[2][t] + bpart[3][t];
    __syncthreads();

    int lane = t & 31, g = lane >> 2, tg = lane & 3, w = t >> 5;
    int rwb = (w & 3) * 32;
    int cwb = (w >> 2) * 32;

    float acc[2][4][4];
#pragma unroll
    for (int m = 0; m < 2; m++)
#pragma unroll
        for (int nt = 0; nt < 4; nt++)
#pragma unroll
            for (int j = 0; j < 4; j++) acc[m][nt][j] = 0.f;

    unsigned aA[8], bA[8], aB[8], bB[8];

#define LDFRAG(K0, AA, BB)                                           \
    {                                                                \
        _Pragma("unroll")                                            \
        for (int m = 0; m < 2; m++) {                                \
            int r0 = rwb + m * 16 + g;                               \
            AA[m*4+0] = Xs[r0 * XS + (K0) + tg];                     \
            AA[m*4+1] = Xs[(r0 + 8) * XS + (K0) + tg];               \
            AA[m*4+2] = Xs[r0 * XS + (K0) + tg + 4];                 \
            AA[m*4+3] = Xs[(r0 + 8) * XS + (K0) + tg + 4];           \
        }                                                            \
        _Pragma("unroll")                                            \
        for (int nt = 0; nt < 4; nt++) {                             \
            int cc = cwb + nt * 8 + g;                               \
            BB[nt*2+0] = Ws[((K0) + tg) * WSD + cc];                 \
            BB[nt*2+1] = Ws[((K0) + tg + 4) * WSD + cc];             \
        }                                                            \
    }

    LDFRAG(0, aA, bA);
#pragma unroll
    for (int k = 0; k < 16; k += 2) {
        if (k + 1 < 16) LDFRAG((k + 1) * 8, aB, bB);
#pragma unroll
        for (int m = 0; m < 2; m++)
#pragma unroll
            for (int nt = 0; nt < 4; nt++)
                mma_tf32(acc[m][nt], aA + m * 4, bA + nt * 2);
        if (k + 2 < 16) LDFRAG((k + 2) * 8, aA, bA);
#pragma unroll
        for (int m = 0; m < 2; m++)
#pragma unroll
            for (int nt = 0; nt < 4; nt++)
                mma_tf32(acc[m][nt], aB + m * 4, bB + nt * 2);
    }
#undef LDFRAG

    float ls[4][2], lq[4][2];
#pragma unroll
    for (int nt = 0; nt < 4; nt++) { ls[nt][0]=0.f; ls[nt][1]=0.f; lq[nt][0]=0.f; lq[nt][1]=0.f; }

#pragma unroll
    for (int nt = 0; nt < 4; nt++) {
        int col = cwb + nt * 8 + 2 * tg;
        float bx = biasSh[col], by = biasSh[col + 1];
#pragma unroll
        for (int m = 0; m < 2; m++) {
            int r0 = base + rwb + m * 16 + g;
            int r1 = r0 + 8;
            float y00 = acc[m][nt][0] + bx, y01 = acc[m][nt][1] + by;
            float y10 = acc[m][nt][2] + bx, y11 = acc[m][nt][3] + by;
            if (doRelu) {
                y00 = fmaxf(y00, 0.f); y01 = fmaxf(y01, 0.f);
                y10 = fmaxf(y10, 0.f); y11 = fmaxf(y11, 0.f);
            }
            if (r0 < N) {
                ((float2*)J.Y)[(size_t)r0 * 64 + (col >> 1)] = make_float2(y00, y01);
                ls[nt][0] += y00; lq[nt][0] += y00 * y00;
                ls[nt][1] += y01; lq[nt][1] += y01 * y01;
            }
            if (r1 < N) {
                ((float2*)J.Y)[(size_t)r1 * 64 + (col >> 1)] = make_float2(y10, y11);
                ls[nt][0] += y10; lq[nt][0] += y10 * y10;
                ls[nt][1] += y11; lq[nt][1] += y11 * y11;
            }
        }
    }

    if (J.sSout) {
#pragma unroll
        for (int off = 4; off <= 16; off <<= 1)
#pragma unroll
            for (int nt = 0; nt < 4; nt++)
#pragma unroll
                for (int j = 0; j < 2; j++) {
                    ls[nt][j] += __shfl_xor_sync(0xffffffffu, ls[nt][j], off);
                    lq[nt][j] += __shfl_xor_sync(0xffffffffu, lq[nt][j], off);
                }
        if (g == 0) {
#pragma unroll
            for (int nt = 0; nt < 4; nt++)
#pragma unroll
                for (int j = 0; j < 2; j++) {
                    int col = cwb + nt * 8 + 2 * tg + j;
                    atomicAdd(&ssum[col], ls[nt][j]);
                    atomicAdd(&ssq[col],  lq[nt][j]);
                }
        }
        __syncthreads();
        if (t < HD) { atomicAdd(&J.sSout[t], ssum[t]); atomicAdd(&J.sQout[t], ssq[t]); }
    }
}

// ---------------- CSR build ------------------------------------------------------
__global__ void k_hist(const int* __restrict__ row, const int* __restrict__ col, int E) {
    int e = blockIdx.x * blockDim.x + threadIdx.x;
    if (e < E) {
        atomicAdd(&g_cnt[col[e]], 1);
        atomicAdd(&g_dcnt[row[e]], 1);
    }
}

__global__ void __launch_bounds__(1024) k_scan1(int N) {
    __shared__ int wsum[32];
    int t = threadIdx.x;
    int idx = blockIdx.x * 1024 + t;
    int v = (idx < N) ? g_cnt[idx] : 0;
    int x = v;
#pragma unroll
    for (int off = 1; off < 32; off <<= 1) {
        int y = __shfl_up_sync(0xffffffffu, x, off);
        if ((t & 31) >= off) x += y;
    }
    if ((t & 31) == 31) wsum[t >> 5] = x;
    __syncthreads();
    if (t < 32) {
        int y = wsum[t];
#pragma unroll
        for (int off = 1; off < 32; off <<= 1) {
            int z = __shfl_up_sync(0xffffffffu, y, off);
            if (t >= off) y += z;
        }
        wsum[t] = y;
    }
    __syncthreads();
    int winc = (t >= 32) ? wsum[(t >> 5) - 1] : 0;
    int incl = x + winc;
    if (idx < N) g_rowptr[idx] = incl - v;
    if (t == 1023) g_bsum[blockIdx.x] = incl;
}

__global__ void k_scan2(int nb) {
    __shared__ int s[64];
    int t = threadIdx.x;
    int v = (t < nb) ? g_bsum[t] : 0;
    s[t] = v;
    __syncthreads();
    for (int off = 1; off < 64; off <<= 1) {
        int a = (t >= off) ? s[t - off] : 0;
        __syncthreads();
        s[t] += a;
        __syncthreads();
    }
    g_boff[t] = s[t] - v;
    if (t == 63) g_total = s[63];
}

__global__ void k_scan3(int N) {
    int idx = blockIdx.x * blockDim.x + threadIdx.x;
    if (idx < N) {
        int r = g_rowptr[idx] + g_boff[idx >> 10];
        g_rowptr[idx] = r;
        g_cursor[idx] = r;
    }
    if (idx == 0) g_rowptr[N] = g_total;
}

__global__ void k_fillcsr(const int* __restrict__ row, const int* __restrict__ col, int E) {
    int e = blockIdx.x * blockDim.x + threadIdx.x;
    if (e >= E) return;
    int c = col[e];
    int p = atomicAdd(&g_cursor[c], 1);
    g_er[p] = row[e];
    g_ee[p] = e;
}

__global__ void k_dinv(int N) {
    int i = blockIdx.x * blockDim.x + threadIdx.x;
    if (i < N) g_degu[i] = rsqrtf((float)g_dcnt[i] + 1.f);
}

__global__ void k_fill(float* p, float v, int n) {
    int i = blockIdx.x * blockDim.x + threadIdx.x;
    if (i < n) p[i] = v;
}

__global__ void k_rsqrt2(float* p1, float* p2, int n) {
    int i = blockIdx.x * blockDim.x + threadIdx.x;
    if (i < n) { p1[i] = rsqrtf(p1[i]); p2[i] = rsqrtf(p2[i]); }
}

// ---------------- CSR gathers -----------------------------------------------------
__global__ void __launch_bounds__(256) k_gather(const float* __restrict__ lin,
                                                float* __restrict__ out,
                                                const float* __restrict__ dinv,
                                                const float* __restrict__ b, int N,
                                                float* __restrict__ sS,
                                                float* __restrict__ sQ) {
    __shared__ float ssum[HD], ssq[HD];
    int t = threadIdx.x;
    if (t < HD) { ssum[t] = 0.f; ssq[t] = 0.f; }
    __syncthreads();
    int lane = t & 31;
    int warpId = (blockIdx.x * blockDim.x + t) >> 5;
    int nW = (blockDim.x * gridDim.x) >> 5;
    float4 bb = ((const float4*)b)[lane];
    float s0=0,s1=0,s2=0,s3=0,q0=0,q1=0,q2=0,q3=0;
    for (int i = warpId; i < N; i += nW) {
        int start = g_rowptr[i], end = g_rowptr[i + 1];
        float di = dinv[i];
        float4 acc = __ldg(&((const float4*)lin)[(size_t)i * HD4 + lane]);
        float sl = di * di;
        acc.x *= sl; acc.y *= sl; acc.z *= sl; acc.w *= sl;
        for (int j0 = start; j0 < end; j0 += 32) {
            int jj = j0 + lane;
            int r = 0; float dr = 0.f;
            if (jj < end) { r = g_er[jj]; dr = dinv[r]; }
            int cnt = min(32, end - j0);
            for (int k = 0; k < cnt; k++) {
                int   rr = __shfl_sync(0xffffffffu, r, k);
                float nn = __shfl_sync(0xffffffffu, dr, k) * di;
                float4 v = __ldg(&((const float4*)lin)[(size_t)rr * HD4 + lane]);
                acc.x += v.x * nn; acc.y += v.y * nn;
                acc.z += v.z * nn; acc.w += v.w * nn;
            }
        }
        acc.x = fmaxf(acc.x + bb.x, 0.f); acc.y = fmaxf(acc.y + bb.y, 0.f);
        acc.z = fmaxf(acc.z + bb.z, 0.f); acc.w = fmaxf(acc.w + bb.w, 0.f);
        ((float4*)out)[(size_t)i * HD4 + lane] = acc;
        s0 += acc.x; q0 += acc.x*acc.x; s1 += acc.y; q1 += acc.y*acc.y;
        s2 += acc.z; q2 += acc.z*acc.z; s3 += acc.w; q3 += acc.w*acc.w;
    }
    if (sS) {
        atomicAdd(&ssum[lane*4+0], s0); atomicAdd(&ssq[lane*4+0], q0);
        atomicAdd(&ssum[lane*4+1], s1); atomicAdd(&ssq[lane*4+1], q1);
        atomicAdd(&ssum[lane*4+2], s2); atomicAdd(&ssq[lane*4+2], q2);
        atomicAdd(&ssum[lane*4+3], s3); atomicAdd(&ssq[lane*4+3], q3);
        __syncthreads();
        if (t < HD) { atomicAdd(&sS[t], ssum[t]); atomicAdd(&sQ[t], ssq[t]); }
    }
}

__global__ void __launch_bounds__(256) k_gather2(const float* __restrict__ linC,
                                                 const float* __restrict__ linO,
                                                 float* __restrict__ outC,
                                                 float* __restrict__ outO,
                                                 const float* __restrict__ dc,
                                                 const float* __restrict__ dd,
                                                 const float* __restrict__ bc,
                                                 const float* __restrict__ bo, int N,
                                                 float* sSc, float* sQc,
                                                 float* sSo, float* sQo) {
    __shared__ float red[4][HD];
    int t = threadIdx.x;
    for (int i = t; i < 4 * HD; i += blockDim.x) ((float*)red)[i] = 0.f;
    __syncthreads();
    int lane = t & 31;
    int warpId = (blockIdx.x * blockDim.x + t) >> 5;
    int nW = (blockDim.x * gridDim.x) >> 5;
    float4 bbc = ((const float4*)bc)[lane];
    float4 bbo = ((const float4*)bo)[lane];
    float sc[4]={0,0,0,0}, qc[4]={0,0,0,0}, so[4]={0,0,0,0}, qo[4]={0,0,0,0};
    for (int i = warpId; i < N; i += nW) {
        int start = g_rowptr[i], end = g_rowptr[i + 1];
        float dci = dc[i], doi = dd[i];
        float4 aC = __ldg(&((const float4*)linC)[(size_t)i * HD4 + lane]);
        float4 aO = __ldg(&((const float4*)linO)[(size_t)i * HD4 + lane]);
        float slc = dci * dci, slo = doi * doi;
        aC.x *= slc; aC.y *= slc; aC.z *= slc; aC.w *= slc;
        aO.x *= slo; aO.y *= slo; aO.z *= slo; aO.w *= slo;
        for (int j0 = start; j0 < end; j0 += 32) {
            int jj = j0 + lane;
            float wc = 0.f, wo = 0.f; int r = 0;
            if (jj < end) {
                r = g_er[jj];
                int e = g_ee[jj];
                wc = dc[r] * g_att0[e];
                wo = dd[r] * g_att1[e];
            }
            int cnt = min(32, end - j0);
            for (int k = 0; k < cnt; k++) {
                int   rr = __shfl_sync(0xffffffffu, r, k);
                float nc = __shfl_sync(0xffffffffu, wc, k) * dci;
                float no = __shfl_sync(0xffffffffu, wo, k) * doi;
                float4 vC = __ldg(&((const float4*)linC)[(size_t)rr * HD4 + lane]);
                float4 vO = __ldg(&((const float4*)linO)[(size_t)rr * HD4 + lane]);
                aC.x += vC.x * nc; aC.y += vC.y * nc; aC.z += vC.z * nc; aC.w += vC.w * nc;
                aO.x += vO.x * no; aO.y += vO.y * no; aO.z += vO.z * no; aO.w += vO.w * no;
            }
        }
        aC.x = fmaxf(aC.x + bbc.x, 0.f); aC.y = fmaxf(aC.y + bbc.y, 0.f);
        aC.z = fmaxf(aC.z + bbc.z, 0.f); aC.w = fmaxf(aC.w + bbc.w, 0.f);
        aO.x = fmaxf(aO.x + bbo.x, 0.f); aO.y = fmaxf(aO.y + bbo.y, 0.f);
        aO.z = fmaxf(aO.z + bbo.z, 0.f); aO.w = fmaxf(aO.w + bbo.w, 0.f);
        ((float4*)outC)[(size_t)i * HD4 + lane] = aC;
        ((float4*)outO)[(size_t)i * HD4 + lane] = aO;
        sc[0]+=aC.x; qc[0]+=aC.x*aC.x; sc[1]+=aC.y; qc[1]+=aC.y*aC.y;
        sc[2]+=aC.z; qc[2]+=aC.z*aC.z; sc[3]+=aC.w; qc[3]+=aC.w*aC.w;
        so[0]+=aO.x; qo[0]+=aO.x*aO.x; so[1]+=aO.y; qo[1]+=aO.y*aO.y;
        so[2]+=aO.z; qo[2]+=aO.z*aO.z; so[3]+=aO.w; qo[3]+=aO.w*aO.w;
    }
#pragma unroll
    for (int j = 0; j < 4; j++) {
        atomicAdd(&red[0][lane*4+j], sc[j]);
        atomicAdd(&red[1][lane*4+j], qc[j]);
        atomicAdd(&red[2][lane*4+j], so[j]);
        atomicAdd(&red[3][lane*4+j], qo[j]);
    }
    __syncthreads();
    if (t < HD) {
        atomicAdd(&sSc[t], red[0][t]); atomicAdd(&sQc[t], red[1][t]);
        atomicAdd(&sSo[t], red[2][t]); atomicAdd(&sQo[t], red[3][t]);
    }
}

// ---------------- attention --------------------------------------------------------
__global__ void k_att_node(const float* __restrict__ h,
                           const float* __restrict__ Wna, const float* __restrict__ bna,
                           const float* __restrict__ Wea,
                           float* __restrict__ xc, float* __restrict__ xo, int N,
                           float* sSc, float* sQc, float* sSo, float* sQo) {
    __shared__ float Wc[HD * 6];
    __shared__ float red[4][HD];
    int t = threadIdx.x;
    for (int i = t; i < HD * 6; i += blockDim.x) {
        int k = i / 6, j = i % 6;
        float v;
        if (j < 2)      v = Wna[k * 2 + j];
        else if (j < 4) v = Wea[k * 2 + (j - 2)];
        else            v = Wea[(HD + k) * 2 + (j - 4)];
        Wc[i] = v;
    }
    for (int i = t; i < 4 * HD; i += blockDim.x) ((float*)red)[i] = 0.f;
    __syncthreads();
    int warps = (blockDim.x * gridDim.x) >> 5;
    int gw = (blockIdx.x * blockDim.x + t) >> 5;
    int l  = t & 31;
    float b0 = bna[0], b1 = bna[1];
    float sc[4]={0,0,0,0}, qc[4]={0,0,0,0}, so[4]={0,0,0,0}, qo[4]={0,0,0,0};
    for (int i = gw; i < N; i += warps) {
        float4 hv = ((const float4*)h)[(size_t)i * HD4 + l];
        float p[6];
#pragma unroll
        for (int j = 0; j < 6; j++) {
            p[j] = hv.x * Wc[(4*l+0)*6 + j] + hv.y * Wc[(4*l+1)*6 + j]
                 + hv.z * Wc[(4*l+2)*6 + j] + hv.w * Wc[(4*l+3)*6 + j];
        }
#pragma unroll
        for (int off = 16; off; off >>= 1)
#pragma unroll
            for (int j = 0; j < 6; j++)
                p[j] += __shfl_xor_sync(0xffffffffu, p[j], off);
        float l0 = p[0] + b0, l1 = p[1] + b1;
        float m  = fmaxf(l0, l1);
        float e0 = expf(l0 - m), e1 = expf(l1 - m);
        float inv = 1.f / (e0 + e1);
        float a0 = e0 * inv, a1 = e1 * inv;
        float4 vc = make_float4(hv.x*a0, hv.y*a0, hv.z*a0, hv.w*a0);
        float4 vo = make_float4(hv.x*a1, hv.y*a1, hv.z*a1, hv.w*a1);
        ((float4*)xc)[(size_t)i * HD4 + l] = vc;
        ((float4*)xo)[(size_t)i * HD4 + l] = vo;
        sc[0]+=vc.x; qc[0]+=vc.x*vc.x; sc[1]+=vc.y; qc[1]+=vc.y*vc.y;
        sc[2]+=vc.z; qc[2]+=vc.z*vc.z; sc[3]+=vc.w; qc[3]+=vc.w*vc.w;
        so[0]+=vo.x; qo[0]+=vo.x*vo.x; so[1]+=vo.y; qo[1]+=vo.y*vo.y;
        so[2]+=vo.z; qo[2]+=vo.z*vo.z; so[3]+=vo.w; qo[3]+=vo.w*vo.w;
        if (l == 0) g_eanode[i] = make_float4(p[2], p[3], p[4], p[5]);
    }
#pragma unroll
    for (int j = 0; j < 4; j++) {
        atomicAdd(&red[0][l*4+j], sc[j]);
        atomicAdd(&red[1][l*4+j], qc[j]);
        atomicAdd(&red[2][l*4+j], so[j]);
        atomicAdd(&red[3][l*4+j], qo[j]);
    }
    __syncthreads();
    if (t < HD) {
        atomicAdd(&sSc[t], red[0][t]); atomicAdd(&sQc[t], red[1][t]);
        atomicAdd(&sSo[t], red[2][t]); atomicAdd(&sQo[t], red[3][t]);
    }
}

__global__ void k_att_edge(const int* __restrict__ row, const int* __restrict__ col,
                           const float* __restrict__ bea, int E) {
    int e = blockIdx.x * blockDim.x + threadIdx.x;
    if (e >= E) return;
    int r = row[e], c = col[e];
    float4 tr = g_eanode[r], tc = g_eanode[c];
    float l0 = tr.x + tc.z + bea[0];
    float l1 = tr.y + tc.w + bea[1];
    float m  = fmaxf(l0, l1);
    float e0 = expf(l0 - m), e1 = expf(l1 - m);
    float inv = 1.f / (e0 + e1);
    float a0 = e0 * inv, a1 = e1 * inv;
    g_att0[e] = a0; g_att1[e] = a1;
    atomicAdd(&g_degc[r], a0);
    atomicAdd(&g_dego[r], a1);
}

__global__ void k_permadd_stats(const float* __restrict__ xc, const float* __restrict__ xo,
                                const int* __restrict__ perm, float* __restrict__ z, int N,
                                float* __restrict__ sS, float* __restrict__ sQ) {
    __shared__ float ssum[HD], ssq[HD];
    int t = threadIdx.x;
    if (t < HD) { ssum[t] = 0.f; ssq[t] = 0.f; }
    __syncthreads();
    int total  = N * HD4;
    int stride = blockDim.x * gridDim.x;
    int idx    = blockIdx.x * blockDim.x + t;
    int fb     = (idx & 31) * 4;
    float a0=0,a1=0,a2=0,a3=0,q0=0,q1=0,q2=0,q3=0;
    for (; idx < total; idx += stride) {
        int i = idx >> 5, l = idx & 31;
        int p = perm[i];
        float4 a = ((const float4*)xc)[(size_t)p * HD4 + l];
        float4 b = ((const float4*)xo)[idx];
        a.x += b.x; a.y += b.y; a.z += b.z; a.w += b.w;
        ((float4*)z)[idx] = a;
        a0 += a.x; q0 += a.x*a.x; a1 += a.y; q1 += a.y*a.y;
        a2 += a.z; q2 += a.z*a.z; a3 += a.w; q3 += a.w*a.w;
    }
    atomicAdd(&ssum[fb+0], a0); atomicAdd(&ssq[fb+0], q0);
    atomicAdd(&ssum[fb+1], a1); atomicAdd(&ssq[fb+1], q1);
    atomicAdd(&ssum[fb+2], a2); atomicAdd(&ssq[fb+2], q2);
    atomicAdd(&ssum[fb+3], a3); atomicAdd(&ssq[fb+3], q3);
    __syncthreads();
    if (t < HD) { atomicAdd(&sS[t], ssum[t]); atomicAdd(&sQ[t], ssq[t]); }
}

// ---------------- [N,128]x[128,10] + log_softmax, inline fold, batched ----------
__global__ void k_gemm2_lsm(LJobs jobs, int N, float invN) {
    __shared__ float Ws[HD * 10];
    __shared__ float bs[10];
    __shared__ float scaleSh[HD], tshSh[HD];
    const LJob J = jobs.j[blockIdx.y];
    int t = threadIdx.x;
    if (t < HD) {
        float mu  = J.sSin[t] * invN;
        float var = fmaxf(J.sQin[t] * invN - mu * mu, 0.f);
        float rs  = rsqrtf(var + 1e-5f);
        scaleSh[t] = rs;
        tshSh[t]   = 1e-4f / rs - mu;
    }
    __syncthreads();
    for (int i = t; i < HD * 10; i += blockDim.x)
        Ws[i] = scaleSh[i / 10] * J.W[i];
    __syncthreads();
    if (t < 160) {
        int j = t / 16, seg = t % 16;
        float part = 0.f;
#pragma unroll
        for (int k = 0; k < 8; k++) {
            int kk = seg * 8 + k;
            part += tshSh[kk] * Ws[kk * 10 + j];
        }
#pragma unroll
        for (int off = 8; off; off >>= 1)
            part += __shfl_down_sync(0xffffffffu, part, off, 16);
        if (seg == 0) bs[j] = J.b[j] + part;
    }
    __syncthreads();
    int warps = (blockDim.x * gridDim.x) >> 5;
    int gw = (blockIdx.x * blockDim.x + t) >> 5;
    int l  = t & 31;
    for (int i = gw; i < N; i += warps) {
        float4 z = ((const float4*)J.Z)[(size_t)i * HD4 + l];
        float p[10];
#pragma unroll
        for (int j = 0; j < 10; j++) {
            p[j] = z.x * Ws[(4*l+0)*10 + j] + z.y * Ws[(4*l+1)*10 + j]
                 + z.z * Ws[(4*l+2)*10 + j] + z.w * Ws[(4*l+3)*10 + j];
        }
#pragma unroll
        for (int off = 16; off; off >>= 1)
#pragma unroll
            for (int j = 0; j < 10; j++)
                p[j] += __shfl_xor_sync(0xffffffffu, p[j], off);
        float m = -1e30f;
#pragma unroll
        for (int j = 0; j < 10; j++) { p[j] += bs[j]; m = fmaxf(m, p[j]); }
        float s = 0.f;
#pragma unroll
        for (int j = 0; j < 10; j++) s += expf(p[j] - m);
        float lse = m + logf(s);
        if (l < 10) J.out[(size_t)i * 10 + l] = p[l] - lse;
    }
}

// ---------------- host orchestration ------------------------------------------------
extern "C" void kernel_launch(void* const* d_in, const int* in_sizes, int n_in,
                              void* d_out, int out_size) {
    const float* x      = (const float*)d_in[0];
    const int*   ei     = (const int*)  d_in[1];
    const int*   perm   = (const int*)  d_in[2];
    const float* W_feat = (const float*)d_in[3];
    const float* b_feat = (const float*)d_in[4];
    const float* W_convs= (const float*)d_in[5];
    const float* b_convs= (const float*)d_in[6];
    const float* W_ea   = (const float*)d_in[7];
    const float* b_ea   = (const float*)d_in[8];
    const float* W_na   = (const float*)d_in[9];
    const float* b_na   = (const float*)d_in[10];
    const float* W_ctx  = (const float*)d_in[11];
    const float* b_ctx  = (const float*)d_in[12];
    const float* W_obj  = (const float*)d_in[13];
    const float* b_obj  = (const float*)d_in[14];
    const float* W_fc1  = (const float*)d_in[15];
    const float* b_fc1  = (const float*)d_in[16];
    const float* W_fc2  = (const float*)d_in[17];
    const float* b_fc2  = (const float*)d_in[18];

    int N = in_sizes[0] / HD;
    int E = in_sizes[1] / 2;
    const int* row = ei;
    const int* col = ei + E;
    float* out = (float*)d_out;

    float* Bbase = nullptr;
    cudaGetSymbolAddress((void**)&Bbase, g_B);
    float* B0 = Bbase + 0 * (size_t)MAXN * HD;
    float* B1 = Bbase + 1 * (size_t)MAXN * HD;
    float* B2 = Bbase + 2 * (size_t)MAXN * HD;
    float* B3 = Bbase + 3 * (size_t)MAXN * HD;
    float* B4 = Bbase + 4 * (size_t)MAXN * HD;
    float* B5 = Bbase + 5 * (size_t)MAXN * HD;
    float *degup, *degcp, *degop, *ssump, *ssqp;
    int *cntp, *dcntp;
    cudaGetSymbolAddress((void**)&degup, g_degu);
    cudaGetSymbolAddress((void**)&degcp, g_degc);
    cudaGetSymbolAddress((void**)&degop, g_dego);
    cudaGetSymbolAddress((void**)&ssump, g_ssum);
    cudaGetSymbolAddress((void**)&ssqp,  g_ssq);
    cudaGetSymbolAddress((void**)&cntp,  g_cnt);
    cudaGetSymbolAddress((void**)&dcntp, g_dcnt);
    auto S = [&](int i) { return ssump + i * HD; };
    auto Q = [&](int i) { return ssqp  + i * HD; };

    const int gemm_smem = (128 * XS + 128 * WSD) * 4;
    cudaFuncSetAttribute(k_gemm_tc, cudaFuncAttributeMaxDynamicSharedMemorySize, gemm_smem);

    int gbGemm = (N + 127) / 128;
    int gbN    = (N + 255) / 256;
    int gbE    = (E + 255) / 256;
    int nb     = (N + 1023) / 1024;
    float invN = 1.f / (float)N;

    auto gemm1 = [&](const float* X, float* Y, const float* W, const float* b,
                     int sin, int sout, int relu) {
        GJobs js{};
        js.j[0] = {X, Y, W, b, S(sin), Q(sin),
                   sout >= 0 ? S(sout) : nullptr, sout >= 0 ? Q(sout) : nullptr};
        k_gemm_tc<<<dim3(gbGemm, 1), 512, gemm_smem>>>(js, N, relu, invN);
    };

    k_zero_slots<<<(NSLOT * HD + 255) / 256, 256>>>();

    // CSR + degree build
    cudaMemsetAsync(cntp, 0, (size_t)N * sizeof(int));
    cudaMemsetAsync(dcntp, 0, (size_t)N * sizeof(int));
    k_hist<<<gbE, 256>>>(row, col, E);
    k_scan1<<<nb, 1024>>>(N);
    k_scan2<<<1, 64>>>(nb);
    k_scan3<<<nb, 1024>>>(N);
    k_fillcsr<<<gbE, 256>>>(row, col, E);
    k_dinv<<<gbN, 256>>>(N);

    // stage 0
    k_stats<<<512, 256>>>(x, N, S(0), Q(0));
    gemm1(x, B2, W_feat, b_feat, 0, 1, 1);

    // conv1: B2 -> B0
    gemm1(B2, B1, W_convs + 0 * HD * HD, nullptr, 1, -1, 0);
    k_gather<<<1024, 256>>>(B1, B0, degup, b_convs + 0 * HD, N, S(2), Q(2));
    // conv2: B0 -> B2
    gemm1(B0, B1, W_convs + 1 * HD * HD, nullptr, 2, -1, 0);
    k_gather<<<1024, 256>>>(B1, B2, degup, b_convs + 1 * HD, N, S(3), Q(3));
    // conv3: B2 -> B0
    gemm1(B2, B1, W_convs + 2 * HD * HD, nullptr, 3, -1, 0);
    k_gather<<<1024, 256>>>(B1, B0, degup, b_convs + 2 * HD, N, nullptr, nullptr);

    // attention: h=B0 -> xc=B2 (s4), xo=B3 (s5)
    k_att_node<<<256, 256>>>(B0, W_na, b_na, W_ea, B2, B3, N, S(4), Q(4), S(5), Q(5));
    k_fill<<<gbN, 256>>>(degcp, 1.f, N);
    k_fill<<<gbN, 256>>>(degop, 1.f, N);
    k_att_edge<<<gbE, 256>>>(row, col, b_ea, E);
    k_rsqrt2<<<gbN, 256>>>(degcp, degop, N);

    // batched ctx/obj linear: {B2->B1}, {B3->B5}
    {
        GJobs js{};
        js.j[0] = {B2, B1, W_ctx, nullptr, S(4), Q(4), nullptr, nullptr};
        js.j[1] = {B3, B5, W_obj, nullptr, S(5), Q(5), nullptr, nullptr};
        k_gemm_tc<<<dim3(gbGemm, 2), 512, gemm_smem>>>(js, N, 0, invN);
    }
    // merged weighted gather: xc2=B4 (s6), xo2=B3 (s7)
    k_gather2<<<1024, 256>>>(B1, B5, B4, B3, degcp, degop, b_ctx, b_obj, N,
                             S(6), Q(6), S(7), Q(7));

    // permadd: z = B4[perm] + B3 -> B1 (s11)
    k_permadd_stats<<<256, 256>>>(B4, B3, perm, B1, N, S(11), Q(11));

    // batched readout fc1: {B4->B0}, {B3->B5}, {B1->B2}, relu, stats 8/9/10
    {
        GJobs js{};
        js.j[0] = {B4, B0, W_fc1 + 0 * HD * HD, b_fc1 + 0 * HD, S(6),  Q(6),  S(8),  Q(8)};
        js.j[1] = {B3, B5, W_fc1 + 1 * HD * HD, b_fc1 + 1 * HD, S(7),  Q(7),  S(9),  Q(9)};
        js.j[2] = {B1, B2, W_fc1 + 2 * HD * HD, b_fc1 + 2 * HD, S(11), Q(11), S(10), Q(10)};
        k_gemm_tc<<<dim3(gbGemm, 3), 512, gemm_smem>>>(js, N, 1, invN);
    }
    // batched lsm
    {
        LJobs js{};
        js.j[0] = {B0, out,                      W_fc2 + 0 * HD * 10, b_fc2 + 0 * 10, S(8),  Q(8)};
        js.j[1] = {B5, out + (size_t)N * 10,     W_fc2 + 1 * HD * 10, b_fc2 + 1 * 10, S(9),  Q(9)};
        js.j[2] = {B2, out + (size_t)2 * N * 10, W_fc2 + 2 * HD * 10, b_fc2 + 2 * 10, S(10), Q(10)};
        k_gemm2_lsm<<<dim3(512, 3), 256>>>(js, N, invN);
    }
}

// round 5
// speedup vs baseline: 3.2992x; 1.0272x over previous
#include <cuda_runtime.h>
#include <cuda_fp16.h>

#define HD   128
#define HD4  32
#define MAXN 50000
#define MAXE 800000
#define XS   132
#define WSD  136
#define NSLOT 12

// ---------------- scratch ------------------------------------------------------
static __device__ float  g_B[6][(size_t)MAXN * HD];
static __device__ float4 g_eanode[MAXN];
static __device__ float  g_att0[MAXE];
static __device__ float  g_att1[MAXE];
static __device__ float  g_degu[MAXN];
static __device__ float  g_degc[MAXN];
static __device__ float  g_dego[MAXN];
static __device__ float  g_ssum[NSLOT * HD];
static __device__ float  g_ssq [NSLOT * HD];
// CSR
static __device__ int    g_cnt[MAXN];
static __device__ int    g_dcnt[MAXN];
static __device__ int    g_rowptr[MAXN + 1];
static __device__ int    g_cursor[MAXN];
static __device__ int    g_er[MAXE];
static __device__ int    g_ee[MAXE];
static __device__ int    g_bsum[64];
static __device__ int    g_boff[64];
static __device__ int    g_total;

struct GJob {
    const float* X; float* Y; const float* W; const float* b;
    const float* sSin; const float* sQin; float* sSout; float* sQout;
};
struct GJobs { GJob j[3]; };
struct LJob {
    const float* Z; float* out; const float* W; const float* b;
    const float* sSin; const float* sQin;
};
struct LJobs { LJob j[3]; };

__device__ __forceinline__ unsigned f2tf(float f) {
    unsigned r; asm("cvt.rna.tf32.f32 %0, %1;" : "=r"(r) : "f"(f)); return r;
}

__device__ __forceinline__ void mma_tf32(float* c, const unsigned* a, const unsigned* b) {
    asm volatile(
        "mma.sync.aligned.m16n8k8.row.col.f32.tf32.tf32.f32 "
        "{%0,%1,%2,%3}, {%4,%5,%6,%7}, {%8,%9}, {%0,%1,%2,%3};"
        : "+f"(c[0]), "+f"(c[1]), "+f"(c[2]), "+f"(c[3])
        : "r"(a[0]), "r"(a[1]), "r"(a[2]), "r"(a[3]), "r"(b[0]), "r"(b[1]));
}

// ---------------- misc small kernels -------------------------------------------
__global__ void k_zero_slots() {
    int i = blockIdx.x * blockDim.x + threadIdx.x;
    if (i < NSLOT * HD) { g_ssum[i] = 0.f; g_ssq[i] = 0.f; }
}

__global__ void k_stats(const float* __restrict__ X, int N,
                        float* __restrict__ sS, float* __restrict__ sQ) {
    __shared__ float ss[HD], sq[HD];
    int t = threadIdx.x;
    if (t < HD) { ss[t] = 0.f; sq[t] = 0.f; }
    __syncthreads();
    int total  = N * HD4;
    int stride = blockDim.x * gridDim.x;
    int idx    = blockIdx.x * blockDim.x + t;
    int fb     = (idx & 31) * 4;
    float a0=0,a1=0,a2=0,a3=0,q0=0,q1=0,q2=0,q3=0;
    for (; idx < total; idx += stride) {
        float4 v = ((const float4*)X)[idx];
        a0 += v.x; q0 += v.x * v.x;
        a1 += v.y; q1 += v.y * v.y;
        a2 += v.z; q2 += v.z * v.z;
        a3 += v.w; q3 += v.w * v.w;
    }
    atomicAdd(&ss[fb+0], a0); atomicAdd(&sq[fb+0], q0);
    atomicAdd(&ss[fb+1], a1); atomicAdd(&sq[fb+1], q1);
    atomicAdd(&ss[fb+2], a2); atomicAdd(&sq[fb+2], q2);
    atomicAdd(&ss[fb+3], a3); atomicAdd(&sq[fb+3], q3);
    __syncthreads();
    if (t < HD) { atomicAdd(&sS[t], ss[t]); atomicAdd(&sQ[t], sq[t]); }
}

// ---------------- tf32 GEMM with inline BN fold, batched; optional fp16 out ----
__global__ void __launch_bounds__(512) k_gemm_tc(GJobs jobs, int N, int doRelu,
                                                 int outHalf, float invN) {
    extern __shared__ unsigned sh[];
    unsigned* Xs = sh;
    unsigned* Ws = sh + 128 * XS;
    __shared__ float ssum[HD], ssq[HD], scaleSh[HD], tshSh[HD], biasSh[HD];
    __shared__ float bpart[4][HD];
    const GJob J = jobs.j[blockIdx.y];
    int t = threadIdx.x;
    if (t < HD) {
        ssum[t] = 0.f; ssq[t] = 0.f;
        float mu  = J.sSin[t] * invN;
        float var = fmaxf(J.sQin[t] * invN - mu * mu, 0.f);
        float rs  = rsqrtf(var + 1e-5f);
        scaleSh[t] = rs;
        tshSh[t]   = 1e-4f / rs - mu;
        biasSh[t]  = J.b ? J.b[t] : 0.f;
    }
    __syncthreads();
    int base = blockIdx.x * 128;
#pragma unroll
    for (int i = t; i < 4096; i += 512) {
        int r = i >> 5, c = i & 31, gr = base + r;
        float4 v = make_float4(0.f, 0.f, 0.f, 0.f);
        if (gr < N) v = ((const float4*)J.X)[(size_t)gr * 32 + c];
        *(uint4*)&Xs[r * XS + c * 4] =
            make_uint4(f2tf(v.x), f2tf(v.y), f2tf(v.z), f2tf(v.w));
    }
#pragma unroll
    for (int i = t; i < 4096; i += 512) {
        int r = i >> 5, c = i & 31;
        float4 v = ((const float4*)J.W)[i];
        float s = scaleSh[r];
        *(uint4*)&Ws[r * WSD + c * 4] =
            make_uint4(f2tf(v.x * s), f2tf(v.y * s), f2tf(v.z * s), f2tf(v.w * s));
    }
    __syncthreads();

    {
        int j = t & 127, q = t >> 7;
        float part = 0.f;
        int k0 = q * 32;
#pragma unroll
        for (int k = 0; k < 32; k++)
            part += tshSh[k0 + k] * __uint_as_float(Ws[(k0 + k) * WSD + j]);
        bpart[q][j] = part;
    }
    __syncthreads();
    if (t < HD) biasSh[t] += bpart[0][t] + bpart[1][t] + bpart[2][t] + bpart[3][t];
    __syncthreads();

    int lane = t & 31, g = lane >> 2, tg = lane & 3, w = t >> 5;
    int rwb = (w & 3) * 32;
    int cwb = (w >> 2) * 32;

    float acc[2][4][4];
#pragma unroll
    for (int m = 0; m < 2; m++)
#pragma unroll
        for (int nt = 0; nt < 4; nt++)
#pragma unroll
            for (int j = 0; j < 4; j++) acc[m][nt][j] = 0.f;

    unsigned aA[8], bA[8], aB[8], bB[8];

#define LDFRAG(K0, AA, BB)                                           \
    {                                                                \
        _Pragma("unroll")                                            \
        for (int m = 0; m < 2; m++) {                                \
            int r0 = rwb + m * 16 + g;                               \
            AA[m*4+0] = Xs[r0 * XS + (K0) + tg];                     \
            AA[m*4+1] = Xs[(r0 + 8) * XS + (K0) + tg];               \
            AA[m*4+2] = Xs[r0 * XS + (K0) + tg + 4];                 \
            AA[m*4+3] = Xs[(r0 + 8) * XS + (K0) + tg + 4];           \
        }                                                            \
        _Pragma("unroll")                                            \
        for (int nt = 0; nt < 4; nt++) {                             \
            int cc = cwb + nt * 8 + g;                               \
            BB[nt*2+0] = Ws[((K0) + tg) * WSD + cc];                 \
            BB[nt*2+1] = Ws[((K0) + tg + 4) * WSD + cc];             \
        }                                                            \
    }

    LDFRAG(0, aA, bA);
#pragma unroll
    for (int k = 0; k < 16; k += 2) {
        if (k + 1 < 16) LDFRAG((k + 1) * 8, aB, bB);
#pragma unroll
        for (int m = 0; m < 2; m++)
#pragma unroll
            for (int nt = 0; nt < 4; nt++)
                mma_tf32(acc[m][nt], aA + m * 4, bA + nt * 2);
        if (k + 2 < 16) LDFRAG((k + 2) * 8, aA, bA);
#pragma unroll
        for (int m = 0; m < 2; m++)
#pragma unroll
            for (int nt = 0; nt < 4; nt++)
                mma_tf32(acc[m][nt], aB + m * 4, bB + nt * 2);
    }
#undef LDFRAG

    float ls[4][2], lq[4][2];
#pragma unroll
    for (int nt = 0; nt < 4; nt++) { ls[nt][0]=0.f; ls[nt][1]=0.f; lq[nt][0]=0.f; lq[nt][1]=0.f; }

#pragma unroll
    for (int nt = 0; nt < 4; nt++) {
        int col = cwb + nt * 8 + 2 * tg;
        float bx = biasSh[col], by = biasSh[col + 1];
#pragma unroll
        for (int m = 0; m < 2; m++) {
            int r0 = base + rwb + m * 16 + g;
            int r1 = r0 + 8;
            float y00 = acc[m][nt][0] + bx, y01 = acc[m][nt][1] + by;
            float y10 = acc[m][nt][2] + bx, y11 = acc[m][nt][3] + by;
            if (doRelu) {
                y00 = fmaxf(y00, 0.f); y01 = fmaxf(y01, 0.f);
                y10 = fmaxf(y10, 0.f); y11 = fmaxf(y11, 0.f);
            }
            if (r0 < N) {
                if (outHalf)
                    ((__half2*)J.Y)[(size_t)r0 * 64 + (col >> 1)] = __floats2half2_rn(y00, y01);
                else
                    ((float2*)J.Y)[(size_t)r0 * 64 + (col >> 1)] = make_float2(y00, y01);
                ls[nt][0] += y00; lq[nt][0] += y00 * y00;
                ls[nt][1] += y01; lq[nt][1] += y01 * y01;
            }
            if (r1 < N) {
                if (outHalf)
                    ((__half2*)J.Y)[(size_t)r1 * 64 + (col >> 1)] = __floats2half2_rn(y10, y11);
                else
                    ((float2*)J.Y)[(size_t)r1 * 64 + (col >> 1)] = make_float2(y10, y11);
                ls[nt][0] += y10; lq[nt][0] += y10 * y10;
                ls[nt][1] += y11; lq[nt][1] += y11 * y11;
            }
        }
    }

    if (J.sSout) {
#pragma unroll
        for (int off = 4; off <= 16; off <<= 1)
#pragma unroll
            for (int nt = 0; nt < 4; nt++)
#pragma unroll
                for (int j = 0; j < 2; j++) {
                    ls[nt][j] += __shfl_xor_sync(0xffffffffu, ls[nt][j], off);
                    lq[nt][j] += __shfl_xor_sync(0xffffffffu, lq[nt][j], off);
                }
        if (g == 0) {
#pragma unroll
            for (int nt = 0; nt < 4; nt++)
#pragma unroll
                for (int j = 0; j < 2; j++) {
                    int col = cwb + nt * 8 + 2 * tg + j;
                    atomicAdd(&ssum[col], ls[nt][j]);
                    atomicAdd(&ssq[col],  lq[nt][j]);
                }
        }
        __syncthreads();
        if (t < HD) { atomicAdd(&J.sSout[t], ssum[t]); atomicAdd(&J.sQout[t], ssq[t]); }
    }
}

// ---------------- CSR build ------------------------------------------------------
__global__ void k_hist(const int* __restrict__ row, const int* __restrict__ col, int E) {
    int e = blockIdx.x * blockDim.x + threadIdx.x;
    if (e < E) {
        atomicAdd(&g_cnt[col[e]], 1);
        atomicAdd(&g_dcnt[row[e]], 1);
    }
}

__global__ void __launch_bounds__(1024) k_scan1(int N) {
    __shared__ int wsum[32];
    int t = threadIdx.x;
    int idx = blockIdx.x * 1024 + t;
    int v = (idx < N) ? g_cnt[idx] : 0;
    int x = v;
#pragma unroll
    for (int off = 1; off < 32; off <<= 1) {
        int y = __shfl_up_sync(0xffffffffu, x, off);
        if ((t & 31) >= off) x += y;
    }
    if ((t & 31) == 31) wsum[t >> 5] = x;
    __syncthreads();
    if (t < 32) {
        int y = wsum[t];
#pragma unroll
        for (int off = 1; off < 32; off <<= 1) {
            int z = __shfl_up_sync(0xffffffffu, y, off);
            if (t >= off) y += z;
        }
        wsum[t] = y;
    }
    __syncthreads();
    int winc = (t >= 32) ? wsum[(t >> 5) - 1] : 0;
    int incl = x + winc;
    if (idx < N) g_rowptr[idx] = incl - v;
    if (t == 1023) g_bsum[blockIdx.x] = incl;
}

__global__ void k_scan2(int nb) {
    __shared__ int s[64];
    int t = threadIdx.x;
    int v = (t < nb) ? g_bsum[t] : 0;
    s[t] = v;
    __syncthreads();
    for (int off = 1; off < 64; off <<= 1) {
        int a = (t >= off) ? s[t - off] : 0;
        __syncthreads();
        s[t] += a;
        __syncthreads();
    }
    g_boff[t] = s[t] - v;
    if (t == 63) g_total = s[63];
}

__global__ void k_scan3(int N) {
    int idx = blockIdx.x * blockDim.x + threadIdx.x;
    if (idx < N) {
        int r = g_rowptr[idx] + g_boff[idx >> 10];
        g_rowptr[idx] = r;
        g_cursor[idx] = r;
    }
    if (idx == 0) g_rowptr[N] = g_total;
}

__global__ void k_fillcsr(const int* __restrict__ row, const int* __restrict__ col, int E) {
    int e = blockIdx.x * blockDim.x + threadIdx.x;
    if (e >= E) return;
    int c = col[e];
    int p = atomicAdd(&g_cursor[c], 1);
    g_er[p] = row[e];
    g_ee[p] = e;
}

// dinv for unweighted convs + init degc/dego for weighted convs
__global__ void k_dinv(int N) {
    int i = blockIdx.x * blockDim.x + threadIdx.x;
    if (i < N) {
        g_degu[i] = rsqrtf((float)g_dcnt[i] + 1.f);
        g_degc[i] = 1.f;
        g_dego[i] = 1.f;
    }
}

__global__ void k_rsqrt2(float* p1, float* p2, int n) {
    int i = blockIdx.x * blockDim.x + threadIdx.x;
    if (i < n) { p1[i] = rsqrtf(p1[i]); p2[i] = rsqrtf(p2[i]); }
}

// ---------------- CSR gathers (fp16 lin input) -----------------------------------
__device__ __forceinline__ float4 ldhalf4(const __half* lin, size_t rowBase, int lane) {
    uint2 u = __ldg((const uint2*)(lin + rowBase) + lane);
    __half2 h0 = *(__half2*)&u.x, h1 = *(__half2*)&u.y;
    float2 f0 = __half22float2(h0), f1 = __half22float2(h1);
    return make_float4(f0.x, f0.y, f1.x, f1.y);
}

__global__ void __launch_bounds__(256) k_gather(const __half* __restrict__ lin,
                                                float* __restrict__ out,
                                                const float* __restrict__ dinv,
                                                const float* __restrict__ b, int N,
                                                float* __restrict__ sS,
                                                float* __restrict__ sQ) {
    __shared__ float ssum[HD], ssq[HD];
    int t = threadIdx.x;
    if (t < HD) { ssum[t] = 0.f; ssq[t] = 0.f; }
    __syncthreads();
    int lane = t & 31;
    int warpId = (blockIdx.x * blockDim.x + t) >> 5;
    int nW = (blockDim.x * gridDim.x) >> 5;
    float4 bb = ((const float4*)b)[lane];
    float s0=0,s1=0,s2=0,s3=0,q0=0,q1=0,q2=0,q3=0;
    for (int i = warpId; i < N; i += nW) {
        int start = g_rowptr[i], end = g_rowptr[i + 1];
        float di = dinv[i];
        float4 acc = ldhalf4(lin, (size_t)i * HD, lane);
        float sl = di * di;
        acc.x *= sl; acc.y *= sl; acc.z *= sl; acc.w *= sl;
        for (int j0 = start; j0 < end; j0 += 32) {
            int jj = j0 + lane;
            int r = 0; float dr = 0.f;
            if (jj < end) { r = g_er[jj]; dr = dinv[r]; }
            int cnt = min(32, end - j0);
            for (int k = 0; k < cnt; k++) {
                int   rr = __shfl_sync(0xffffffffu, r, k);
                float nn = __shfl_sync(0xffffffffu, dr, k) * di;
                float4 v = ldhalf4(lin, (size_t)rr * HD, lane);
                acc.x += v.x * nn; acc.y += v.y * nn;
                acc.z += v.z * nn; acc.w += v.w * nn;
            }
        }
        acc.x = fmaxf(acc.x + bb.x, 0.f); acc.y = fmaxf(acc.y + bb.y, 0.f);
        acc.z = fmaxf(acc.z + bb.z, 0.f); acc.w = fmaxf(acc.w + bb.w, 0.f);
        ((float4*)out)[(size_t)i * HD4 + lane] = acc;
        s0 += acc.x; q0 += acc.x*acc.x; s1 += acc.y; q1 += acc.y*acc.y;
        s2 += acc.z; q2 += acc.z*acc.z; s3 += acc.w; q3 += acc.w*acc.w;
    }
    if (sS) {
        atomicAdd(&ssum[lane*4+0], s0); atomicAdd(&ssq[lane*4+0], q0);
        atomicAdd(&ssum[lane*4+1], s1); atomicAdd(&ssq[lane*4+1], q1);
        atomicAdd(&ssum[lane*4+2], s2); atomicAdd(&ssq[lane*4+2], q2);
        atomicAdd(&ssum[lane*4+3], s3); atomicAdd(&ssq[lane*4+3], q3);
        __syncthreads();
        if (t < HD) { atomicAdd(&sS[t], ssum[t]); atomicAdd(&sQ[t], ssq[t]); }
    }
}

__global__ void __launch_bounds__(256) k_gather2(const __half* __restrict__ linC,
                                                 const __half* __restrict__ linO,
                                                 float* __restrict__ outC,
                                                 float* __restrict__ outO,
                                                 const float* __restrict__ dc,
                                                 const float* __restrict__ dd,
                                                 const float* __restrict__ bc,
                                                 const float* __restrict__ bo, int N,
                                                 float* sSc, float* sQc,
                                                 float* sSo, float* sQo) {
    __shared__ float red[4][HD];
    int t = threadIdx.x;
    for (int i = t; i < 4 * HD; i += blockDim.x) ((float*)red)[i] = 0.f;
    __syncthreads();
    int lane = t & 31;
    int warpId = (blockIdx.x * blockDim.x + t) >> 5;
    int nW = (blockDim.x * gridDim.x) >> 5;
    float4 bbc = ((const float4*)bc)[lane];
    float4 bbo = ((const float4*)bo)[lane];
    float sc[4]={0,0,0,0}, qc[4]={0,0,0,0}, so[4]={0,0,0,0}, qo[4]={0,0,0,0};
    for (int i = warpId; i < N; i += nW) {
        int start = g_rowptr[i], end = g_rowptr[i + 1];
        float dci = dc[i], doi = dd[i];
        float4 aC = ldhalf4(linC, (size_t)i * HD, lane);
        float4 aO = ldhalf4(linO, (size_t)i * HD, lane);
        float slc = dci * dci, slo = doi * doi;
        aC.x *= slc; aC.y *= slc; aC.z *= slc; aC.w *= slc;
        aO.x *= slo; aO.y *= slo; aO.z *= slo; aO.w *= slo;
        for (int j0 = start; j0 < end; j0 += 32) {
            int jj = j0 + lane;
            float wc = 0.f, wo = 0.f; int r = 0;
            if (jj < end) {
                r = g_er[jj];
                int e = g_ee[jj];
                wc = dc[r] * g_att0[e];
                wo = dd[r] * g_att1[e];
            }
            int cnt = min(32, end - j0);
            for (int k = 0; k < cnt; k++) {
                int   rr = __shfl_sync(0xffffffffu, r, k);
                float nc = __shfl_sync(0xffffffffu, wc, k) * dci;
                float no = __shfl_sync(0xffffffffu, wo, k) * doi;
                float4 vC = ldhalf4(linC, (size_t)rr * HD, lane);
                float4 vO = ldhalf4(linO, (size_t)rr * HD, lane);
                aC.x += vC.x * nc; aC.y += vC.y * nc; aC.z += vC.z * nc; aC.w += vC.w * nc;
                aO.x += vO.x * no; aO.y += vO.y * no; aO.z += vO.z * no; aO.w += vO.w * no;
            }
        }
        aC.x = fmaxf(aC.x + bbc.x, 0.f); aC.y = fmaxf(aC.y + bbc.y, 0.f);
        aC.z = fmaxf(aC.z + bbc.z, 0.f); aC.w = fmaxf(aC.w + bbc.w, 0.f);
        aO.x = fmaxf(aO.x + bbo.x, 0.f); aO.y = fmaxf(aO.y + bbo.y, 0.f);
        aO.z = fmaxf(aO.z + bbo.z, 0.f); aO.w = fmaxf(aO.w + bbo.w, 0.f);
        ((float4*)outC)[(size_t)i * HD4 + lane] = aC;
        ((float4*)outO)[(size_t)i * HD4 + lane] = aO;
        sc[0]+=aC.x; qc[0]+=aC.x*aC.x; sc[1]+=aC.y; qc[1]+=aC.y*aC.y;
        sc[2]+=aC.z; qc[2]+=aC.z*aC.z; sc[3]+=aC.w; qc[3]+=aC.w*aC.w;
        so[0]+=aO.x; qo[0]+=aO.x*aO.x; so[1]+=aO.y; qo[1]+=aO.y*aO.y;
        so[2]+=aO.z; qo[2]+=aO.z*aO.z; so[3]+=aO.w; qo[3]+=aO.w*aO.w;
    }
#pragma unroll
    for (int j = 0; j < 4; j++) {
        atomicAdd(&red[0][lane*4+j], sc[j]);
        atomicAdd(&red[1][lane*4+j], qc[j]);
        atomicAdd(&red[2][lane*4+j], so[j]);
        atomicAdd(&red[3][lane*4+j], qo[j]);
    }
    __syncthreads();
    if (t < HD) {
        atomicAdd(&sSc[t], red[0][t]); atomicAdd(&sQc[t], red[1][t]);
        atomicAdd(&sSo[t], red[2][t]); atomicAdd(&sQo[t], red[3][t]);
    }
}

// ---------------- attention --------------------------------------------------------
__global__ void k_att_node(const float* __restrict__ h,
                           const float* __restrict__ Wna, const float* __restrict__ bna,
                           const float* __restrict__ Wea,
                           float* __restrict__ xc, float* __restrict__ xo, int N,
                           float* sSc, float* sQc, float* sSo, float* sQo) {
    __shared__ float Wc[HD * 6];
    __shared__ float red[4][HD];
    int t = threadIdx.x;
    for (int i = t; i < HD * 6; i += blockDim.x) {
        int k = i / 6, j = i % 6;
        float v;
        if (j < 2)      v = Wna[k * 2 + j];
        else if (j < 4) v = Wea[k * 2 + (j - 2)];
        else            v = Wea[(HD + k) * 2 + (j - 4)];
        Wc[i] = v;
    }
    for (int i = t; i < 4 * HD; i += blockDim.x) ((float*)red)[i] = 0.f;
    __syncthreads();
    int warps = (blockDim.x * gridDim.x) >> 5;
    int gw = (blockIdx.x * blockDim.x + t) >> 5;
    int l  = t & 31;
    float b0 = bna[0], b1 = bna[1];
    float sc[4]={0,0,0,0}, qc[4]={0,0,0,0}, so[4]={0,0,0,0}, qo[4]={0,0,0,0};
    for (int i = gw; i < N; i += warps) {
        float4 hv = ((const float4*)h)[(size_t)i * HD4 + l];
        float p[6];
#pragma unroll
        for (int j = 0; j < 6; j++) {
            p[j] = hv.x * Wc[(4*l+0)*6 + j] + hv.y * Wc[(4*l+1)*6 + j]
                 + hv.z * Wc[(4*l+2)*6 + j] + hv.w * Wc[(4*l+3)*6 + j];
        }
#pragma unroll
        for (int off = 16; off; off >>= 1)
#pragma unroll
            for (int j = 0; j < 6; j++)
                p[j] += __shfl_xor_sync(0xffffffffu, p[j], off);
        float l0 = p[0] + b0, l1 = p[1] + b1;
        float m  = fmaxf(l0, l1);
        float e0 = expf(l0 - m), e1 = expf(l1 - m);
        float inv = 1.f / (e0 + e1);
        float a0 = e0 * inv, a1 = e1 * inv;
        float4 vc = make_float4(hv.x*a0, hv.y*a0, hv.z*a0, hv.w*a0);
        float4 vo = make_float4(hv.x*a1, hv.y*a1, hv.z*a1, hv.w*a1);
        ((float4*)xc)[(size_t)i * HD4 + l] = vc;
        ((float4*)xo)[(size_t)i * HD4 + l] = vo;
        sc[0]+=vc.x; qc[0]+=vc.x*vc.x; sc[1]+=vc.y; qc[1]+=vc.y*vc.y;
        sc[2]+=vc.z; qc[2]+=vc.z*vc.z; sc[3]+=vc.w; qc[3]+=vc.w*vc.w;
        so[0]+=vo.x; qo[0]+=vo.x*vo.x; so[1]+=vo.y; qo[1]+=vo.y*vo.y;
        so[2]+=vo.z; qo[2]+=vo.z*vo.z; so[3]+=vo.w; qo[3]+=vo.w*vo.w;
        if (l == 0) g_eanode[i] = make_float4(p[2], p[3], p[4], p[5]);
    }
#pragma unroll
    for (int j = 0; j < 4; j++) {
        atomicAdd(&red[0][l*4+j], sc[j]);
        atomicAdd(&red[1][l*4+j], qc[j]);
        atomicAdd(&red[2][l*4+j], so[j]);
        atomicAdd(&red[3][l*4+j], qo[j]);
    }
    __syncthreads();
    if (t < HD) {
        atomicAdd(&sSc[t], red[0][t]); atomicAdd(&sQc[t], red[1][t]);
        atomicAdd(&sSo[t], red[2][t]); atomicAdd(&sQo[t], red[3][t]);
    }
}

__global__ void k_att_edge(const int* __restrict__ row, const int* __restrict__ col,
                           const float* __restrict__ bea, int E) {
    int e = blockIdx.x * blockDim.x + threadIdx.x;
    if (e >= E) return;
    int r = row[e], c = col[e];
    float4 tr = g_eanode[r], tc = g_eanode[c];
    float l0 = tr.x + tc.z + bea[0];
    float l1 = tr.y + tc.w + bea[1];
    float m  = fmaxf(l0, l1);
    float e0 = expf(l0 - m), e1 = expf(l1 - m);
    float inv = 1.f / (e0 + e1);
    float a0 = e0 * inv, a1 = e1 * inv;
    g_att0[e] = a0; g_att1[e] = a1;
    atomicAdd(&g_degc[r], a0);
    atomicAdd(&g_dego[r], a1);
}

__global__ void k_permadd_stats(const float* __restrict__ xc, const float* __restrict__ xo,
                                const int* __restrict__ perm, float* __restrict__ z, int N,
                                float* __restrict__ sS, float* __restrict__ sQ) {
    __shared__ float ssum[HD], ssq[HD];
    int t = threadIdx.x;
    if (t < HD) { ssum[t] = 0.f; ssq[t] = 0.f; }
    __syncthreads();
    int total  = N * HD4;
    int stride = blockDim.x * gridDim.x;
    int idx    = blockIdx.x * blockDim.x + t;
    int fb     = (idx & 31) * 4;
    float a0=0,a1=0,a2=0,a3=0,q0=0,q1=0,q2=0,q3=0;
    for (; idx < total; idx += stride) {
        int i = idx >> 5, l = idx & 31;
        int p = perm[i];
        float4 a = ((const float4*)xc)[(size_t)p * HD4 + l];
        float4 b = ((const float4*)xo)[idx];
        a.x += b.x; a.y += b.y; a.z += b.z; a.w += b.w;
        ((float4*)z)[idx] = a;
        a0 += a.x; q0 += a.x*a.x; a1 += a.y; q1 += a.y*a.y;
        a2 += a.z; q2 += a.z*a.z; a3 += a.w; q3 += a.w*a.w;
    }
    atomicAdd(&ssum[fb+0], a0); atomicAdd(&ssq[fb+0], q0);
    atomicAdd(&ssum[fb+1], a1); atomicAdd(&ssq[fb+1], q1);
    atomicAdd(&ssum[fb+2], a2); atomicAdd(&ssq[fb+2], q2);
    atomicAdd(&ssum[fb+3], a3); atomicAdd(&ssq[fb+3], q3);
    __syncthreads();
    if (t < HD) { atomicAdd(&sS[t], ssum[t]); atomicAdd(&sQ[t], ssq[t]); }
}

// ---------------- [N,128]x[128,10] + log_softmax, inline fold, batched ----------
__global__ void k_gemm2_lsm(LJobs jobs, int N, float invN) {
    __shared__ float Ws[HD * 10];
    __shared__ float bs[10];
    __shared__ float scaleSh[HD], tshSh[HD];
    const LJob J = jobs.j[blockIdx.y];
    int t = threadIdx.x;
    if (t < HD) {
        float mu  = J.sSin[t] * invN;
        float var = fmaxf(J.sQin[t] * invN - mu * mu, 0.f);
        float rs  = rsqrtf(var + 1e-5f);
        scaleSh[t] = rs;
        tshSh[t]   = 1e-4f / rs - mu;
    }
    __syncthreads();
    for (int i = t; i < HD * 10; i += blockDim.x)
        Ws[i] = scaleSh[i / 10] * J.W[i];
    __syncthreads();
    if (t < 160) {
        int j = t / 16, seg = t % 16;
        float part = 0.f;
#pragma unroll
        for (int k = 0; k < 8; k++) {
            int kk = seg * 8 + k;
            part += tshSh[kk] * Ws[kk * 10 + j];
        }
#pragma unroll
        for (int off = 8; off; off >>= 1)
            part += __shfl_down_sync(0xffffffffu, part, off, 16);
        if (seg == 0) bs[j] = J.b[j] + part;
    }
    __syncthreads();
    int warps = (blockDim.x * gridDim.x) >> 5;
    int gw = (blockIdx.x * blockDim.x + t) >> 5;
    int l  = t & 31;
    for (int i = gw; i < N; i += warps) {
        float4 z = ((const float4*)J.Z)[(size_t)i * HD4 + l];
        float p[10];
#pragma unroll
        for (int j = 0; j < 10; j++) {
            p[j] = z.x * Ws[(4*l+0)*10 + j] + z.y * Ws[(4*l+1)*10 + j]
                 + z.z * Ws[(4*l+2)*10 + j] + z.w * Ws[(4*l+3)*10 + j];
        }
#pragma unroll
        for (int off = 16; off; off >>= 1)
#pragma unroll
            for (int j = 0; j < 10; j++)
                p[j] += __shfl_xor_sync(0xffffffffu, p[j], off);
        float m = -1e30f;
#pragma unroll
        for (int j = 0; j < 10; j++) { p[j] += bs[j]; m = fmaxf(m, p[j]); }
        float s = 0.f;
#pragma unroll
        for (int j = 0; j < 10; j++) s += expf(p[j] - m);
        float lse = m + logf(s);
        if (l < 10) J.out[(size_t)i * 10 + l] = p[l] - lse;
    }
}

// ---------------- host orchestration ------------------------------------------------
extern "C" void kernel_launch(void* const* d_in, const int* in_sizes, int n_in,
                              void* d_out, int out_size) {
    const float* x      = (const float*)d_in[0];
    const int*   ei     = (const int*)  d_in[1];
    const int*   perm   = (const int*)  d_in[2];
    const float* W_feat = (const float*)d_in[3];
    const float* b_feat = (const float*)d_in[4];
    const float* W_convs= (const float*)d_in[5];
    const float* b_convs= (const float*)d_in[6];
    const float* W_ea   = (const float*)d_in[7];
    const float* b_ea   = (const float*)d_in[8];
    const float* W_na   = (const float*)d_in[9];
    const float* b_na   = (const float*)d_in[10];
    const float* W_ctx  = (const float*)d_in[11];
    const float* b_ctx  = (const float*)d_in[12];
    const float* W_obj  = (const float*)d_in[13];
    const float* b_obj  = (const float*)d_in[14];
    const float* W_fc1  = (const float*)d_in[15];
    const float* b_fc1  = (const float*)d_in[16];
    const float* W_fc2  = (const float*)d_in[17];
    const float* b_fc2  = (const float*)d_in[18];

    int N = in_sizes[0] / HD;
    int E = in_sizes[1] / 2;
    const int* row = ei;
    const int* col = ei + E;
    float* out = (float*)d_out;

    float* Bbase = nullptr;
    cudaGetSymbolAddress((void**)&Bbase, g_B);
    float* B0 = Bbase + 0 * (size_t)MAXN * HD;
    float* B1 = Bbase + 1 * (size_t)MAXN * HD;
    float* B2 = Bbase + 2 * (size_t)MAXN * HD;
    float* B3 = Bbase + 3 * (size_t)MAXN * HD;
    float* B4 = Bbase + 4 * (size_t)MAXN * HD;
    float* B5 = Bbase + 5 * (size_t)MAXN * HD;
    __half* H1 = (__half*)B1;   // fp16 views (half the footprint of the fp32 buffer)
    __half* H5 = (__half*)B5;
    float *degup, *degcp, *degop, *ssump, *ssqp;
    int *cntp, *dcntp;
    cudaGetSymbolAddress((void**)&degup, g_degu);
    cudaGetSymbolAddress((void**)&degcp, g_degc);
    cudaGetSymbolAddress((void**)&degop, g_dego);
    cudaGetSymbolAddress((void**)&ssump, g_ssum);
    cudaGetSymbolAddress((void**)&ssqp,  g_ssq);
    cudaGetSymbolAddress((void**)&cntp,  g_cnt);
    cudaGetSymbolAddress((void**)&dcntp, g_dcnt);
    auto S = [&](int i) { return ssump + i * HD; };
    auto Q = [&](int i) { return ssqp  + i * HD; };

    const int gemm_smem = (128 * XS + 128 * WSD) * 4;
    cudaFuncSetAttribute(k_gemm_tc, cudaFuncAttributeMaxDynamicSharedMemorySize, gemm_smem);

    int gbGemm = (N + 127) / 128;
    int gbN    = (N + 255) / 256;
    int gbE    = (E + 255) / 256;
    int nb     = (N + 1023) / 1024;
    float invN = 1.f / (float)N;

    auto gemm1 = [&](const float* X, float* Y, const float* W, const float* b,
                     int sin, int sout, int relu, int outHalf) {
        GJobs js{};
        js.j[0] = {X, Y, W, b, S(sin), Q(sin),
                   sout >= 0 ? S(sout) : nullptr, sout >= 0 ? Q(sout) : nullptr};
        k_gemm_tc<<<dim3(gbGemm, 1), 512, gemm_smem>>>(js, N, relu, outHalf, invN);
    };

    k_zero_slots<<<(NSLOT * HD + 255) / 256, 256>>>();

    // CSR + degree build
    cudaMemsetAsync(cntp, 0, (size_t)N * sizeof(int));
    cudaMemsetAsync(dcntp, 0, (size_t)N * sizeof(int));
    k_hist<<<gbE, 256>>>(row, col, E);
    k_scan1<<<nb, 1024>>>(N);
    k_scan2<<<1, 64>>>(nb);
    k_scan3<<<nb, 1024>>>(N);
    k_fillcsr<<<gbE, 256>>>(row, col, E);
    k_dinv<<<gbN, 256>>>(N);

    // stage 0
    k_stats<<<512, 256>>>(x, N, S(0), Q(0));
    gemm1(x, B2, W_feat, b_feat, 0, 1, 1, 0);

    // conv1: B2 -> B0 (lin fp16 in H1)
    gemm1(B2, (float*)H1, W_convs + 0 * HD * HD, nullptr, 1, -1, 0, 1);
    k_gather<<<1024, 256>>>(H1, B0, degup, b_convs + 0 * HD, N, S(2), Q(2));
    // conv2: B0 -> B2
    gemm1(B0, (float*)H1, W_convs + 1 * HD * HD, nullptr, 2, -1, 0, 1);
    k_gather<<<1024, 256>>>(H1, B2, degup, b_convs + 1 * HD, N, S(3), Q(3));
    // conv3: B2 -> B0
    gemm1(B2, (float*)H1, W_convs + 2 * HD * HD, nullptr, 3, -1, 0, 1);
    k_gather<<<1024, 256>>>(H1, B0, degup, b_convs + 2 * HD, N, nullptr, nullptr);

    // attention: h=B0 -> xc=B2 (s4), xo=B3 (s5)
    k_att_node<<<256, 256>>>(B0, W_na, b_na, W_ea, B2, B3, N, S(4), Q(4), S(5), Q(5));
    k_att_edge<<<gbE, 256>>>(row, col, b_ea, E);
    k_rsqrt2<<<gbN, 256>>>(degcp, degop, N);

    // batched ctx/obj linear (fp16 out): {B2->H1}, {B3->H5}
    {
        GJobs js{};
        js.j[0] = {B2, (float*)H1, W_ctx, nullptr, S(4), Q(4), nullptr, nullptr};
        js.j[1] = {B3, (float*)H5, W_obj, nullptr, S(5), Q(5), nullptr, nullptr};
        k_gemm_tc<<<dim3(gbGemm, 2), 512, gemm_smem>>>(js, N, 0, 1, invN);
    }
    // merged weighted gather: xc2=B4 (s6), xo2=B3 (s7)
    k_gather2<<<1024, 256>>>(H1, H5, B4, B3, degcp, degop, b_ctx, b_obj, N,
                             S(6), Q(6), S(7), Q(7));

    // permadd: z = B4[perm] + B3 -> B1 (s11)
    k_permadd_stats<<<256, 256>>>(B4, B3, perm, B1, N, S(11), Q(11));

    // batched readout fc1: {B4->B0}, {B3->B5}, {B1->B2}, relu, stats 8/9/10
    {
        GJobs js{};
        js.j[0] = {B4, B0, W_fc1 + 0 * HD * HD, b_fc1 + 0 * HD, S(6),  Q(6),  S(8),  Q(8)};
        js.j[1] = {B3, B5, W_fc1 + 1 * HD * HD, b_fc1 + 1 * HD, S(7),  Q(7),  S(9),  Q(9)};
        js.j[2] = {B1, B2, W_fc1 + 2 * HD * HD, b_fc1 + 2 * HD, S(11), Q(11), S(10), Q(10)};
        k_gemm_tc<<<dim3(gbGemm, 3), 512, gemm_smem>>>(js, N, 1, 0, invN);
    }
    // batched lsm
    {
        LJobs js{};
        js.j[0] = {B0, out,                      W_fc2 + 0 * HD * 10, b_fc2 + 0 * 10, S(8),  Q(8)};
        js.j[1] = {B5, out + (size_t)N * 10,     W_fc2 + 1 * HD * 10, b_fc2 + 1 * 10, S(9),  Q(9)};
        js.j[2] = {B2, out + (size_t)2 * N * 10, W_fc2 + 2 * HD * 10, b_fc2 + 2 * 10, S(10), Q(10)};
        k_gemm2_lsm<<<dim3(512, 3), 256>>>(js, N, invN);
    }
}

// round 6
// speedup vs baseline: 3.7132x; 1.1255x over previous
#include <cuda_runtime.h>
#include <cuda_fp16.h>

#define HD   128
#define HD4  32
#define MAXN 50000
#define MAXE 800000
#define AS   136   // smem stride in halves (8-half pad -> conflict-free ldmatrix)
#define BS   136
#define NSLOT 12

// ---------------- scratch ------------------------------------------------------
static __device__ float  g_B[6][(size_t)MAXN * HD];
static __device__ float4 g_eanode[MAXN];
static __device__ float  g_att0[MAXE];
static __device__ float  g_att1[MAXE];
static __device__ float  g_degu[MAXN];
static __device__ float  g_degc[MAXN];
static __device__ float  g_dego[MAXN];
static __device__ float  g_ssum[NSLOT * HD];
static __device__ float  g_ssq [NSLOT * HD];
// CSR
static __device__ int    g_cnt[MAXN];
static __device__ int    g_dcnt[MAXN];
static __device__ int    g_rowptr[MAXN + 1];
static __device__ int    g_cursor[MAXN];
static __device__ int    g_er[MAXE];
static __device__ int    g_ee[MAXE];
static __device__ int    g_bsum[64];
static __device__ int    g_boff[64];
static __device__ int    g_total;

struct GJob {
    const float* X; float* Y; const float* W; const float* b;
    const float* sSin; const float* sQin; float* sSout; float* sQout;
};
struct GJobs { GJob j[3]; };
struct LJob {
    const float* Z; float* out; const float* W; const float* b;
    const float* sSin; const float* sQin;
};
struct LJobs { LJob j[3]; };

__device__ __forceinline__ unsigned s2u(const void* p) {
    return (unsigned)__cvta_generic_to_shared(p);
}

__device__ __forceinline__ void ldsm_x4(unsigned* a, unsigned addr) {
    asm volatile("ldmatrix.sync.aligned.m8n8.x4.shared.b16 {%0,%1,%2,%3}, [%4];"
                 : "=r"(a[0]), "=r"(a[1]), "=r"(a[2]), "=r"(a[3]) : "r"(addr));
}
__device__ __forceinline__ void ldsm_x2t(unsigned* b, unsigned addr) {
    asm volatile("ldmatrix.sync.aligned.m8n8.x2.trans.shared.b16 {%0,%1}, [%2];"
                 : "=r"(b[0]), "=r"(b[1]) : "r"(addr));
}
__device__ __forceinline__ void mma_f16(float* c, const unsigned* a, const unsigned* b) {
    asm volatile(
        "mma.sync.aligned.m16n8k16.row.col.f32.f16.f16.f32 "
        "{%0,%1,%2,%3}, {%4,%5,%6,%7}, {%8,%9}, {%0,%1,%2,%3};"
        : "+f"(c[0]), "+f"(c[1]), "+f"(c[2]), "+f"(c[3])
        : "r"(a[0]), "r"(a[1]), "r"(a[2]), "r"(a[3]), "r"(b[0]), "r"(b[1]));
}

// ---------------- misc small kernels -------------------------------------------
__global__ void k_zero_slots() {
    int i = blockIdx.x * blockDim.x + threadIdx.x;
    if (i < NSLOT * HD) { g_ssum[i] = 0.f; g_ssq[i] = 0.f; }
}

__global__ void k_stats(const float* __restrict__ X, int N,
                        float* __restrict__ sS, float* __restrict__ sQ) {
    __shared__ float ss[HD], sq[HD];
    int t = threadIdx.x;
    if (t < HD) { ss[t] = 0.f; sq[t] = 0.f; }
    __syncthreads();
    int total  = N * HD4;
    int stride = blockDim.x * gridDim.x;
    int idx    = blockIdx.x * blockDim.x + t;
    int fb     = (idx & 31) * 4;
    float a0=0,a1=0,a2=0,a3=0,q0=0,q1=0,q2=0,q3=0;
    for (; idx < total; idx += stride) {
        float4 v = ((const float4*)X)[idx];
        a0 += v.x; q0 += v.x * v.x;
        a1 += v.y; q1 += v.y * v.y;
        a2 += v.z; q2 += v.z * v.z;
        a3 += v.w; q3 += v.w * v.w;
    }
    atomicAdd(&ss[fb+0], a0); atomicAdd(&sq[fb+0], q0);
    atomicAdd(&ss[fb+1], a1); atomicAdd(&sq[fb+1], q1);
    atomicAdd(&ss[fb+2], a2); atomicAdd(&sq[fb+2], q2);
    atomicAdd(&ss[fb+3], a3); atomicAdd(&sq[fb+3], q3);
    __syncthreads();
    if (t < HD) { atomicAdd(&sS[t], ss[t]); atomicAdd(&sQ[t], sq[t]); }
}

// ---------------- fp16 tensor-core GEMM, inline BN fold, batched ----------------
__global__ void __launch_bounds__(512) k_gemm_tc(GJobs jobs, int N, int doRelu,
                                                 int outHalf, float invN) {
    extern __shared__ __half sh[];
    __half* Ah = sh;               // 128 x AS
    __half* Bh = sh + 128 * AS;    // 128 x BS
    __shared__ float ssum[HD], ssq[HD], scaleSh[HD], tshSh[HD], biasSh[HD];
    __shared__ float bpart[4][HD];
    const GJob J = jobs.j[blockIdx.y];
    int t = threadIdx.x;
    if (t < HD) {
        ssum[t] = 0.f; ssq[t] = 0.f;
        float mu  = J.sSin[t] * invN;
        float var = fmaxf(J.sQin[t] * invN - mu * mu, 0.f);
        float rs  = rsqrtf(var + 1e-5f);
        scaleSh[t] = rs;
        tshSh[t]   = 1e-4f / rs - mu;
        biasSh[t]  = J.b ? J.b[t] : 0.f;
    }
    __syncthreads();
    int base = blockIdx.x * 128;
#pragma unroll
    for (int i = t; i < 4096; i += 512) {
        int r = i >> 5, c = i & 31, gr = base + r;
        float4 v = make_float4(0.f, 0.f, 0.f, 0.f);
        if (gr < N) v = ((const float4*)J.X)[(size_t)gr * 32 + c];
        __half2* dst = (__half2*)&Ah[r * AS + c * 4];
        dst[0] = __floats2half2_rn(v.x, v.y);
        dst[1] = __floats2half2_rn(v.z, v.w);
    }
#pragma unroll
    for (int i = t; i < 4096; i += 512) {
        int r = i >> 5, c = i & 31;
        float4 v = ((const float4*)J.W)[i];
        float s = scaleSh[r];
        __half2* dst = (__half2*)&Bh[r * BS + c * 4];
        dst[0] = __floats2half2_rn(v.x * s, v.y * s);
        dst[1] = __floats2half2_rn(v.z * s, v.w * s);
    }
    __syncthreads();

    // bias += shift . W (fp16-rounded scaled W)
    {
        int j = t & 127, q = t >> 7;
        float part = 0.f;
        int k0 = q * 32;
#pragma unroll
        for (int k = 0; k < 32; k++)
            part += tshSh[k0 + k] * __half2float(Bh[(k0 + k) * BS + j]);
        bpart[q][j] = part;
    }
    __syncthreads();
    if (t < HD) biasSh[t] += bpart[0][t] + bpart[1][t] + bpart[2][t] + bpart[3][t];
    __syncthreads();

    int lane = t & 31, g = lane >> 2, tg = lane & 3, w = t >> 5;
    int rwb = (w & 3) * 32;
    int cwb = (w >> 2) * 32;

    // ldmatrix address precompute
    int m8 = lane >> 3, lr = lane & 7;
    int arowOff = (m8 & 1) * 8 + lr;        // within 16-row tile
    int acolOff = (m8 >> 1) * 8;            // k half
    unsigned aBase = s2u(Ah);
    unsigned bBase = s2u(Bh);
    int bk = lane & 15;                      // lanes 0-15 used by x2

    float acc[2][4][4];
#pragma unroll
    for (int m = 0; m < 2; m++)
#pragma unroll
        for (int nt = 0; nt < 4; nt++)
#pragma unroll
            for (int j = 0; j < 4; j++) acc[m][nt][j] = 0.f;

    unsigned aA[8], bA[8], aB[8], bB[8];

#define LDFRAG(K0, AA, BB)                                                      \
    {                                                                           \
        _Pragma("unroll")                                                       \
        for (int m = 0; m < 2; m++) {                                           \
            int arow = rwb + m * 16 + arowOff;                                  \
            ldsm_x4(AA + m * 4, aBase + (arow * AS + (K0) + acolOff) * 2);      \
        }                                                                       \
        _Pragma("unroll")                                                       \
        for (int nt = 0; nt < 4; nt++) {                                        \
            ldsm_x2t(BB + nt * 2, bBase + (((K0) + bk) * BS + cwb + nt * 8) * 2);\
        }                                                                       \
    }

    LDFRAG(0, aA, bA);
#pragma unroll
    for (int ks = 0; ks < 8; ks += 2) {
        if (ks + 1 < 8) LDFRAG((ks + 1) * 16, aB, bB);
#pragma unroll
        for (int m = 0; m < 2; m++)
#pragma unroll
            for (int nt = 0; nt < 4; nt++)
                mma_f16(acc[m][nt], aA + m * 4, bA + nt * 2);
        if (ks + 2 < 8) LDFRAG((ks + 2) * 16, aA, bA);
#pragma unroll
        for (int m = 0; m < 2; m++)
#pragma unroll
            for (int nt = 0; nt < 4; nt++)
                mma_f16(acc[m][nt], aB + m * 4, bB + nt * 2);
    }
#undef LDFRAG

    float ls[4][2], lq[4][2];
#pragma unroll
    for (int nt = 0; nt < 4; nt++) { ls[nt][0]=0.f; ls[nt][1]=0.f; lq[nt][0]=0.f; lq[nt][1]=0.f; }

#pragma unroll
    for (int nt = 0; nt < 4; nt++) {
        int col = cwb + nt * 8 + 2 * tg;
        float bx = biasSh[col], by = biasSh[col + 1];
#pragma unroll
        for (int m = 0; m < 2; m++) {
            int r0 = base + rwb + m * 16 + g;
            int r1 = r0 + 8;
            float y00 = acc[m][nt][0] + bx, y01 = acc[m][nt][1] + by;
            float y10 = acc[m][nt][2] + bx, y11 = acc[m][nt][3] + by;
            if (doRelu) {
                y00 = fmaxf(y00, 0.f); y01 = fmaxf(y01, 0.f);
                y10 = fmaxf(y10, 0.f); y11 = fmaxf(y11, 0.f);
            }
            if (r0 < N) {
                if (outHalf)
                    ((__half2*)J.Y)[(size_t)r0 * 64 + (col >> 1)] = __floats2half2_rn(y00, y01);
                else
                    ((float2*)J.Y)[(size_t)r0 * 64 + (col >> 1)] = make_float2(y00, y01);
                ls[nt][0] += y00; lq[nt][0] += y00 * y00;
                ls[nt][1] += y01; lq[nt][1] += y01 * y01;
            }
            if (r1 < N) {
                if (outHalf)
                    ((__half2*)J.Y)[(size_t)r1 * 64 + (col >> 1)] = __floats2half2_rn(y10, y11);
                else
                    ((float2*)J.Y)[(size_t)r1 * 64 + (col >> 1)] = make_float2(y10, y11);
                ls[nt][0] += y10; lq[nt][0] += y10 * y10;
                ls[nt][1] += y11; lq[nt][1] += y11 * y11;
            }
        }
    }

    if (J.sSout) {
#pragma unroll
        for (int off = 4; off <= 16; off <<= 1)
#pragma unroll
            for (int nt = 0; nt < 4; nt++)
#pragma unroll
                for (int j = 0; j < 2; j++) {
                    ls[nt][j] += __shfl_xor_sync(0xffffffffu, ls[nt][j], off);
                    lq[nt][j] += __shfl_xor_sync(0xffffffffu, lq[nt][j], off);
                }
        if (g == 0) {
#pragma unroll
            for (int nt = 0; nt < 4; nt++)
#pragma unroll
                for (int j = 0; j < 2; j++) {
                    int col = cwb + nt * 8 + 2 * tg + j;
                    atomicAdd(&ssum[col], ls[nt][j]);
                    atomicAdd(&ssq[col],  lq[nt][j]);
                }
        }
        __syncthreads();
        if (t < HD) { atomicAdd(&J.sSout[t], ssum[t]); atomicAdd(&J.sQout[t], ssq[t]); }
    }
}

// ---------------- CSR build ------------------------------------------------------
__global__ void k_hist(const int* __restrict__ row, const int* __restrict__ col, int E) {
    int e = blockIdx.x * blockDim.x + threadIdx.x;
    if (e < E) {
        atomicAdd(&g_cnt[col[e]], 1);
        atomicAdd(&g_dcnt[row[e]], 1);
    }
}

__global__ void __launch_bounds__(1024) k_scan1(int N) {
    __shared__ int wsum[32];
    int t = threadIdx.x;
    int idx = blockIdx.x * 1024 + t;
    int v = (idx < N) ? g_cnt[idx] : 0;
    int x = v;
#pragma unroll
    for (int off = 1; off < 32; off <<= 1) {
        int y = __shfl_up_sync(0xffffffffu, x, off);
        if ((t & 31) >= off) x += y;
    }
    if ((t & 31) == 31) wsum[t >> 5] = x;
    __syncthreads();
    if (t < 32) {
        int y = wsum[t];
#pragma unroll
        for (int off = 1; off < 32; off <<= 1) {
            int z = __shfl_up_sync(0xffffffffu, y, off);
            if (t >= off) y += z;
        }
        wsum[t] = y;
    }
    __syncthreads();
    int winc = (t >= 32) ? wsum[(t >> 5) - 1] : 0;
    int incl = x + winc;
    if (idx < N) g_rowptr[idx] = incl - v;
    if (t == 1023) g_bsum[blockIdx.x] = incl;
}

__global__ void k_scan2(int nb) {
    __shared__ int s[64];
    int t = threadIdx.x;
    int v = (t < nb) ? g_bsum[t] : 0;
    s[t] = v;
    __syncthreads();
    for (int off = 1; off < 64; off <<= 1) {
        int a = (t >= off) ? s[t - off] : 0;
        __syncthreads();
        s[t] += a;
        __syncthreads();
    }
    g_boff[t] = s[t] - v;
    if (t == 63) g_total = s[63];
}

// scan finalize + all degree init (dinv for unweighted, 1.0 for weighted sums)
__global__ void k_scan3(int N) {
    int idx = blockIdx.x * blockDim.x + threadIdx.x;
    if (idx < N) {
        int r = g_rowptr[idx] + g_boff[idx >> 10];
        g_rowptr[idx] = r;
        g_cursor[idx] = r;
        g_degu[idx] = rsqrtf((float)g_dcnt[idx] + 1.f);
        g_degc[idx] = 1.f;
        g_dego[idx] = 1.f;
    }
    if (idx == 0) g_rowptr[N] = g_total;
}

__global__ void k_fillcsr(const int* __restrict__ row, const int* __restrict__ col, int E) {
    int e = blockIdx.x * blockDim.x + threadIdx.x;
    if (e >= E) return;
    int c = col[e];
    int p = atomicAdd(&g_cursor[c], 1);
    g_er[p] = row[e];
    g_ee[p] = e;
}

// ---------------- CSR gathers (fp16 lin input, unrolled edge loop) --------------
__device__ __forceinline__ float4 ldhalf4(const __half* lin, size_t rowBase, int lane) {
    uint2 u = __ldg((const uint2*)(lin + rowBase) + lane);
    __half2 h0 = *(__half2*)&u.x, h1 = *(__half2*)&u.y;
    float2 f0 = __half22float2(h0), f1 = __half22float2(h1);
    return make_float4(f0.x, f0.y, f1.x, f1.y);
}

__global__ void __launch_bounds__(256) k_gather(const __half* __restrict__ lin,
                                                float* __restrict__ out,
                                                const float* __restrict__ dinv,
                                                const float* __restrict__ b, int N,
                                                float* __restrict__ sS,
                                                float* __restrict__ sQ) {
    __shared__ float ssum[HD], ssq[HD];
    int t = threadIdx.x;
    if (t < HD) { ssum[t] = 0.f; ssq[t] = 0.f; }
    __syncthreads();
    int lane = t & 31;
    int warpId = (blockIdx.x * blockDim.x + t) >> 5;
    int nW = (blockDim.x * gridDim.x) >> 5;
    float4 bb = ((const float4*)b)[lane];
    float s0=0,s1=0,s2=0,s3=0,q0=0,q1=0,q2=0,q3=0;
    for (int i = warpId; i < N; i += nW) {
        int start = g_rowptr[i], end = g_rowptr[i + 1];
        float di = dinv[i];
        float4 acc = ldhalf4(lin, (size_t)i * HD, lane);
        float sl = di * di;
        acc.x *= sl; acc.y *= sl; acc.z *= sl; acc.w *= sl;
        int j0 = start;
        for (; j0 + 32 <= end; j0 += 32) {
            int r = g_er[j0 + lane];
            float dr = dinv[r];
#pragma unroll 8
            for (int k = 0; k < 32; k++) {
                int   rr = __shfl_sync(0xffffffffu, r, k);
                float nn = __shfl_sync(0xffffffffu, dr, k) * di;
                float4 v = ldhalf4(lin, (size_t)rr * HD, lane);
                acc.x += v.x * nn; acc.y += v.y * nn;
                acc.z += v.z * nn; acc.w += v.w * nn;
            }
        }
        if (j0 < end) {
            int jj = j0 + lane;
            int r = 0; float dr = 0.f;
            if (jj < end) { r = g_er[jj]; dr = dinv[r]; }
            int cnt = end - j0;
            for (int k = 0; k < cnt; k++) {
                int   rr = __shfl_sync(0xffffffffu, r, k);
                float nn = __shfl_sync(0xffffffffu, dr, k) * di;
                float4 v = ldhalf4(lin, (size_t)rr * HD, lane);
                acc.x += v.x * nn; acc.y += v.y * nn;
                acc.z += v.z * nn; acc.w += v.w * nn;
            }
        }
        acc.x = fmaxf(acc.x + bb.x, 0.f); acc.y = fmaxf(acc.y + bb.y, 0.f);
        acc.z = fmaxf(acc.z + bb.z, 0.f); acc.w = fmaxf(acc.w + bb.w, 0.f);
        ((float4*)out)[(size_t)i * HD4 + lane] = acc;
        s0 += acc.x; q0 += acc.x*acc.x; s1 += acc.y; q1 += acc.y*acc.y;
        s2 += acc.z; q2 += acc.z*acc.z; s3 += acc.w; q3 += acc.w*acc.w;
    }
    if (sS) {
        atomicAdd(&ssum[lane*4+0], s0); atomicAdd(&ssq[lane*4+0], q0);
        atomicAdd(&ssum[lane*4+1], s1); atomicAdd(&ssq[lane*4+1], q1);
        atomicAdd(&ssum[lane*4+2], s2); atomicAdd(&ssq[lane*4+2], q2);
        atomicAdd(&ssum[lane*4+3], s3); atomicAdd(&ssq[lane*4+3], q3);
        __syncthreads();
        if (t < HD) { atomicAdd(&sS[t], ssum[t]); atomicAdd(&sQ[t], ssq[t]); }
    }
}

__global__ void __launch_bounds__(256) k_gather2(const __half* __restrict__ linC,
                                                 const __half* __restrict__ linO,
                                                 float* __restrict__ outC,
                                                 float* __restrict__ outO,
                                                 const float* __restrict__ dc,
                                                 const float* __restrict__ dd,
                                                 const float* __restrict__ bc,
                                                 const float* __restrict__ bo, int N,
                                                 float* sSc, float* sQc,
                                                 float* sSo, float* sQo) {
    __shared__ float red[4][HD];
    int t = threadIdx.x;
    for (int i = t; i < 4 * HD; i += blockDim.x) ((float*)red)[i] = 0.f;
    __syncthreads();
    int lane = t & 31;
    int warpId = (blockIdx.x * blockDim.x + t) >> 5;
    int nW = (blockDim.x * gridDim.x) >> 5;
    float4 bbc = ((const float4*)bc)[lane];
    float4 bbo = ((const float4*)bo)[lane];
    float sc[4]={0,0,0,0}, qc[4]={0,0,0,0}, so[4]={0,0,0,0}, qo[4]={0,0,0,0};
    for (int i = warpId; i < N; i += nW) {
        int start = g_rowptr[i], end = g_rowptr[i + 1];
        float dci = rsqrtf(dc[i]), doi = rsqrtf(dd[i]);
        float4 aC = ldhalf4(linC, (size_t)i * HD, lane);
        float4 aO = ldhalf4(linO, (size_t)i * HD, lane);
        float slc = dci * dci, slo = doi * doi;
        aC.x *= slc; aC.y *= slc; aC.z *= slc; aC.w *= slc;
        aO.x *= slo; aO.y *= slo; aO.z *= slo; aO.w *= slo;
        int j0 = start;
        for (; j0 + 32 <= end; j0 += 32) {
            int jj = j0 + lane;
            int r = g_er[jj];
            int e = g_ee[jj];
            float wc = rsqrtf(dc[r]) * g_att0[e];
            float wo = rsqrtf(dd[r]) * g_att1[e];
#pragma unroll 4
            for (int k = 0; k < 32; k++) {
                int   rr = __shfl_sync(0xffffffffu, r, k);
                float nc = __shfl_sync(0xffffffffu, wc, k) * dci;
                float no = __shfl_sync(0xffffffffu, wo, k) * doi;
                float4 vC = ldhalf4(linC, (size_t)rr * HD, lane);
                float4 vO = ldhalf4(linO, (size_t)rr * HD, lane);
                aC.x += vC.x * nc; aC.y += vC.y * nc; aC.z += vC.z * nc; aC.w += vC.w * nc;
                aO.x += vO.x * no; aO.y += vO.y * no; aO.z += vO.z * no; aO.w += vO.w * no;
            }
        }
        if (j0 < end) {
            int jj = j0 + lane;
            float wc = 0.f, wo = 0.f; int r = 0;
            if (jj < end) {
                r = g_er[jj];
                int e = g_ee[jj];
                wc = rsqrtf(dc[r]) * g_att0[e];
                wo = rsqrtf(dd[r]) * g_att1[e];
            }
            int cnt = end - j0;
            for (int k = 0; k < cnt; k++) {
                int   rr = __shfl_sync(0xffffffffu, r, k);
                float nc = __shfl_sync(0xffffffffu, wc, k) * dci;
                float no = __shfl_sync(0xffffffffu, wo, k) * doi;
                float4 vC = ldhalf4(linC, (size_t)rr * HD, lane);
                float4 vO = ldhalf4(linO, (size_t)rr * HD, lane);
                aC.x += vC.x * nc; aC.y += vC.y * nc; aC.z += vC.z * nc; aC.w += vC.w * nc;
                aO.x += vO.x * no; aO.y += vO.y * no; aO.z += vO.z * no; aO.w += vO.w * no;
            }
        }
        aC.x = fmaxf(aC.x + bbc.x, 0.f); aC.y = fmaxf(aC.y + bbc.y, 0.f);
        aC.z = fmaxf(aC.z + bbc.z, 0.f); aC.w = fmaxf(aC.w + bbc.w, 0.f);
        aO.x = fmaxf(aO.x + bbo.x, 0.f); aO.y = fmaxf(aO.y + bbo.y, 0.f);
        aO.z = fmaxf(aO.z + bbo.z, 0.f); aO.w = fmaxf(aO.w + bbo.w, 0.f);
        ((float4*)outC)[(size_t)i * HD4 + lane] = aC;
        ((float4*)outO)[(size_t)i * HD4 + lane] = aO;
        sc[0]+=aC.x; qc[0]+=aC.x*aC.x; sc[1]+=aC.y; qc[1]+=aC.y*aC.y;
        sc[2]+=aC.z; qc[2]+=aC.z*aC.z; sc[3]+=aC.w; qc[3]+=aC.w*aC.w;
        so[0]+=aO.x; qo[0]+=aO.x*aO.x; so[1]+=aO.y; qo[1]+=aO.y*aO.y;
        so[2]+=aO.z; qo[2]+=aO.z*aO.z; so[3]+=aO.w; qo[3]+=aO.w*aO.w;
    }
#pragma unroll
    for (int j = 0; j < 4; j++) {
        atomicAdd(&red[0][lane*4+j], sc[j]);
        atomicAdd(&red[1][lane*4+j], qc[j]);
        atomicAdd(&red[2][lane*4+j], so[j]);
        atomicAdd(&red[3][lane*4+j], qo[j]);
    }
    __syncthreads();
    if (t < HD) {
        atomicAdd(&sSc[t], red[0][t]); atomicAdd(&sQc[t], red[1][t]);
        atomicAdd(&sSo[t], red[2][t]); atomicAdd(&sQo[t], red[3][t]);
    }
}

// ---------------- attention --------------------------------------------------------
__global__ void k_att_node(const float* __restrict__ h,
                           const float* __restrict__ Wna, const float* __restrict__ bna,
                           const float* __restrict__ Wea,
                           float* __restrict__ xc, float* __restrict__ xo, int N,
                           float* sSc, float* sQc, float* sSo, float* sQo) {
    __shared__ float Wc[HD * 6];
    __shared__ float red[4][HD];
    int t = threadIdx.x;
    for (int i = t; i < HD * 6; i += blockDim.x) {
        int k = i / 6, j = i % 6;
        float v;
        if (j < 2)      v = Wna[k * 2 + j];
        else if (j < 4) v = Wea[k * 2 + (j - 2)];
        else            v = Wea[(HD + k) * 2 + (j - 4)];
        Wc[i] = v;
    }
    for (int i = t; i < 4 * HD; i += blockDim.x) ((float*)red)[i] = 0.f;
    __syncthreads();
    int warps = (blockDim.x * gridDim.x) >> 5;
    int gw = (blockIdx.x * blockDim.x + t) >> 5;
    int l  = t & 31;
    float b0 = bna[0], b1 = bna[1];
    float sc[4]={0,0,0,0}, qc[4]={0,0,0,0}, so[4]={0,0,0,0}, qo[4]={0,0,0,0};
    for (int i = gw; i < N; i += warps) {
        float4 hv = ((const float4*)h)[(size_t)i * HD4 + l];
        float p[6];
#pragma unroll
        for (int j = 0; j < 6; j++) {
            p[j] = hv.x * Wc[(4*l+0)*6 + j] + hv.y * Wc[(4*l+1)*6 + j]
                 + hv.z * Wc[(4*l+2)*6 + j] + hv.w * Wc[(4*l+3)*6 + j];
        }
#pragma unroll
        for (int off = 16; off; off >>= 1)
#pragma unroll
            for (int j = 0; j < 6; j++)
                p[j] += __shfl_xor_sync(0xffffffffu, p[j], off);
        float l0 = p[0] + b0, l1 = p[1] + b1;
        float m  = fmaxf(l0, l1);
        float e0 = expf(l0 - m), e1 = expf(l1 - m);
        float inv = 1.f / (e0 + e1);
        float a0 = e0 * inv, a1 = e1 * inv;
        float4 vc = make_float4(hv.x*a0, hv.y*a0, hv.z*a0, hv.w*a0);
        float4 vo = make_float4(hv.x*a1, hv.y*a1, hv.z*a1, hv.w*a1);
        ((float4*)xc)[(size_t)i * HD4 + l] = vc;
        ((float4*)xo)[(size_t)i * HD4 + l] = vo;
        sc[0]+=vc.x; qc[0]+=vc.x*vc.x; sc[1]+=vc.y; qc[1]+=vc.y*vc.y;
        sc[2]+=vc.z; qc[2]+=vc.z*vc.z; sc[3]+=vc.w; qc[3]+=vc.w*vc.w;
        so[0]+=vo.x; qo[0]+=vo.x*vo.x; so[1]+=vo.y; qo[1]+=vo.y*vo.y;
        so[2]+=vo.z; qo[2]+=vo.z*vo.z; so[3]+=vo.w; qo[3]+=vo.w*vo.w;
        if (l == 0) g_eanode[i] = make_float4(p[2], p[3], p[4], p[5]);
    }
#pragma unroll
    for (int j = 0; j < 4; j++) {
        atomicAdd(&red[0][l*4+j], sc[j]);
        atomicAdd(&red[1][l*4+j], qc[j]);
        atomicAdd(&red[2][l*4+j], so[j]);
        atomicAdd(&red[3][l*4+j], qo[j]);
    }
    __syncthreads();
    if (t < HD) {
        atomicAdd(&sSc[t], red[0][t]); atomicAdd(&sQc[t], red[1][t]);
        atomicAdd(&sSo[t], red[2][t]); atomicAdd(&sQo[t], red[3][t]);
    }
}

__global__ void k_att_edge(const int* __restrict__ row, const int* __restrict__ col,
                           const float* __restrict__ bea, int E) {
    int e = blockIdx.x * blockDim.x + threadIdx.x;
    if (e >= E) return;
    int r = row[e], c = col[e];
    float4 tr = g_eanode[r], tc = g_eanode[c];
    float l0 = tr.x + tc.z + bea[0];
    float l1 = tr.y + tc.w + bea[1];
    float m  = fmaxf(l0, l1);
    float e0 = expf(l0 - m), e1 = expf(l1 - m);
    float inv = 1.f / (e0 + e1);
    float a0 = e0 * inv, a1 = e1 * inv;
    g_att0[e] = a0; g_att1[e] = a1;
    atomicAdd(&g_degc[r], a0);
    atomicAdd(&g_dego[r], a1);
}

__global__ void k_permadd_stats(const float* __restrict__ xc, const float* __restrict__ xo,
                                const int* __restrict__ perm, float* __restrict__ z, int N,
                                float* __restrict__ sS, float* __restrict__ sQ) {
    __shared__ float ssum[HD], ssq[HD];
    int t = threadIdx.x;
    if (t < HD) { ssum[t] = 0.f; ssq[t] = 0.f; }
    __syncthreads();
    int total  = N * HD4;
    int stride = blockDim.x * gridDim.x;
    int idx    = blockIdx.x * blockDim.x + t;
    int fb     = (idx & 31) * 4;
    float a0=0,a1=0,a2=0,a3=0,q0=0,q1=0,q2=0,q3=0;
    for (; idx < total; idx += stride) {
        int i = idx >> 5, l = idx & 31;
        int p = perm[i];
        float4 a = ((const float4*)xc)[(size_t)p * HD4 + l];
        float4 b = ((const float4*)xo)[idx];
        a.x += b.x; a.y += b.y; a.z += b.z; a.w += b.w;
        ((float4*)z)[idx] = a;
        a0 += a.x; q0 += a.x*a.x; a1 += a.y; q1 += a.y*a.y;
        a2 += a.z; q2 += a.z*a.z; a3 += a.w; q3 += a.w*a.w;
    }
    atomicAdd(&ssum[fb+0], a0); atomicAdd(&ssq[fb+0], q0);
    atomicAdd(&ssum[fb+1], a1); atomicAdd(&ssq[fb+1], q1);
    atomicAdd(&ssum[fb+2], a2); atomicAdd(&ssq[fb+2], q2);
    atomicAdd(&ssum[fb+3], a3); atomicAdd(&ssq[fb+3], q3);
    __syncthreads();
    if (t < HD) { atomicAdd(&sS[t], ssum[t]); atomicAdd(&sQ[t], ssq[t]); }
}

// ---------------- [N,128]x[128,10] + log_softmax, inline fold, batched ----------
__global__ void k_gemm2_lsm(LJobs jobs, int N, float invN) {
    __shared__ float Ws[HD * 10];
    __shared__ float bs[10];
    __shared__ float scaleSh[HD], tshSh[HD];
    const LJob J = jobs.j[blockIdx.y];
    int t = threadIdx.x;
    if (t < HD) {
        float mu  = J.sSin[t] * invN;
        float var = fmaxf(J.sQin[t] * invN - mu * mu, 0.f);
        float rs  = rsqrtf(var + 1e-5f);
        scaleSh[t] = rs;
        tshSh[t]   = 1e-4f / rs - mu;
    }
    __syncthreads();
    for (int i = t; i < HD * 10; i += blockDim.x)
        Ws[i] = scaleSh[i / 10] * J.W[i];
    __syncthreads();
    if (t < 160) {
        int j = t / 16, seg = t % 16;
        float part = 0.f;
#pragma unroll
        for (int k = 0; k < 8; k++) {
            int kk = seg * 8 + k;
            part += tshSh[kk] * Ws[kk * 10 + j];
        }
#pragma unroll
        for (int off = 8; off; off >>= 1)
            part += __shfl_down_sync(0xffffffffu, part, off, 16);
        if (seg == 0) bs[j] = J.b[j] + part;
    }
    __syncthreads();
    int warps = (blockDim.x * gridDim.x) >> 5;
    int gw = (blockIdx.x * blockDim.x + t) >> 5;
    int l  = t & 31;
    for (int i = gw; i < N; i += warps) {
        float4 z = ((const float4*)J.Z)[(size_t)i * HD4 + l];
        float p[10];
#pragma unroll
        for (int j = 0; j < 10; j++) {
            p[j] = z.x * Ws[(4*l+0)*10 + j] + z.y * Ws[(4*l+1)*10 + j]
                 + z.z * Ws[(4*l+2)*10 + j] + z.w * Ws[(4*l+3)*10 + j];
        }
#pragma unroll
        for (int off = 16; off; off >>= 1)
#pragma unroll
            for (int j = 0; j < 10; j++)
                p[j] += __shfl_xor_sync(0xffffffffu, p[j], off);
        float m = -1e30f;
#pragma unroll
        for (int j = 0; j < 10; j++) { p[j] += bs[j]; m = fmaxf(m, p[j]); }
        float s = 0.f;
#pragma unroll
        for (int j = 0; j < 10; j++) s += expf(p[j] - m);
        float lse = m + logf(s);
        if (l < 10) J.out[(size_t)i * 10 + l] = p[l] - lse;
    }
}

// ---------------- host orchestration ------------------------------------------------
extern "C" void kernel_launch(void* const* d_in, const int* in_sizes, int n_in,
                              void* d_out, int out_size) {
    const float* x      = (const float*)d_in[0];
    const int*   ei     = (const int*)  d_in[1];
    const int*   perm   = (const int*)  d_in[2];
    const float* W_feat = (const float*)d_in[3];
    const float* b_feat = (const float*)d_in[4];
    const float* W_convs= (const float*)d_in[5];
    const float* b_convs= (const float*)d_in[6];
    const float* W_ea   = (const float*)d_in[7];
    const float* b_ea   = (const float*)d_in[8];
    const float* W_na   = (const float*)d_in[9];
    const float* b_na   = (const float*)d_in[10];
    const float* W_ctx  = (const float*)d_in[11];
    const float* b_ctx  = (const float*)d_in[12];
    const float* W_obj  = (const float*)d_in[13];
    const float* b_obj  = (const float*)d_in[14];
    const float* W_fc1  = (const float*)d_in[15];
    const float* b_fc1  = (const float*)d_in[16];
    const float* W_fc2  = (const float*)d_in[17];
    const float* b_fc2  = (const float*)d_in[18];

    int N = in_sizes[0] / HD;
    int E = in_sizes[1] / 2;
    const int* row = ei;
    const int* col = ei + E;
    float* out = (float*)d_out;

    float* Bbase = nullptr;
    cudaGetSymbolAddress((void**)&Bbase, g_B);
    float* B0 = Bbase + 0 * (size_t)MAXN * HD;
    float* B1 = Bbase + 1 * (size_t)MAXN * HD;
    float* B2 = Bbase + 2 * (size_t)MAXN * HD;
    float* B3 = Bbase + 3 * (size_t)MAXN * HD;
    float* B4 = Bbase + 4 * (size_t)MAXN * HD;
    float* B5 = Bbase + 5 * (size_t)MAXN * HD;
    __half* H1 = (__half*)B1;
    __half* H5 = (__half*)B5;
    float *degup, *degcp, *degop, *ssump, *ssqp;
    int *cntp, *dcntp;
    cudaGetSymbolAddress((void**)&degup, g_degu);
    cudaGetSymbolAddress((void**)&degcp, g_degc);
    cudaGetSymbolAddress((void**)&degop, g_dego);
    cudaGetSymbolAddress((void**)&ssump, g_ssum);
    cudaGetSymbolAddress((void**)&ssqp,  g_ssq);
    cudaGetSymbolAddress((void**)&cntp,  g_cnt);
    cudaGetSymbolAddress((void**)&dcntp, g_dcnt);
    auto S = [&](int i) { return ssump + i * HD; };
    auto Q = [&](int i) { return ssqp  + i * HD; };

    const int gemm_smem = 2 * 128 * AS * (int)sizeof(__half);
    cudaFuncSetAttribute(k_gemm_tc, cudaFuncAttributeMaxDynamicSharedMemorySize, gemm_smem);

    int gbGemm = (N + 127) / 128;
    int gbN    = (N + 255) / 256;
    int gbE    = (E + 255) / 256;
    int nb     = (N + 1023) / 1024;
    float invN = 1.f / (float)N;

    auto gemm1 = [&](const float* X, float* Y, const float* W, const float* b,
                     int sin, int sout, int relu, int outHalf) {
        GJobs js{};
        js.j[0] = {X, Y, W, b, S(sin), Q(sin),
                   sout >= 0 ? S(sout) : nullptr, sout >= 0 ? Q(sout) : nullptr};
        k_gemm_tc<<<dim3(gbGemm, 1), 512, gemm_smem>>>(js, N, relu, outHalf, invN);
    };

    k_zero_slots<<<(NSLOT * HD + 255) / 256, 256>>>();

    // CSR + degree build
    cudaMemsetAsync(cntp, 0, (size_t)N * sizeof(int));
    cudaMemsetAsync(dcntp, 0, (size_t)N * sizeof(int));
    k_hist<<<gbE, 256>>>(row, col, E);
    k_scan1<<<nb, 1024>>>(N);
    k_scan2<<<1, 64>>>(nb);
    k_scan3<<<nb, 1024>>>(N);
    k_fillcsr<<<gbE, 256>>>(row, col, E);

    // stage 0
    k_stats<<<512, 256>>>(x, N, S(0), Q(0));
    gemm1(x, B2, W_feat, b_feat, 0, 1, 1, 0);

    // conv1: B2 -> B0 (lin fp16 in H1)
    gemm1(B2, (float*)H1, W_convs + 0 * HD * HD, nullptr, 1, -1, 0, 1);
    k_gather<<<1024, 256>>>(H1, B0, degup, b_convs + 0 * HD, N, S(2), Q(2));
    // conv2: B0 -> B2
    gemm1(B0, (float*)H1, W_convs + 1 * HD * HD, nullptr, 2, -1, 0, 1);
    k_gather<<<1024, 256>>>(H1, B2, degup, b_convs + 1 * HD, N, S(3), Q(3));
    // conv3: B2 -> B0
    gemm1(B2, (float*)H1, W_convs + 2 * HD * HD, nullptr, 3, -1, 0, 1);
    k_gather<<<1024, 256>>>(H1, B0, degup, b_convs + 2 * HD, N, nullptr, nullptr);

    // attention
    k_att_node<<<256, 256>>>(B0, W_na, b_na, W_ea, B2, B3, N, S(4), Q(4), S(5), Q(5));
    k_att_edge<<<gbE, 256>>>(row, col, b_ea, E);

    // batched ctx/obj linear (fp16 out): {B2->H1}, {B3->H5}
    {
        GJobs js{};
        js.j[0] = {B2, (float*)H1, W_ctx, nullptr, S(4), Q(4), nullptr, nullptr};
        js.j[1] = {B3, (float*)H5, W_obj, nullptr, S(5), Q(5), nullptr, nullptr};
        k_gemm_tc<<<dim3(gbGemm, 2), 512, gemm_smem>>>(js, N, 0, 1, invN);
    }
    // merged weighted gather (rsqrt inline): xc2=B4 (s6), xo2=B3 (s7)
    k_gather2<<<1024, 256>>>(H1, H5, B4, B3, degcp, degop, b_ctx, b_obj, N,
                             S(6), Q(6), S(7), Q(7));

    // permadd: z = B4[perm] + B3 -> B1 (s11)
    k_permadd_stats<<<256, 256>>>(B4, B3, perm, B1, N, S(11), Q(11));

    // batched readout fc1
    {
        GJobs js{};
        js.j[0] = {B4, B0, W_fc1 + 0 * HD * HD, b_fc1 + 0 * HD, S(6),  Q(6),  S(8),  Q(8)};
        js.j[1] = {B3, B5, W_fc1 + 1 * HD * HD, b_fc1 + 1 * HD, S(7),  Q(7),  S(9),  Q(9)};
        js.j[2] = {B1, B2, W_fc1 + 2 * HD * HD, b_fc1 + 2 * HD, S(11), Q(11), S(10), Q(10)};
        k_gemm_tc<<<dim3(gbGemm, 3), 512, gemm_smem>>>(js, N, 1, 0, invN);
    }
    // batched lsm
    {
        LJobs js{};
        js.j[0] = {B0, out,                      W_fc2 + 0 * HD * 10, b_fc2 + 0 * 10, S(8),  Q(8)};
        js.j[1] = {B5, out + (size_t)N * 10,     W_fc2 + 1 * HD * 10, b_fc2 + 1 * 10, S(9),  Q(9)};
        js.j[2] = {B2, out + (size_t)2 * N * 10, W_fc2 + 2 * HD * 10, b_fc2 + 2 * 10, S(10), Q(10)};
        k_gemm2_lsm<<<dim3(512, 3), 256>>>(js, N, invN);
    }
}

// round 7
// speedup vs baseline: 3.7725x; 1.0160x over previous
#include <cuda_runtime.h>
#include <cuda_fp16.h>

#define HD   128
#define HD4  32
#define MAXN 50000
#define MAXE 800000
#define AS   136   // smem stride in halves (8-half pad -> conflict-free ldmatrix)
#define BS   136
#define NSLOT 12

// ---------------- scratch ------------------------------------------------------
static __device__ float  g_B[6][(size_t)MAXN * HD];
static __device__ float4 g_eanode[MAXN];
static __device__ float  g_att0[MAXE];
static __device__ float  g_att1[MAXE];
static __device__ float  g_degu[MAXN];
static __device__ float  g_degc[MAXN];
static __device__ float  g_dego[MAXN];
static __device__ float  g_ssum[NSLOT * HD];
static __device__ float  g_ssq [NSLOT * HD];
// CSR
static __device__ int    g_cnt[MAXN];
static __device__ int    g_dcnt[MAXN];
static __device__ int    g_rowptr[MAXN + 1];
static __device__ int    g_cursor[MAXN];
static __device__ int    g_er[MAXE];
static __device__ int    g_ee[MAXE];
static __device__ int    g_bsum[64];
static __device__ int    g_boff[64];
static __device__ int    g_total;

struct GJob {
    const float* X; float* Y; const float* W; const float* b;
    const float* sSin; const float* sQin; float* sSout; float* sQout;
};
struct GJobs { GJob j[3]; };
struct LJob {
    const float* Z; float* out; const float* W; const float* b;
    const float* sSin; const float* sQin;
};
struct LJobs { LJob j[3]; };

__device__ __forceinline__ unsigned s2u(const void* p) {
    return (unsigned)__cvta_generic_to_shared(p);
}

__device__ __forceinline__ void ldsm_x4(unsigned* a, unsigned addr) {
    asm volatile("ldmatrix.sync.aligned.m8n8.x4.shared.b16 {%0,%1,%2,%3}, [%4];"
                 : "=r"(a[0]), "=r"(a[1]), "=r"(a[2]), "=r"(a[3]) : "r"(addr));
}
__device__ __forceinline__ void ldsm_x2t(unsigned* b, unsigned addr) {
    asm volatile("ldmatrix.sync.aligned.m8n8.x2.trans.shared.b16 {%0,%1}, [%2];"
                 : "=r"(b[0]), "=r"(b[1]) : "r"(addr));
}
__device__ __forceinline__ void mma_f16(float* c, const unsigned* a, const unsigned* b) {
    asm volatile(
        "mma.sync.aligned.m16n8k16.row.col.f32.f16.f16.f32 "
        "{%0,%1,%2,%3}, {%4,%5,%6,%7}, {%8,%9}, {%0,%1,%2,%3};"
        : "+f"(c[0]), "+f"(c[1]), "+f"(c[2]), "+f"(c[3])
        : "r"(a[0]), "r"(a[1]), "r"(a[2]), "r"(a[3]), "r"(b[0]), "r"(b[1]));
}

// 8-wide fp16 -> fp32 fma into accumulator
__device__ __forceinline__ void fma8(float* a, uint4 u, float nn) {
    __half2* h = (__half2*)&u;
#pragma unroll
    for (int j = 0; j < 4; j++) {
        float2 f = __half22float2(h[j]);
        a[2*j]   += f.x * nn;
        a[2*j+1] += f.y * nn;
    }
}

// ---------------- misc small kernels -------------------------------------------
__global__ void k_stats(const float* __restrict__ X, int N,
                        float* __restrict__ sS, float* __restrict__ sQ) {
    __shared__ float ss[HD], sq[HD];
    int t = threadIdx.x;
    if (t < HD) { ss[t] = 0.f; sq[t] = 0.f; }
    __syncthreads();
    int total  = N * HD4;
    int stride = blockDim.x * gridDim.x;
    int idx    = blockIdx.x * blockDim.x + t;
    int fb     = (idx & 31) * 4;
    float a0=0,a1=0,a2=0,a3=0,q0=0,q1=0,q2=0,q3=0;
    for (; idx < total; idx += stride) {
        float4 v = ((const float4*)X)[idx];
        a0 += v.x; q0 += v.x * v.x;
        a1 += v.y; q1 += v.y * v.y;
        a2 += v.z; q2 += v.z * v.z;
        a3 += v.w; q3 += v.w * v.w;
    }
    atomicAdd(&ss[fb+0], a0); atomicAdd(&sq[fb+0], q0);
    atomicAdd(&ss[fb+1], a1); atomicAdd(&sq[fb+1], q1);
    atomicAdd(&ss[fb+2], a2); atomicAdd(&sq[fb+2], q2);
    atomicAdd(&ss[fb+3], a3); atomicAdd(&sq[fb+3], q3);
    __syncthreads();
    if (t < HD) { atomicAdd(&sS[t], ss[t]); atomicAdd(&sQ[t], sq[t]); }
}

// ---------------- fp16 tensor-core GEMM, inline BN fold, batched ----------------
__global__ void __launch_bounds__(512) k_gemm_tc(GJobs jobs, int N, int doRelu,
                                                 int outHalf, float invN) {
    extern __shared__ __half sh[];
    __half* Ah = sh;               // 128 x AS
    __half* Bh = sh + 128 * AS;    // 128 x BS
    __shared__ float ssum[HD], ssq[HD], scaleSh[HD], tshSh[HD], biasSh[HD];
    __shared__ float bpart[4][HD];
    const GJob J = jobs.j[blockIdx.y];
    int t = threadIdx.x;
    if (t < HD) {
        ssum[t] = 0.f; ssq[t] = 0.f;
        float mu  = J.sSin[t] * invN;
        float var = fmaxf(J.sQin[t] * invN - mu * mu, 0.f);
        float rs  = rsqrtf(var + 1e-5f);
        scaleSh[t] = rs;
        tshSh[t]   = 1e-4f / rs - mu;
        biasSh[t]  = J.b ? J.b[t] : 0.f;
    }
    __syncthreads();
    int base = blockIdx.x * 128;
#pragma unroll
    for (int i = t; i < 4096; i += 512) {
        int r = i >> 5, c = i & 31, gr = base + r;
        float4 v = make_float4(0.f, 0.f, 0.f, 0.f);
        if (gr < N) v = ((const float4*)J.X)[(size_t)gr * 32 + c];
        __half2* dst = (__half2*)&Ah[r * AS + c * 4];
        dst[0] = __floats2half2_rn(v.x, v.y);
        dst[1] = __floats2half2_rn(v.z, v.w);
    }
#pragma unroll
    for (int i = t; i < 4096; i += 512) {
        int r = i >> 5, c = i & 31;
        float4 v = ((const float4*)J.W)[i];
        float s = scaleSh[r];
        __half2* dst = (__half2*)&Bh[r * BS + c * 4];
        dst[0] = __floats2half2_rn(v.x * s, v.y * s);
        dst[1] = __floats2half2_rn(v.z * s, v.w * s);
    }
    __syncthreads();

    {
        int j = t & 127, q = t >> 7;
        float part = 0.f;
        int k0 = q * 32;
#pragma unroll
        for (int k = 0; k < 32; k++)
            part += tshSh[k0 + k] * __half2float(Bh[(k0 + k) * BS + j]);
        bpart[q][j] = part;
    }
    __syncthreads();
    if (t < HD) biasSh[t] += bpart[0][t] + bpart[1][t] + bpart[2][t] + bpart[3][t];
    __syncthreads();

    int lane = t & 31, g = lane >> 2, tg = lane & 3, w = t >> 5;
    int rwb = (w & 3) * 32;
    int cwb = (w >> 2) * 32;

    int m8 = lane >> 3, lr = lane & 7;
    int arowOff = (m8 & 1) * 8 + lr;
    int acolOff = (m8 >> 1) * 8;
    unsigned aBase = s2u(Ah);
    unsigned bBase = s2u(Bh);
    int bk = lane & 15;

    float acc[2][4][4];
#pragma unroll
    for (int m = 0; m < 2; m++)
#pragma unroll
        for (int nt = 0; nt < 4; nt++)
#pragma unroll
            for (int j = 0; j < 4; j++) acc[m][nt][j] = 0.f;

    unsigned aA[8], bA[8], aB[8], bB[8];

#define LDFRAG(K0, AA, BB)                                                      \
    {                                                                           \
        _Pragma("unroll")                                                       \
        for (int m = 0; m < 2; m++) {                                           \
            int arow = rwb + m * 16 + arowOff;                                  \
            ldsm_x4(AA + m * 4, aBase + (arow * AS + (K0) + acolOff) * 2);      \
        }                                                                       \
        _Pragma("unroll")                                                       \
        for (int nt = 0; nt < 4; nt++) {                                        \
            ldsm_x2t(BB + nt * 2, bBase + (((K0) + bk) * BS + cwb + nt * 8) * 2);\
        }                                                                       \
    }

    LDFRAG(0, aA, bA);
#pragma unroll
    for (int ks = 0; ks < 8; ks += 2) {
        if (ks + 1 < 8) LDFRAG((ks + 1) * 16, aB, bB);
#pragma unroll
        for (int m = 0; m < 2; m++)
#pragma unroll
            for (int nt = 0; nt < 4; nt++)
                mma_f16(acc[m][nt], aA + m * 4, bA + nt * 2);
        if (ks + 2 < 8) LDFRAG((ks + 2) * 16, aA, bA);
#pragma unroll
        for (int m = 0; m < 2; m++)
#pragma unroll
            for (int nt = 0; nt < 4; nt++)
                mma_f16(acc[m][nt], aB + m * 4, bB + nt * 2);
    }
#undef LDFRAG

    float ls[4][2], lq[4][2];
#pragma unroll
    for (int nt = 0; nt < 4; nt++) { ls[nt][0]=0.f; ls[nt][1]=0.f; lq[nt][0]=0.f; lq[nt][1]=0.f; }

#pragma unroll
    for (int nt = 0; nt < 4; nt++) {
        int col = cwb + nt * 8 + 2 * tg;
        float bx = biasSh[col], by = biasSh[col + 1];
#pragma unroll
        for (int m = 0; m < 2; m++) {
            int r0 = base + rwb + m * 16 + g;
            int r1 = r0 + 8;
            float y00 = acc[m][nt][0] + bx, y01 = acc[m][nt][1] + by;
            float y10 = acc[m][nt][2] + bx, y11 = acc[m][nt][3] + by;
            if (doRelu) {
                y00 = fmaxf(y00, 0.f); y01 = fmaxf(y01, 0.f);
                y10 = fmaxf(y10, 0.f); y11 = fmaxf(y11, 0.f);
            }
            if (r0 < N) {
                if (outHalf)
                    ((__half2*)J.Y)[(size_t)r0 * 64 + (col >> 1)] = __floats2half2_rn(y00, y01);
                else
                    ((float2*)J.Y)[(size_t)r0 * 64 + (col >> 1)] = make_float2(y00, y01);
                ls[nt][0] += y00; lq[nt][0] += y00 * y00;
                ls[nt][1] += y01; lq[nt][1] += y01 * y01;
            }
            if (r1 < N) {
                if (outHalf)
                    ((__half2*)J.Y)[(size_t)r1 * 64 + (col >> 1)] = __floats2half2_rn(y10, y11);
                else
                    ((float2*)J.Y)[(size_t)r1 * 64 + (col >> 1)] = make_float2(y10, y11);
                ls[nt][0] += y10; lq[nt][0] += y10 * y10;
                ls[nt][1] += y11; lq[nt][1] += y11 * y11;
            }
        }
    }

    if (J.sSout) {
#pragma unroll
        for (int off = 4; off <= 16; off <<= 1)
#pragma unroll
            for (int nt = 0; nt < 4; nt++)
#pragma unroll
                for (int j = 0; j < 2; j++) {
                    ls[nt][j] += __shfl_xor_sync(0xffffffffu, ls[nt][j], off);
                    lq[nt][j] += __shfl_xor_sync(0xffffffffu, lq[nt][j], off);
                }
        if (g == 0) {
#pragma unroll
            for (int nt = 0; nt < 4; nt++)
#pragma unroll
                for (int j = 0; j < 2; j++) {
                    int col = cwb + nt * 8 + 2 * tg + j;
                    atomicAdd(&ssum[col], ls[nt][j]);
                    atomicAdd(&ssq[col],  lq[nt][j]);
                }
        }
        __syncthreads();
        if (t < HD) { atomicAdd(&J.sSout[t], ssum[t]); atomicAdd(&J.sQout[t], ssq[t]); }
    }
}

// ---------------- CSR build ------------------------------------------------------
__global__ void k_hist(const int* __restrict__ row, const int* __restrict__ col, int E) {
    int e = blockIdx.x * blockDim.x + threadIdx.x;
    if (e < NSLOT * HD) { g_ssum[e] = 0.f; g_ssq[e] = 0.f; }   // fold zero_slots
    if (e < E) {
        atomicAdd(&g_cnt[col[e]], 1);
        atomicAdd(&g_dcnt[row[e]], 1);
    }
}

__global__ void __launch_bounds__(1024) k_scan1(int N) {
    __shared__ int wsum[32];
    int t = threadIdx.x;
    int idx = blockIdx.x * 1024 + t;
    int v = (idx < N) ? g_cnt[idx] : 0;
    int x = v;
#pragma unroll
    for (int off = 1; off < 32; off <<= 1) {
        int y = __shfl_up_sync(0xffffffffu, x, off);
        if ((t & 31) >= off) x += y;
    }
    if ((t & 31) == 31) wsum[t >> 5] = x;
    __syncthreads();
    if (t < 32) {
        int y = wsum[t];
#pragma unroll
        for (int off = 1; off < 32; off <<= 1) {
            int z = __shfl_up_sync(0xffffffffu, y, off);
            if (t >= off) y += z;
        }
        wsum[t] = y;
    }
    __syncthreads();
    int winc = (t >= 32) ? wsum[(t >> 5) - 1] : 0;
    int incl = x + winc;
    if (idx < N) g_rowptr[idx] = incl - v;
    if (t == 1023) g_bsum[blockIdx.x] = incl;
}

__global__ void k_scan2(int nb) {
    __shared__ int s[64];
    int t = threadIdx.x;
    int v = (t < nb) ? g_bsum[t] : 0;
    s[t] = v;
    __syncthreads();
    for (int off = 1; off < 64; off <<= 1) {
        int a = (t >= off) ? s[t - off] : 0;
        __syncthreads();
        s[t] += a;
        __syncthreads();
    }
    g_boff[t] = s[t] - v;
    if (t == 63) g_total = s[63];
}

__global__ void k_scan3(int N) {
    int idx = blockIdx.x * blockDim.x + threadIdx.x;
    if (idx < N) {
        int r = g_rowptr[idx] + g_boff[idx >> 10];
        g_rowptr[idx] = r;
        g_cursor[idx] = r;
        g_degu[idx] = rsqrtf((float)g_dcnt[idx] + 1.f);
        g_degc[idx] = 1.f;
        g_dego[idx] = 1.f;
    }
    if (idx == 0) g_rowptr[N] = g_total;
}

__global__ void k_fillcsr(const int* __restrict__ row, const int* __restrict__ col, int E) {
    int e = blockIdx.x * blockDim.x + threadIdx.x;
    if (e >= E) return;
    int c = col[e];
    int p = atomicAdd(&g_cursor[c], 1);
    g_er[p] = row[e];
    g_ee[p] = e;
}

// ---------------- CSR gathers: half-warp edge pairing ---------------------------
// Lanes 0-15 handle edge 2k, lanes 16-31 edge 2k+1 (same node); combine at end.
__global__ void __launch_bounds__(256) k_gather(const __half* __restrict__ lin,
                                                float* __restrict__ out,
                                                const float* __restrict__ dinv,
                                                const float* __restrict__ b, int N,
                                                float* __restrict__ sS,
                                                float* __restrict__ sQ) {
    __shared__ float ssum[HD], ssq[HD];
    int t = threadIdx.x;
    if (t < HD) { ssum[t] = 0.f; ssq[t] = 0.f; }
    __syncthreads();
    int lane = t & 31, hw = lane >> 4, hl = lane & 15;
    int warpId = (blockIdx.x * blockDim.x + t) >> 5;
    int nW = (blockDim.x * gridDim.x) >> 5;
    float4 bb0 = ((const float4*)b)[hl * 2 + 0];
    float4 bb1 = ((const float4*)b)[hl * 2 + 1];
    float st[8] = {0,0,0,0,0,0,0,0}, qt[8] = {0,0,0,0,0,0,0,0};
    for (int i = warpId; i < N; i += nW) {
        int start = g_rowptr[i], end = g_rowptr[i + 1];
        float di = dinv[i];
        float a[8] = {0,0,0,0,0,0,0,0};
        if (hw == 0) {
            uint4 u = __ldg((const uint4*)(lin + (size_t)i * HD) + hl);
            fma8(a, u, di * di);
        }
        int j0 = start;
        for (; j0 + 32 <= end; j0 += 32) {
            int r = g_er[j0 + lane];
            float dr = dinv[r];
#pragma unroll
            for (int k = 0; k < 16; k++) {
                int src = 2 * k + hw;
                int   rr = __shfl_sync(0xffffffffu, r, src);
                float nn = __shfl_sync(0xffffffffu, dr, src) * di;
                uint4 u = __ldg((const uint4*)(lin + (size_t)rr * HD) + hl);
                fma8(a, u, nn);
            }
        }
        if (j0 < end) {
            int cnt = end - j0;
            int r = 0; float dr = 0.f;
            if (lane < cnt) { r = g_er[j0 + lane]; dr = dinv[r]; }
            int pairs = (cnt + 1) >> 1;
            for (int k = 0; k < pairs; k++) {
                int src = 2 * k + hw;
                int   rr = __shfl_sync(0xffffffffu, r, src);
                float nn = __shfl_sync(0xffffffffu, dr, src) * di;
                if (src < cnt) {
                    uint4 u = __ldg((const uint4*)(lin + (size_t)rr * HD) + hl);
                    fma8(a, u, nn);
                }
            }
        }
#pragma unroll
        for (int j = 0; j < 8; j++)
            a[j] += __shfl_xor_sync(0xffffffffu, a[j], 16);
        if (hw == 0) {
            a[0] = fmaxf(a[0] + bb0.x, 0.f); a[1] = fmaxf(a[1] + bb0.y, 0.f);
            a[2] = fmaxf(a[2] + bb0.z, 0.f); a[3] = fmaxf(a[3] + bb0.w, 0.f);
            a[4] = fmaxf(a[4] + bb1.x, 0.f); a[5] = fmaxf(a[5] + bb1.y, 0.f);
            a[6] = fmaxf(a[6] + bb1.z, 0.f); a[7] = fmaxf(a[7] + bb1.w, 0.f);
            float4* o = (float4*)(out + (size_t)i * HD) + hl * 2;
            o[0] = make_float4(a[0], a[1], a[2], a[3]);
            o[1] = make_float4(a[4], a[5], a[6], a[7]);
#pragma unroll
            for (int j = 0; j < 8; j++) { st[j] += a[j]; qt[j] += a[j] * a[j]; }
        }
    }
    if (sS) {
        if (hw == 0) {
#pragma unroll
            for (int j = 0; j < 8; j++) {
                atomicAdd(&ssum[hl * 8 + j], st[j]);
                atomicAdd(&ssq[hl * 8 + j],  qt[j]);
            }
        }
        __syncthreads();
        if (t < HD) { atomicAdd(&sS[t], ssum[t]); atomicAdd(&sQ[t], ssq[t]); }
    }
}

// merged weighted ctx/obj gather, half-warp edge pairing (both matrices per edge)
__global__ void __launch_bounds__(256) k_gather2(const __half* __restrict__ linC,
                                                 const __half* __restrict__ linO,
                                                 float* __restrict__ outC,
                                                 float* __restrict__ outO,
                                                 const float* __restrict__ dc,
                                                 const float* __restrict__ dd,
                                                 const float* __restrict__ bc,
                                                 const float* __restrict__ bo, int N,
                                                 float* sSc, float* sQc,
                                                 float* sSo, float* sQo) {
    __shared__ float red[4][HD];
    int t = threadIdx.x;
    for (int i = t; i < 4 * HD; i += blockDim.x) ((float*)red)[i] = 0.f;
    __syncthreads();
    int lane = t & 31, hw = lane >> 4, hl = lane & 15;
    int warpId = (blockIdx.x * blockDim.x + t) >> 5;
    int nW = (blockDim.x * gridDim.x) >> 5;
    float4 bc0 = ((const float4*)bc)[hl * 2 + 0];
    float4 bc1 = ((const float4*)bc)[hl * 2 + 1];
    float4 bo0 = ((const float4*)bo)[hl * 2 + 0];
    float4 bo1 = ((const float4*)bo)[hl * 2 + 1];
    float stc[8] = {0,0,0,0,0,0,0,0}, qtc[8] = {0,0,0,0,0,0,0,0};
    float sto[8] = {0,0,0,0,0,0,0,0}, qto[8] = {0,0,0,0,0,0,0,0};
    for (int i = warpId; i < N; i += nW) {
        int start = g_rowptr[i], end = g_rowptr[i + 1];
        float dci = rsqrtf(dc[i]), doi = rsqrtf(dd[i]);
        float aC[8] = {0,0,0,0,0,0,0,0}, aO[8] = {0,0,0,0,0,0,0,0};
        if (hw == 0) {
            uint4 u = __ldg((const uint4*)(linC + (size_t)i * HD) + hl);
            fma8(aC, u, dci * dci);
        } else {
            uint4 u = __ldg((const uint4*)(linO + (size_t)i * HD) + hl);
            fma8(aO, u, doi * doi);
        }
        int j0 = start;
        for (; j0 + 32 <= end; j0 += 32) {
            int jj = j0 + lane;
            int r = g_er[jj];
            int e = g_ee[jj];
            float wc = rsqrtf(dc[r]) * g_att0[e];
            float wo = rsqrtf(dd[r]) * g_att1[e];
#pragma unroll
            for (int k = 0; k < 16; k++) {
                int src = 2 * k + hw;
                int   rr = __shfl_sync(0xffffffffu, r, src);
                float nc = __shfl_sync(0xffffffffu, wc, src) * dci;
                float no = __shfl_sync(0xffffffffu, wo, src) * doi;
                uint4 uC = __ldg((const uint4*)(linC + (size_t)rr * HD) + hl);
                uint4 uO = __ldg((const uint4*)(linO + (size_t)rr * HD) + hl);
                fma8(aC, uC, nc);
                fma8(aO, uO, no);
            }
        }
        if (j0 < end) {
            int cnt = end - j0;
            int r = 0; float wc = 0.f, wo = 0.f;
            if (lane < cnt) {
                int jj = j0 + lane;
                r = g_er[jj];
                int e = g_ee[jj];
                wc = rsqrtf(dc[r]) * g_att0[e];
                wo = rsqrtf(dd[r]) * g_att1[e];
            }
            int pairs = (cnt + 1) >> 1;
            for (int k = 0; k < pairs; k++) {
                int src = 2 * k + hw;
                int   rr = __shfl_sync(0xffffffffu, r, src);
                float nc = __shfl_sync(0xffffffffu, wc, src) * dci;
                float no = __shfl_sync(0xffffffffu, wo, src) * doi;
                if (src < cnt) {
                    uint4 uC = __ldg((const uint4*)(linC + (size_t)rr * HD) + hl);
                    uint4 uO = __ldg((const uint4*)(linO + (size_t)rr * HD) + hl);
                    fma8(aC, uC, nc);
                    fma8(aO, uO, no);
                }
            }
        }
#pragma unroll
        for (int j = 0; j < 8; j++) {
            aC[j] += __shfl_xor_sync(0xffffffffu, aC[j], 16);
            aO[j] += __shfl_xor_sync(0xffffffffu, aO[j], 16);
        }
        if (hw == 0) {
            aC[0] = fmaxf(aC[0] + bc0.x, 0.f); aC[1] = fmaxf(aC[1] + bc0.y, 0.f);
            aC[2] = fmaxf(aC[2] + bc0.z, 0.f); aC[3] = fmaxf(aC[3] + bc0.w, 0.f);
            aC[4] = fmaxf(aC[4] + bc1.x, 0.f); aC[5] = fmaxf(aC[5] + bc1.y, 0.f);
            aC[6] = fmaxf(aC[6] + bc1.z, 0.f); aC[7] = fmaxf(aC[7] + bc1.w, 0.f);
            aO[0] = fmaxf(aO[0] + bo0.x, 0.f); aO[1] = fmaxf(aO[1] + bo0.y, 0.f);
            aO[2] = fmaxf(aO[2] + bo0.z, 0.f); aO[3] = fmaxf(aO[3] + bo0.w, 0.f);
            aO[4] = fmaxf(aO[4] + bo1.x, 0.f); aO[5] = fmaxf(aO[5] + bo1.y, 0.f);
            aO[6] = fmaxf(aO[6] + bo1.z, 0.f); aO[7] = fmaxf(aO[7] + bo1.w, 0.f);
            float4* oc = (float4*)(outC + (size_t)i * HD) + hl * 2;
            float4* oo = (float4*)(outO + (size_t)i * HD) + hl * 2;
            oc[0] = make_float4(aC[0], aC[1], aC[2], aC[3]);
            oc[1] = make_float4(aC[4], aC[5], aC[6], aC[7]);
            oo[0] = make_float4(aO[0], aO[1], aO[2], aO[3]);
            oo[1] = make_float4(aO[4], aO[5], aO[6], aO[7]);
#pragma unroll
            for (int j = 0; j < 8; j++) {
                stc[j] += aC[j]; qtc[j] += aC[j] * aC[j];
                sto[j] += aO[j]; qto[j] += aO[j] * aO[j];
            }
        }
    }
    if (hw == 0) {
#pragma unroll
        for (int j = 0; j < 8; j++) {
            atomicAdd(&red[0][hl * 8 + j], stc[j]);
            atomicAdd(&red[1][hl * 8 + j], qtc[j]);
            atomicAdd(&red[2][hl * 8 + j], sto[j]);
            atomicAdd(&red[3][hl * 8 + j], qto[j]);
        }
    }
    __syncthreads();
    if (t < HD) {
        atomicAdd(&sSc[t], red[0][t]); atomicAdd(&sQc[t], red[1][t]);
        atomicAdd(&sSo[t], red[2][t]); atomicAdd(&sQo[t], red[3][t]);
    }
}

// ---------------- attention --------------------------------------------------------
__global__ void k_att_node(const float* __restrict__ h,
                           const float* __restrict__ Wna, const float* __restrict__ bna,
                           const float* __restrict__ Wea,
                           float* __restrict__ xc, float* __restrict__ xo, int N,
                           float* sSc, float* sQc, float* sSo, float* sQo) {
    __shared__ float Wc[HD * 6];
    __shared__ float red[4][HD];
    int t = threadIdx.x;
    for (int i = t; i < HD * 6; i += blockDim.x) {
        int k = i / 6, j = i % 6;
        float v;
        if (j < 2)      v = Wna[k * 2 + j];
        else if (j < 4) v = Wea[k * 2 + (j - 2)];
        else            v = Wea[(HD + k) * 2 + (j - 4)];
        Wc[i] = v;
    }
    for (int i = t; i < 4 * HD; i += blockDim.x) ((float*)red)[i] = 0.f;
    __syncthreads();
    int warps = (blockDim.x * gridDim.x) >> 5;
    int gw = (blockIdx.x * blockDim.x + t) >> 5;
    int l  = t & 31;
    float b0 = bna[0], b1 = bna[1];
    float sc[4]={0,0,0,0}, qc[4]={0,0,0,0}, so[4]={0,0,0,0}, qo[4]={0,0,0,0};
    for (int i = gw; i < N; i += warps) {
        float4 hv = ((const float4*)h)[(size_t)i * HD4 + l];
        float p[6];
#pragma unroll
        for (int j = 0; j < 6; j++) {
            p[j] = hv.x * Wc[(4*l+0)*6 + j] + hv.y * Wc[(4*l+1)*6 + j]
                 + hv.z * Wc[(4*l+2)*6 + j] + hv.w * Wc[(4*l+3)*6 + j];
        }
#pragma unroll
        for (int off = 16; off; off >>= 1)
#pragma unroll
            for (int j = 0; j < 6; j++)
                p[j] += __shfl_xor_sync(0xffffffffu, p[j], off);
        float l0 = p[0] + b0, l1 = p[1] + b1;
        float m  = fmaxf(l0, l1);
        float e0 = expf(l0 - m), e1 = expf(l1 - m);
        float inv = 1.f / (e0 + e1);
        float a0 = e0 * inv, a1 = e1 * inv;
        float4 vc = make_float4(hv.x*a0, hv.y*a0, hv.z*a0, hv.w*a0);
        float4 vo = make_float4(hv.x*a1, hv.y*a1, hv.z*a1, hv.w*a1);
        ((float4*)xc)[(size_t)i * HD4 + l] = vc;
        ((float4*)xo)[(size_t)i * HD4 + l] = vo;
        sc[0]+=vc.x; qc[0]+=vc.x*vc.x; sc[1]+=vc.y; qc[1]+=vc.y*vc.y;
        sc[2]+=vc.z; qc[2]+=vc.z*vc.z; sc[3]+=vc.w; qc[3]+=vc.w*vc.w;
        so[0]+=vo.x; qo[0]+=vo.x*vo.x; so[1]+=vo.y; qo[1]+=vo.y*vo.y;
        so[2]+=vo.z; qo[2]+=vo.z*vo.z; so[3]+=vo.w; qo[3]+=vo.w*vo.w;
        if (l == 0) g_eanode[i] = make_float4(p[2], p[3], p[4], p[5]);
    }
#pragma unroll
    for (int j = 0; j < 4; j++) {
        atomicAdd(&red[0][l*4+j], sc[j]);
        atomicAdd(&red[1][l*4+j], qc[j]);
        atomicAdd(&red[2][l*4+j], so[j]);
        atomicAdd(&red[3][l*4+j], qo[j]);
    }
    __syncthreads();
    if (t < HD) {
        atomicAdd(&sSc[t], red[0][t]); atomicAdd(&sQc[t], red[1][t]);
        atomicAdd(&sSo[t], red[2][t]); atomicAdd(&sQo[t], red[3][t]);
    }
}

__global__ void k_att_edge(const int* __restrict__ row, const int* __restrict__ col,
                           const float* __restrict__ bea, int E) {
    int e = blockIdx.x * blockDim.x + threadIdx.x;
    if (e >= E) return;
    int r = row[e], c = col[e];
    float4 tr = g_eanode[r], tc = g_eanode[c];
    float l0 = tr.x + tc.z + bea[0];
    float l1 = tr.y + tc.w + bea[1];
    float m  = fmaxf(l0, l1);
    float e0 = expf(l0 - m), e1 = expf(l1 - m);
    float inv = 1.f / (e0 + e1);
    float a0 = e0 * inv, a1 = e1 * inv;
    g_att0[e] = a0; g_att1[e] = a1;
    atomicAdd(&g_degc[r], a0);
    atomicAdd(&g_dego[r], a1);
}

__global__ void k_permadd_stats(const float* __restrict__ xc, const float* __restrict__ xo,
                                const int* __restrict__ perm, float* __restrict__ z, int N,
                                float* __restrict__ sS, float* __restrict__ sQ) {
    __shared__ float ssum[HD], ssq[HD];
    int t = threadIdx.x;
    if (t < HD) { ssum[t] = 0.f; ssq[t] = 0.f; }
    __syncthreads();
    int total  = N * HD4;
    int stride = blockDim.x * gridDim.x;
    int idx    = blockIdx.x * blockDim.x + t;
    int fb     = (idx & 31) * 4;
    float a0=0,a1=0,a2=0,a3=0,q0=0,q1=0,q2=0,q3=0;
    for (; idx < total; idx += stride) {
        int i = idx >> 5, l = idx & 31;
        int p = perm[i];
        float4 a = ((const float4*)xc)[(size_t)p * HD4 + l];
        float4 b = ((const float4*)xo)[idx];
        a.x += b.x; a.y += b.y; a.z += b.z; a.w += b.w;
        ((float4*)z)[idx] = a;
        a0 += a.x; q0 += a.x*a.x; a1 += a.y; q1 += a.y*a.y;
        a2 += a.z; q2 += a.z*a.z; a3 += a.w; q3 += a.w*a.w;
    }
    atomicAdd(&ssum[fb+0], a0); atomicAdd(&ssq[fb+0], q0);
    atomicAdd(&ssum[fb+1], a1); atomicAdd(&ssq[fb+1], q1);
    atomicAdd(&ssum[fb+2], a2); atomicAdd(&ssq[fb+2], q2);
    atomicAdd(&ssum[fb+3], a3); atomicAdd(&ssq[fb+3], q3);
    __syncthreads();
    if (t < HD) { atomicAdd(&sS[t], ssum[t]); atomicAdd(&sQ[t], ssq[t]); }
}

// ---------------- [N,128]x[128,10] + log_softmax, inline fold, batched ----------
__global__ void k_gemm2_lsm(LJobs jobs, int N, float invN) {
    __shared__ float Ws[HD * 10];
    __shared__ float bs[10];
    __shared__ float scaleSh[HD], tshSh[HD];
    const LJob J = jobs.j[blockIdx.y];
    int t = threadIdx.x;
    if (t < HD) {
        float mu  = J.sSin[t] * invN;
        float var = fmaxf(J.sQin[t] * invN - mu * mu, 0.f);
        float rs  = rsqrtf(var + 1e-5f);
        scaleSh[t] = rs;
        tshSh[t]   = 1e-4f / rs - mu;
    }
    __syncthreads();
    for (int i = t; i < HD * 10; i += blockDim.x)
        Ws[i] = scaleSh[i / 10] * J.W[i];
    __syncthreads();
    if (t < 160) {
        int j = t / 16, seg = t % 16;
        float part = 0.f;
#pragma unroll
        for (int k = 0; k < 8; k++) {
            int kk = seg * 8 + k;
            part += tshSh[kk] * Ws[kk * 10 + j];
        }
#pragma unroll
        for (int off = 8; off; off >>= 1)
            part += __shfl_down_sync(0xffffffffu, part, off, 16);
        if (seg == 0) bs[j] = J.b[j] + part;
    }
    __syncthreads();
    int warps = (blockDim.x * gridDim.x) >> 5;
    int gw = (blockIdx.x * blockDim.x + t) >> 5;
    int l  = t & 31;
    for (int i = gw; i < N; i += warps) {
        float4 z = ((const float4*)J.Z)[(size_t)i * HD4 + l];
        float p[10];
#pragma unroll
        for (int j = 0; j < 10; j++) {
            p[j] = z.x * Ws[(4*l+0)*10 + j] + z.y * Ws[(4*l+1)*10 + j]
                 + z.z * Ws[(4*l+2)*10 + j] + z.w * Ws[(4*l+3)*10 + j];
        }
#pragma unroll
        for (int off = 16; off; off >>= 1)
#pragma unroll
            for (int j = 0; j < 10; j++)
                p[j] += __shfl_xor_sync(0xffffffffu, p[j], off);
        float m = -1e30f;
#pragma unroll
        for (int j = 0; j < 10; j++) { p[j] += bs[j]; m = fmaxf(m, p[j]); }
        float s = 0.f;
#pragma unroll
        for (int j = 0; j < 10; j++) s += expf(p[j] - m);
        float lse = m + logf(s);
        if (l < 10) J.out[(size_t)i * 10 + l] = p[l] - lse;
    }
}

// ---------------- host orchestration ------------------------------------------------
extern "C" void kernel_launch(void* const* d_in, const int* in_sizes, int n_in,
                              void* d_out, int out_size) {
    const float* x      = (const float*)d_in[0];
    const int*   ei     = (const int*)  d_in[1];
    const int*   perm   = (const int*)  d_in[2];
    const float* W_feat = (const float*)d_in[3];
    const float* b_feat = (const float*)d_in[4];
    const float* W_convs= (const float*)d_in[5];
    const float* b_convs= (const float*)d_in[6];
    const float* W_ea   = (const float*)d_in[7];
    const float* b_ea   = (const float*)d_in[8];
    const float* W_na   = (const float*)d_in[9];
    const float* b_na   = (const float*)d_in[10];
    const float* W_ctx  = (const float*)d_in[11];
    const float* b_ctx  = (const float*)d_in[12];
    const float* W_obj  = (const float*)d_in[13];
    const float* b_obj  = (const float*)d_in[14];
    const float* W_fc1  = (const float*)d_in[15];
    const float* b_fc1  = (const float*)d_in[16];
    const float* W_fc2  = (const float*)d_in[17];
    const float* b_fc2  = (const float*)d_in[18];

    int N = in_sizes[0] / HD;
    int E = in_sizes[1] / 2;
    const int* row = ei;
    const int* col = ei + E;
    float* out = (float*)d_out;

    float* Bbase = nullptr;
    cudaGetSymbolAddress((void**)&Bbase, g_B);
    float* B0 = Bbase + 0 * (size_t)MAXN * HD;
    float* B1 = Bbase + 1 * (size_t)MAXN * HD;
    float* B2 = Bbase + 2 * (size_t)MAXN * HD;
    float* B3 = Bbase + 3 * (size_t)MAXN * HD;
    float* B4 = Bbase + 4 * (size_t)MAXN * HD;
    float* B5 = Bbase + 5 * (size_t)MAXN * HD;
    __half* H1 = (__half*)B1;
    __half* H5 = (__half*)B5;
    float *degup, *degcp, *degop, *ssump, *ssqp;
    int *cntp, *dcntp;
    cudaGetSymbolAddress((void**)&degup, g_degu);
    cudaGetSymbolAddress((void**)&degcp, g_degc);
    cudaGetSymbolAddress((void**)&degop, g_dego);
    cudaGetSymbolAddress((void**)&ssump, g_ssum);
    cudaGetSymbolAddress((void**)&ssqp,  g_ssq);
    cudaGetSymbolAddress((void**)&cntp,  g_cnt);
    cudaGetSymbolAddress((void**)&dcntp, g_dcnt);
    auto S = [&](int i) { return ssump + i * HD; };
    auto Q = [&](int i) { return ssqp  + i * HD; };

    const int gemm_smem = 2 * 128 * AS * (int)sizeof(__half);
    cudaFuncSetAttribute(k_gemm_tc, cudaFuncAttributeMaxDynamicSharedMemorySize, gemm_smem);

    int gbGemm = (N + 127) / 128;
    int gbN    = (N + 255) / 256;
    int gbE    = (E + 255) / 256;
    int nb     = (N + 1023) / 1024;
    float invN = 1.f / (float)N;

    auto gemm1 = [&](const float* X, float* Y, const float* W, const float* b,
                     int sin, int sout, int relu, int outHalf) {
        GJobs js{};
        js.j[0] = {X, Y, W, b, S(sin), Q(sin),
                   sout >= 0 ? S(sout) : nullptr, sout >= 0 ? Q(sout) : nullptr};
        k_gemm_tc<<<dim3(gbGemm, 1), 512, gemm_smem>>>(js, N, relu, outHalf, invN);
    };

    // CSR + degree build (hist also zeroes the stats slots)
    cudaMemsetAsync(cntp, 0, (size_t)N * sizeof(int));
    cudaMemsetAsync(dcntp, 0, (size_t)N * sizeof(int));
    k_hist<<<gbE, 256>>>(row, col, E);
    k_scan1<<<nb, 1024>>>(N);
    k_scan2<<<1, 64>>>(nb);
    k_scan3<<<nb, 1024>>>(N);
    k_fillcsr<<<gbE, 256>>>(row, col, E);

    // stage 0
    k_stats<<<512, 256>>>(x, N, S(0), Q(0));
    gemm1(x, B2, W_feat, b_feat, 0, 1, 1, 0);

    // conv1: B2 -> B0 (lin fp16 in H1)
    gemm1(B2, (float*)H1, W_convs + 0 * HD * HD, nullptr, 1, -1, 0, 1);
    k_gather<<<1024, 256>>>(H1, B0, degup, b_convs + 0 * HD, N, S(2), Q(2));
    // conv2: B0 -> B2
    gemm1(B0, (float*)H1, W_convs + 1 * HD * HD, nullptr, 2, -1, 0, 1);
    k_gather<<<1024, 256>>>(H1, B2, degup, b_convs + 1 * HD, N, S(3), Q(3));
    // conv3: B2 -> B0
    gemm1(B2, (float*)H1, W_convs + 2 * HD * HD, nullptr, 3, -1, 0, 1);
    k_gather<<<1024, 256>>>(H1, B0, degup, b_convs + 2 * HD, N, nullptr, nullptr);

    // attention
    k_att_node<<<256, 256>>>(B0, W_na, b_na, W_ea, B2, B3, N, S(4), Q(4), S(5), Q(5));
    k_att_edge<<<gbE, 256>>>(row, col, b_ea, E);

    // batched ctx/obj linear (fp16 out): {B2->H1}, {B3->H5}
    {
        GJobs js{};
        js.j[0] = {B2, (float*)H1, W_ctx, nullptr, S(4), Q(4), nullptr, nullptr};
        js.j[1] = {B3, (float*)H5, W_obj, nullptr, S(5), Q(5), nullptr, nullptr};
        k_gemm_tc<<<dim3(gbGemm, 2), 512, gemm_smem>>>(js, N, 0, 1, invN);
    }
    // merged weighted gather (rsqrt inline): xc2=B4 (s6), xo2=B3 (s7)
    k_gather2<<<1024, 256>>>(H1, H5, B4, B3, degcp, degop, b_ctx, b_obj, N,
                             S(6), Q(6), S(7), Q(7));

    // permadd: z = B4[perm] + B3 -> B1 (s11)
    k_permadd_stats<<<256, 256>>>(B4, B3, perm, B1, N, S(11), Q(11));

    // batched readout fc1
    {
        GJobs js{};
        js.j[0] = {B4, B0, W_fc1 + 0 * HD * HD, b_fc1 + 0 * HD, S(6),  Q(6),  S(8),  Q(8)};
        js.j[1] = {B3, B5, W_fc1 + 1 * HD * HD, b_fc1 + 1 * HD, S(7),  Q(7),  S(9),  Q(9)};
        js.j[2] = {B1, B2, W_fc1 + 2 * HD * HD, b_fc1 + 2 * HD, S(11), Q(11), S(10), Q(10)};
        k_gemm_tc<<<dim3(gbGemm, 3), 512, gemm_smem>>>(js, N, 1, 0, invN);
    }
    // batched lsm
    {
        LJobs js{};
        js.j[0] = {B0, out,                      W_fc2 + 0 * HD * 10, b_fc2 + 0 * 10, S(8),  Q(8)};
        js.j[1] = {B5, out + (size_t)N * 10,     W_fc2 + 1 * HD * 10, b_fc2 + 1 * 10, S(9),  Q(9)};
        js.j[2] = {B2, out + (size_t)2 * N * 10, W_fc2 + 2 * HD * 10, b_fc2 + 2 * 10, S(10), Q(10)};
        k_gemm2_lsm<<<dim3(512, 3), 256>>>(js, N, invN);
    }
}

// round 8
// speedup vs baseline: 3.8641x; 1.0243x over previous
#include <cuda_runtime.h>
#include <cuda_fp16.h>

#define HD   128
#define HD4  32
#define MAXN 50000
#define MAXE 800000
#define AS   136   // smem stride in halves (8-half pad -> conflict-free ldmatrix)
#define BS   136
#define NSLOT 12

// ---------------- scratch ------------------------------------------------------
static __device__ float  g_B[6][(size_t)MAXN * HD];
static __device__ float4 g_eanode[MAXN];
static __device__ float  g_att0[MAXE];
static __device__ float  g_att1[MAXE];
static __device__ float  g_degu[MAXN];
static __device__ float  g_degc[MAXN];
static __device__ float  g_dego[MAXN];
static __device__ float  g_stats[2 * NSLOT * HD];   // [sum | sq]
// CSR
static __device__ int    g_cnt2[2 * MAXN];          // [in-cnt | out-cnt]
static __device__ int    g_rowptr[MAXN + 1];
static __device__ int    g_cursor[MAXN];
static __device__ int    g_er[MAXE];
static __device__ int    g_ee[MAXE];
static __device__ int    g_bsum[64];

struct GJob {
    const float* X; float* Y; const float* W; const float* b;
    const float* sSin; const float* sQin; float* sSout; float* sQout;
};
struct GJobs { GJob j[3]; };
struct LJob {
    const float* Z; float* out; const float* W; const float* b;
    const float* sSin; const float* sQin;
};
struct LJobs { LJob j[3]; };

__device__ __forceinline__ unsigned s2u(const void* p) {
    return (unsigned)__cvta_generic_to_shared(p);
}

__device__ __forceinline__ void ldsm_x4(unsigned* a, unsigned addr) {
    asm volatile("ldmatrix.sync.aligned.m8n8.x4.shared.b16 {%0,%1,%2,%3}, [%4];"
                 : "=r"(a[0]), "=r"(a[1]), "=r"(a[2]), "=r"(a[3]) : "r"(addr));
}
__device__ __forceinline__ void ldsm_x2t(unsigned* b, unsigned addr) {
    asm volatile("ldmatrix.sync.aligned.m8n8.x2.trans.shared.b16 {%0,%1}, [%2];"
                 : "=r"(b[0]), "=r"(b[1]) : "r"(addr));
}
__device__ __forceinline__ void mma_f16(float* c, const unsigned* a, const unsigned* b) {
    asm volatile(
        "mma.sync.aligned.m16n8k16.row.col.f32.f16.f16.f32 "
        "{%0,%1,%2,%3}, {%4,%5,%6,%7}, {%8,%9}, {%0,%1,%2,%3};"
        : "+f"(c[0]), "+f"(c[1]), "+f"(c[2]), "+f"(c[3])
        : "r"(a[0]), "r"(a[1]), "r"(a[2]), "r"(a[3]), "r"(b[0]), "r"(b[1]));
}

__device__ __forceinline__ void fma8(float* a, uint4 u, float nn) {
    __half2* h = (__half2*)&u;
#pragma unroll
    for (int j = 0; j < 4; j++) {
        float2 f = __half22float2(h[j]);
        a[2*j]   += f.x * nn;
        a[2*j+1] += f.y * nn;
    }
}

// ---------------- misc small kernels -------------------------------------------
__global__ void k_stats(const float* __restrict__ X, int N,
                        float* __restrict__ sS, float* __restrict__ sQ) {
    __shared__ float ss[HD], sq[HD];
    int t = threadIdx.x;
    if (t < HD) { ss[t] = 0.f; sq[t] = 0.f; }
    __syncthreads();
    int total  = N * HD4;
    int stride = blockDim.x * gridDim.x;
    int idx    = blockIdx.x * blockDim.x + t;
    int fb     = (idx & 31) * 4;
    float a0=0,a1=0,a2=0,a3=0,q0=0,q1=0,q2=0,q3=0;
    for (; idx < total; idx += stride) {
        float4 v = ((const float4*)X)[idx];
        a0 += v.x; q0 += v.x * v.x;
        a1 += v.y; q1 += v.y * v.y;
        a2 += v.z; q2 += v.z * v.z;
        a3 += v.w; q3 += v.w * v.w;
    }
    atomicAdd(&ss[fb+0], a0); atomicAdd(&sq[fb+0], q0);
    atomicAdd(&ss[fb+1], a1); atomicAdd(&sq[fb+1], q1);
    atomicAdd(&ss[fb+2], a2); atomicAdd(&sq[fb+2], q2);
    atomicAdd(&ss[fb+3], a3); atomicAdd(&sq[fb+3], q3);
    __syncthreads();
    if (t < HD) { atomicAdd(&sS[t], ss[t]); atomicAdd(&sQ[t], sq[t]); }
}

// ---------------- fp16 tensor-core GEMM, inline BN fold, batched ----------------
__global__ void __launch_bounds__(512) k_gemm_tc(GJobs jobs, int N, int doRelu,
                                                 int outHalf, float invN) {
    extern __shared__ __half sh[];
    __half* Ah = sh;               // 128 x AS
    __half* Bh = sh + 128 * AS;    // 128 x BS
    __shared__ float ssum[HD], ssq[HD], scaleSh[HD], tshSh[HD], biasSh[HD];
    __shared__ float bpart[4][HD];
    const GJob J = jobs.j[blockIdx.y];
    int t = threadIdx.x;
    if (t < HD) {
        ssum[t] = 0.f; ssq[t] = 0.f;
        float mu  = J.sSin[t] * invN;
        float var = fmaxf(J.sQin[t] * invN - mu * mu, 0.f);
        float rs  = rsqrtf(var + 1e-5f);
        scaleSh[t] = rs;
        tshSh[t]   = 1e-4f / rs - mu;
        biasSh[t]  = J.b ? J.b[t] : 0.f;
    }
    __syncthreads();
    int base = blockIdx.x * 128;
#pragma unroll
    for (int i = t; i < 4096; i += 512) {
        int r = i >> 5, c = i & 31, gr = base + r;
        float4 v = make_float4(0.f, 0.f, 0.f, 0.f);
        if (gr < N) v = ((const float4*)J.X)[(size_t)gr * 32 + c];
        __half2* dst = (__half2*)&Ah[r * AS + c * 4];
        dst[0] = __floats2half2_rn(v.x, v.y);
        dst[1] = __floats2half2_rn(v.z, v.w);
    }
#pragma unroll
    for (int i = t; i < 4096; i += 512) {
        int r = i >> 5, c = i & 31;
        float4 v = ((const float4*)J.W)[i];
        float s = scaleSh[r];
        __half2* dst = (__half2*)&Bh[r * BS + c * 4];
        dst[0] = __floats2half2_rn(v.x * s, v.y * s);
        dst[1] = __floats2half2_rn(v.z * s, v.w * s);
    }
    __syncthreads();

    {
        int j = t & 127, q = t >> 7;
        float part = 0.f;
        int k0 = q * 32;
#pragma unroll
        for (int k = 0; k < 32; k++)
            part += tshSh[k0 + k] * __half2float(Bh[(k0 + k) * BS + j]);
        bpart[q][j] = part;
    }
    __syncthreads();
    if (t < HD) biasSh[t] += bpart[0][t] + bpart[1][t] + bpart[2][t] + bpart[3][t];
    __syncthreads();

    int lane = t & 31, g = lane >> 2, tg = lane & 3, w = t >> 5;
    int rwb = (w & 3) * 32;
    int cwb = (w >> 2) * 32;

    int m8 = lane >> 3, lr = lane & 7;
    int arowOff = (m8 & 1) * 8 + lr;
    int acolOff = (m8 >> 1) * 8;
    unsigned aBase = s2u(Ah);
    unsigned bBase = s2u(Bh);
    int bk = lane & 15;

    float acc[2][4][4];
#pragma unroll
    for (int m = 0; m < 2; m++)
#pragma unroll
        for (int nt = 0; nt < 4; nt++)
#pragma unroll
            for (int j = 0; j < 4; j++) acc[m][nt][j] = 0.f;

    unsigned aA[8], bA[8], aB[8], bB[8];

#define LDFRAG(K0, AA, BB)                                                      \
    {                                                                           \
        _Pragma("unroll")                                                       \
        for (int m = 0; m < 2; m++) {                                           \
            int arow = rwb + m * 16 + arowOff;                                  \
            ldsm_x4(AA + m * 4, aBase + (arow * AS + (K0) + acolOff) * 2);      \
        }                                                                       \
        _Pragma("unroll")                                                       \
        for (int nt = 0; nt < 4; nt++) {                                        \
            ldsm_x2t(BB + nt * 2, bBase + (((K0) + bk) * BS + cwb + nt * 8) * 2);\
        }                                                                       \
    }

    LDFRAG(0, aA, bA);
#pragma unroll
    for (int ks = 0; ks < 8; ks += 2) {
        if (ks + 1 < 8) LDFRAG((ks + 1) * 16, aB, bB);
#pragma unroll
        for (int m = 0; m < 2; m++)
#pragma unroll
            for (int nt = 0; nt < 4; nt++)
                mma_f16(acc[m][nt], aA + m * 4, bA + nt * 2);
        if (ks + 2 < 8) LDFRAG((ks + 2) * 16, aA, bA);
#pragma unroll
        for (int m = 0; m < 2; m++)
#pragma unroll
            for (int nt = 0; nt < 4; nt++)
                mma_f16(acc[m][nt], aB + m * 4, bB + nt * 2);
    }
#undef LDFRAG

    float ls[4][2], lq[4][2];
#pragma unroll
    for (int nt = 0; nt < 4; nt++) { ls[nt][0]=0.f; ls[nt][1]=0.f; lq[nt][0]=0.f; lq[nt][1]=0.f; }

#pragma unroll
    for (int nt = 0; nt < 4; nt++) {
        int col = cwb + nt * 8 + 2 * tg;
        float bx = biasSh[col], by = biasSh[col + 1];
#pragma unroll
        for (int m = 0; m < 2; m++) {
            int r0 = base + rwb + m * 16 + g;
            int r1 = r0 + 8;
            float y00 = acc[m][nt][0] + bx, y01 = acc[m][nt][1] + by;
            float y10 = acc[m][nt][2] + bx, y11 = acc[m][nt][3] + by;
            if (doRelu) {
                y00 = fmaxf(y00, 0.f); y01 = fmaxf(y01, 0.f);
                y10 = fmaxf(y10, 0.f); y11 = fmaxf(y11, 0.f);
            }
            if (r0 < N) {
                if (outHalf)
                    ((__half2*)J.Y)[(size_t)r0 * 64 + (col >> 1)] = __floats2half2_rn(y00, y01);
                else
                    ((float2*)J.Y)[(size_t)r0 * 64 + (col >> 1)] = make_float2(y00, y01);
                ls[nt][0] += y00; lq[nt][0] += y00 * y00;
                ls[nt][1] += y01; lq[nt][1] += y01 * y01;
            }
            if (r1 < N) {
                if (outHalf)
                    ((__half2*)J.Y)[(size_t)r1 * 64 + (col >> 1)] = __floats2half2_rn(y10, y11);
                else
                    ((float2*)J.Y)[(size_t)r1 * 64 + (col >> 1)] = make_float2(y10, y11);
                ls[nt][0] += y10; lq[nt][0] += y10 * y10;
                ls[nt][1] += y11; lq[nt][1] += y11 * y11;
            }
        }
    }

    if (J.sSout) {
#pragma unroll
        for (int off = 4; off <= 16; off <<= 1)
#pragma unroll
            for (int nt = 0; nt < 4; nt++)
#pragma unroll
                for (int j = 0; j < 2; j++) {
                    ls[nt][j] += __shfl_xor_sync(0xffffffffu, ls[nt][j], off);
                    lq[nt][j] += __shfl_xor_sync(0xffffffffu, lq[nt][j], off);
                }
        if (g == 0) {
#pragma unroll
            for (int nt = 0; nt < 4; nt++)
#pragma unroll
                for (int j = 0; j < 2; j++) {
                    int col = cwb + nt * 8 + 2 * tg + j;
                    atomicAdd(&ssum[col], ls[nt][j]);
                    atomicAdd(&ssq[col],  lq[nt][j]);
                }
        }
        __syncthreads();
        if (t < HD) { atomicAdd(&J.sSout[t], ssum[t]); atomicAdd(&J.sQout[t], ssq[t]); }
    }
}

// ---------------- CSR build ------------------------------------------------------
__global__ void k_hist(const int* __restrict__ row, const int* __restrict__ col, int E) {
    int e = blockIdx.x * blockDim.x + threadIdx.x;
    if (e < E) {
        atomicAdd(&g_cnt2[col[e]], 1);
        atomicAdd(&g_cnt2[MAXN + row[e]], 1);
    }
}

__global__ void __launch_bounds__(1024) k_scan1(int N) {
    __shared__ int wsum[32];
    int t = threadIdx.x;
    int idx = blockIdx.x * 1024 + t;
    int v = (idx < N) ? g_cnt2[idx] : 0;
    int x = v;
#pragma unroll
    for (int off = 1; off < 32; off <<= 1) {
        int y = __shfl_up_sync(0xffffffffu, x, off);
        if ((t & 31) >= off) x += y;
    }
    if ((t & 31) == 31) wsum[t >> 5] = x;
    __syncthreads();
    if (t < 32) {
        int y = wsum[t];
#pragma unroll
        for (int off = 1; off < 32; off <<= 1) {
            int z = __shfl_up_sync(0xffffffffu, y, off);
            if (t >= off) y += z;
        }
        wsum[t] = y;
    }
    __syncthreads();
    int winc = (t >= 32) ? wsum[(t >> 5) - 1] : 0;
    int incl = x + winc;
    if (idx < N) g_rowptr[idx] = incl - v;
    if (t == 1023) g_bsum[blockIdx.x] = incl;
}

// merged scan finalize: each block redundantly scans g_bsum, applies offset,
// and does all degree init.
__global__ void __launch_bounds__(1024) k_scanfin(int N, int nb) {
    __shared__ int s[64];
    int t = threadIdx.x;
    if (t < 64) s[t] = (t < nb) ? g_bsum[t] : 0;
    __syncthreads();
    for (int off = 1; off < 64; off <<= 1) {
        int a = (t < 64 && t >= off) ? s[t - off] : 0;
        __syncthreads();
        if (t < 64) s[t] += a;
        __syncthreads();
    }
    int boff = s[blockIdx.x] - g_bsum[blockIdx.x];   // exclusive block offset
    int idx = blockIdx.x * 1024 + t;
    if (idx < N) {
        int r = g_rowptr[idx] + boff;
        g_rowptr[idx] = r;
        g_cursor[idx] = r;
        g_degu[idx] = rsqrtf((float)g_cnt2[MAXN + idx] + 1.f);
        g_degc[idx] = 1.f;
        g_dego[idx] = 1.f;
    }
    if (blockIdx.x == 0 && t == 0) g_rowptr[N] = s[63];
}

__global__ void k_fillcsr(const int* __restrict__ row, const int* __restrict__ col, int E) {
    int e = blockIdx.x * blockDim.x + threadIdx.x;
    if (e >= E) return;
    int c = col[e];
    int p = atomicAdd(&g_cursor[c], 1);
    g_er[p] = row[e];
    g_ee[p] = e;
}

// ---------------- CSR gathers: half-warp edge pairing ---------------------------
__global__ void __launch_bounds__(256) k_gather(const __half* __restrict__ lin,
                                                float* __restrict__ out,
                                                const float* __restrict__ dinv,
                                                const float* __restrict__ b, int N,
                                                float* __restrict__ sS,
                                                float* __restrict__ sQ) {
    __shared__ float ssum[HD], ssq[HD];
    int t = threadIdx.x;
    if (t < HD) { ssum[t] = 0.f; ssq[t] = 0.f; }
    __syncthreads();
    int lane = t & 31, hw = lane >> 4, hl = lane & 15;
    int warpId = (blockIdx.x * blockDim.x + t) >> 5;
    int nW = (blockDim.x * gridDim.x) >> 5;
    float4 bb0 = ((const float4*)b)[hl * 2 + 0];
    float4 bb1 = ((const float4*)b)[hl * 2 + 1];
    float st[8] = {0,0,0,0,0,0,0,0}, qt[8] = {0,0,0,0,0,0,0,0};
    for (int i = warpId; i < N; i += nW) {
        int start = g_rowptr[i], end = g_rowptr[i + 1];
        float di = dinv[i];
        float a[8] = {0,0,0,0,0,0,0,0};
        if (hw == 0) {
            uint4 u = __ldg((const uint4*)(lin + (size_t)i * HD) + hl);
            fma8(a, u, di * di);
        }
        int j0 = start;
        for (; j0 + 32 <= end; j0 += 32) {
            int r = g_er[j0 + lane];
            float dr = dinv[r];
#pragma unroll
            for (int k = 0; k < 16; k++) {
                int src = 2 * k + hw;
                int   rr = __shfl_sync(0xffffffffu, r, src);
                float nn = __shfl_sync(0xffffffffu, dr, src) * di;
                uint4 u = __ldg((const uint4*)(lin + (size_t)rr * HD) + hl);
                fma8(a, u, nn);
            }
        }
        if (j0 < end) {
            int cnt = end - j0;
            int r = 0; float dr = 0.f;
            if (lane < cnt) { r = g_er[j0 + lane]; dr = dinv[r]; }
            int pairs = (cnt + 1) >> 1;
            for (int k = 0; k < pairs; k++) {
                int src = 2 * k + hw;
                int   rr = __shfl_sync(0xffffffffu, r, src);
                float nn = __shfl_sync(0xffffffffu, dr, src) * di;
                if (src < cnt) {
                    uint4 u = __ldg((const uint4*)(lin + (size_t)rr * HD) + hl);
                    fma8(a, u, nn);
                }
            }
        }
#pragma unroll
        for (int j = 0; j < 8; j++)
            a[j] += __shfl_xor_sync(0xffffffffu, a[j], 16);
        if (hw == 0) {
            a[0] = fmaxf(a[0] + bb0.x, 0.f); a[1] = fmaxf(a[1] + bb0.y, 0.f);
            a[2] = fmaxf(a[2] + bb0.z, 0.f); a[3] = fmaxf(a[3] + bb0.w, 0.f);
            a[4] = fmaxf(a[4] + bb1.x, 0.f); a[5] = fmaxf(a[5] + bb1.y, 0.f);
            a[6] = fmaxf(a[6] + bb1.z, 0.f); a[7] = fmaxf(a[7] + bb1.w, 0.f);
            float4* o = (float4*)(out + (size_t)i * HD) + hl * 2;
            o[0] = make_float4(a[0], a[1], a[2], a[3]);
            o[1] = make_float4(a[4], a[5], a[6], a[7]);
#pragma unroll
            for (int j = 0; j < 8; j++) { st[j] += a[j]; qt[j] += a[j] * a[j]; }
        }
    }
    if (sS) {
        if (hw == 0) {
#pragma unroll
            for (int j = 0; j < 8; j++) {
                atomicAdd(&ssum[hl * 8 + j], st[j]);
                atomicAdd(&ssq[hl * 8 + j],  qt[j]);
            }
        }
        __syncthreads();
        if (t < HD) { atomicAdd(&sS[t], ssum[t]); atomicAdd(&sQ[t], ssq[t]); }
    }
}

__global__ void __launch_bounds__(256) k_gather2(const __half* __restrict__ linC,
                                                 const __half* __restrict__ linO,
                                                 float* __restrict__ outC,
                                                 float* __restrict__ outO,
                                                 const float* __restrict__ dc,
                                                 const float* __restrict__ dd,
                                                 const float* __restrict__ bc,
                                                 const float* __restrict__ bo, int N,
                                                 float* sSc, float* sQc,
                                                 float* sSo, float* sQo) {
    __shared__ float red[4][HD];
    int t = threadIdx.x;
    for (int i = t; i < 4 * HD; i += blockDim.x) ((float*)red)[i] = 0.f;
    __syncthreads();
    int lane = t & 31, hw = lane >> 4, hl = lane & 15;
    int warpId = (blockIdx.x * blockDim.x + t) >> 5;
    int nW = (blockDim.x * gridDim.x) >> 5;
    float4 bc0 = ((const float4*)bc)[hl * 2 + 0];
    float4 bc1 = ((const float4*)bc)[hl * 2 + 1];
    float4 bo0 = ((const float4*)bo)[hl * 2 + 0];
    float4 bo1 = ((const float4*)bo)[hl * 2 + 1];
    float stc[8] = {0,0,0,0,0,0,0,0}, qtc[8] = {0,0,0,0,0,0,0,0};
    float sto[8] = {0,0,0,0,0,0,0,0}, qto[8] = {0,0,0,0,0,0,0,0};
    for (int i = warpId; i < N; i += nW) {
        int start = g_rowptr[i], end = g_rowptr[i + 1];
        float dci = rsqrtf(dc[i]), doi = rsqrtf(dd[i]);
        float aC[8] = {0,0,0,0,0,0,0,0}, aO[8] = {0,0,0,0,0,0,0,0};
        if (hw == 0) {
            uint4 u = __ldg((const uint4*)(linC + (size_t)i * HD) + hl);
            fma8(aC, u, dci * dci);
        } else {
            uint4 u = __ldg((const uint4*)(linO + (size_t)i * HD) + hl);
            fma8(aO, u, doi * doi);
        }
        int j0 = start;
        for (; j0 + 32 <= end; j0 += 32) {
            int jj = j0 + lane;
            int r = g_er[jj];
            int e = g_ee[jj];
            float wc = rsqrtf(dc[r]) * g_att0[e];
            float wo = rsqrtf(dd[r]) * g_att1[e];
#pragma unroll
            for (int k = 0; k < 16; k++) {
                int src = 2 * k + hw;
                int   rr = __shfl_sync(0xffffffffu, r, src);
                float nc = __shfl_sync(0xffffffffu, wc, src) * dci;
                float no = __shfl_sync(0xffffffffu, wo, src) * doi;
                uint4 uC = __ldg((const uint4*)(linC + (size_t)rr * HD) + hl);
                uint4 uO = __ldg((const uint4*)(linO + (size_t)rr * HD) + hl);
                fma8(aC, uC, nc);
                fma8(aO, uO, no);
            }
        }
        if (j0 < end) {
            int cnt = end - j0;
            int r = 0; float wc = 0.f, wo = 0.f;
            if (lane < cnt) {
                int jj = j0 + lane;
                r = g_er[jj];
                int e = g_ee[jj];
                wc = rsqrtf(dc[r]) * g_att0[e];
                wo = rsqrtf(dd[r]) * g_att1[e];
            }
            int pairs = (cnt + 1) >> 1;
            for (int k = 0; k < pairs; k++) {
                int src = 2 * k + hw;
                int   rr = __shfl_sync(0xffffffffu, r, src);
                float nc = __shfl_sync(0xffffffffu, wc, src) * dci;
                float no = __shfl_sync(0xffffffffu, wo, src) * doi;
                if (src < cnt) {
                    uint4 uC = __ldg((const uint4*)(linC + (size_t)rr * HD) + hl);
                    uint4 uO = __ldg((const uint4*)(linO + (size_t)rr * HD) + hl);
                    fma8(aC, uC, nc);
                    fma8(aO, uO, no);
                }
            }
        }
#pragma unroll
        for (int j = 0; j < 8; j++) {
            aC[j] += __shfl_xor_sync(0xffffffffu, aC[j], 16);
            aO[j] += __shfl_xor_sync(0xffffffffu, aO[j], 16);
        }
        if (hw == 0) {
            aC[0] = fmaxf(aC[0] + bc0.x, 0.f); aC[1] = fmaxf(aC[1] + bc0.y, 0.f);
            aC[2] = fmaxf(aC[2] + bc0.z, 0.f); aC[3] = fmaxf(aC[3] + bc0.w, 0.f);
            aC[4] = fmaxf(aC[4] + bc1.x, 0.f); aC[5] = fmaxf(aC[5] + bc1.y, 0.f);
            aC[6] = fmaxf(aC[6] + bc1.z, 0.f); aC[7] = fmaxf(aC[7] + bc1.w, 0.f);
            aO[0] = fmaxf(aO[0] + bo0.x, 0.f); aO[1] = fmaxf(aO[1] + bo0.y, 0.f);
            aO[2] = fmaxf(aO[2] + bo0.z, 0.f); aO[3] = fmaxf(aO[3] + bo0.w, 0.f);
            aO[4] = fmaxf(aO[4] + bo1.x, 0.f); aO[5] = fmaxf(aO[5] + bo1.y, 0.f);
            aO[6] = fmaxf(aO[6] + bo1.z, 0.f); aO[7] = fmaxf(aO[7] + bo1.w, 0.f);
            float4* oc = (float4*)(outC + (size_t)i * HD) + hl * 2;
            float4* oo = (float4*)(outO + (size_t)i * HD) + hl * 2;
            oc[0] = make_float4(aC[0], aC[1], aC[2], aC[3]);
            oc[1] = make_float4(aC[4], aC[5], aC[6], aC[7]);
            oo[0] = make_float4(aO[0], aO[1], aO[2], aO[3]);
            oo[1] = make_float4(aO[4], aO[5], aO[6], aO[7]);
#pragma unroll
            for (int j = 0; j < 8; j++) {
                stc[j] += aC[j]; qtc[j] += aC[j] * aC[j];
                sto[j] += aO[j]; qto[j] += aO[j] * aO[j];
            }
        }
    }
    if (hw == 0) {
#pragma unroll
        for (int j = 0; j < 8; j++) {
            atomicAdd(&red[0][hl * 8 + j], stc[j]);
            atomicAdd(&red[1][hl * 8 + j], qtc[j]);
            atomicAdd(&red[2][hl * 8 + j], sto[j]);
            atomicAdd(&red[3][hl * 8 + j], qto[j]);
        }
    }
    __syncthreads();
    if (t < HD) {
        atomicAdd(&sSc[t], red[0][t]); atomicAdd(&sQc[t], red[1][t]);
        atomicAdd(&sSo[t], red[2][t]); atomicAdd(&sQo[t], red[3][t]);
    }
}

// ---------------- attention --------------------------------------------------------
__global__ void k_att_node(const float* __restrict__ h,
                           const float* __restrict__ Wna, const float* __restrict__ bna,
                           const float* __restrict__ Wea,
                           float* __restrict__ xc, float* __restrict__ xo, int N,
                           float* sSc, float* sQc, float* sSo, float* sQo) {
    __shared__ float Wc[HD * 6];
    __shared__ float red[4][HD];
    int t = threadIdx.x;
    for (int i = t; i < HD * 6; i += blockDim.x) {
        int k = i / 6, j = i % 6;
        float v;
        if (j < 2)      v = Wna[k * 2 + j];
        else if (j < 4) v = Wea[k * 2 + (j - 2)];
        else            v = Wea[(HD + k) * 2 + (j - 4)];
        Wc[i] = v;
    }
    for (int i = t; i < 4 * HD; i += blockDim.x) ((float*)red)[i] = 0.f;
    __syncthreads();
    int warps = (blockDim.x * gridDim.x) >> 5;
    int gw = (blockIdx.x * blockDim.x + t) >> 5;
    int l  = t & 31;
    float b0 = bna[0], b1 = bna[1];
    float sc[4]={0,0,0,0}, qc[4]={0,0,0,0}, so[4]={0,0,0,0}, qo[4]={0,0,0,0};
    for (int i = gw; i < N; i += warps) {
        float4 hv = ((const float4*)h)[(size_t)i * HD4 + l];
        float p[6];
#pragma unroll
        for (int j = 0; j < 6; j++) {
            p[j] = hv.x * Wc[(4*l+0)*6 + j] + hv.y * Wc[(4*l+1)*6 + j]
                 + hv.z * Wc[(4*l+2)*6 + j] + hv.w * Wc[(4*l+3)*6 + j];
        }
#pragma unroll
        for (int off = 16; off; off >>= 1)
#pragma unroll
            for (int j = 0; j < 6; j++)
                p[j] += __shfl_xor_sync(0xffffffffu, p[j], off);
        float l0 = p[0] + b0, l1 = p[1] + b1;
        float m  = fmaxf(l0, l1);
        float e0 = expf(l0 - m), e1 = expf(l1 - m);
        float inv = 1.f / (e0 + e1);
        float a0 = e0 * inv, a1 = e1 * inv;
        float4 vc = make_float4(hv.x*a0, hv.y*a0, hv.z*a0, hv.w*a0);
        float4 vo = make_float4(hv.x*a1, hv.y*a1, hv.z*a1, hv.w*a1);
        ((float4*)xc)[(size_t)i * HD4 + l] = vc;
        ((float4*)xo)[(size_t)i * HD4 + l] = vo;
        sc[0]+=vc.x; qc[0]+=vc.x*vc.x; sc[1]+=vc.y; qc[1]+=vc.y*vc.y;
        sc[2]+=vc.z; qc[2]+=vc.z*vc.z; sc[3]+=vc.w; qc[3]+=vc.w*vc.w;
        so[0]+=vo.x; qo[0]+=vo.x*vo.x; so[1]+=vo.y; qo[1]+=vo.y*vo.y;
        so[2]+=vo.z; qo[2]+=vo.z*vo.z; so[3]+=vo.w; qo[3]+=vo.w*vo.w;
        if (l == 0) g_eanode[i] = make_float4(p[2], p[3], p[4], p[5]);
    }
#pragma unroll
    for (int j = 0; j < 4; j++) {
        atomicAdd(&red[0][l*4+j], sc[j]);
        atomicAdd(&red[1][l*4+j], qc[j]);
        atomicAdd(&red[2][l*4+j], so[j]);
        atomicAdd(&red[3][l*4+j], qo[j]);
    }
    __syncthreads();
    if (t < HD) {
        atomicAdd(&sSc[t], red[0][t]); atomicAdd(&sQc[t], red[1][t]);
        atomicAdd(&sSo[t], red[2][t]); atomicAdd(&sQo[t], red[3][t]);
    }
}

__global__ void k_att_edge(const int* __restrict__ row, const int* __restrict__ col,
                           const float* __restrict__ bea, int E) {
    int e = blockIdx.x * blockDim.x + threadIdx.x;
    if (e >= E) return;
    int r = row[e], c = col[e];
    float4 tr = g_eanode[r], tc = g_eanode[c];
    float l0 = tr.x + tc.z + bea[0];
    float l1 = tr.y + tc.w + bea[1];
    float m  = fmaxf(l0, l1);
    float e0 = expf(l0 - m), e1 = expf(l1 - m);
    float inv = 1.f / (e0 + e1);
    float a0 = e0 * inv, a1 = e1 * inv;
    g_att0[e] = a0; g_att1[e] = a1;
    atomicAdd(&g_degc[r], a0);
    atomicAdd(&g_dego[r], a1);
}

__global__ void k_permadd_stats(const float* __restrict__ xc, const float* __restrict__ xo,
                                const int* __restrict__ perm, float* __restrict__ z, int N,
                                float* __restrict__ sS, float* __restrict__ sQ) {
    __shared__ float ssum[HD], ssq[HD];
    int t = threadIdx.x;
    if (t < HD) { ssum[t] = 0.f; ssq[t] = 0.f; }
    __syncthreads();
    int total  = N * HD4;
    int stride = blockDim.x * gridDim.x;
    int idx    = blockIdx.x * blockDim.x + t;
    int fb     = (idx & 31) * 4;
    float a0=0,a1=0,a2=0,a3=0,q0=0,q1=0,q2=0,q3=0;
    for (; idx < total; idx += stride) {
        int i = idx >> 5, l = idx & 31;
        int p = perm[i];
        float4 a = ((const float4*)xc)[(size_t)p * HD4 + l];
        float4 b = ((const float4*)xo)[idx];
        a.x += b.x; a.y += b.y; a.z += b.z; a.w += b.w;
        ((float4*)z)[idx] = a;
        a0 += a.x; q0 += a.x*a.x; a1 += a.y; q1 += a.y*a.y;
        a2 += a.z; q2 += a.z*a.z; a3 += a.w; q3 += a.w*a.w;
    }
    atomicAdd(&ssum[fb+0], a0); atomicAdd(&ssq[fb+0], q0);
    atomicAdd(&ssum[fb+1], a1); atomicAdd(&ssq[fb+1], q1);
    atomicAdd(&ssum[fb+2], a2); atomicAdd(&ssq[fb+2], q2);
    atomicAdd(&ssum[fb+3], a3); atomicAdd(&ssq[fb+3], q3);
    __syncthreads();
    if (t < HD) { atomicAdd(&sS[t], ssum[t]); atomicAdd(&sQ[t], ssq[t]); }
}

// ---------------- [N,128]x[128,10] + log_softmax, inline fold, batched ----------
__global__ void k_gemm2_lsm(LJobs jobs, int N, float invN) {
    __shared__ float Ws[HD * 10];
    __shared__ float bs[10];
    __shared__ float scaleSh[HD], tshSh[HD];
    const LJob J = jobs.j[blockIdx.y];
    int t = threadIdx.x;
    if (t < HD) {
        float mu  = J.sSin[t] * invN;
        float var = fmaxf(J.sQin[t] * invN - mu * mu, 0.f);
        float rs  = rsqrtf(var + 1e-5f);
        scaleSh[t] = rs;
        tshSh[t]   = 1e-4f / rs - mu;
    }
    __syncthreads();
    for (int i = t; i < HD * 10; i += blockDim.x)
        Ws[i] = scaleSh[i / 10] * J.W[i];
    __syncthreads();
    if (t < 160) {
        int j = t / 16, seg = t % 16;
        float part = 0.f;
#pragma unroll
        for (int k = 0; k < 8; k++) {
            int kk = seg * 8 + k;
            part += tshSh[kk] * Ws[kk * 10 + j];
        }
#pragma unroll
        for (int off = 8; off; off >>= 1)
            part += __shfl_down_sync(0xffffffffu, part, off, 16);
        if (seg == 0) bs[j] = J.b[j] + part;
    }
    __syncthreads();
    int warps = (blockDim.x * gridDim.x) >> 5;
    int gw = (blockIdx.x * blockDim.x + t) >> 5;
    int l  = t & 31;
    for (int i = gw; i < N; i += warps) {
        float4 z = ((const float4*)J.Z)[(size_t)i * HD4 + l];
        float p[10];
#pragma unroll
        for (int j = 0; j < 10; j++) {
            p[j] = z.x * Ws[(4*l+0)*10 + j] + z.y * Ws[(4*l+1)*10 + j]
                 + z.z * Ws[(4*l+2)*10 + j] + z.w * Ws[(4*l+3)*10 + j];
        }
#pragma unroll
        for (int off = 16; off; off >>= 1)
#pragma unroll
            for (int j = 0; j < 10; j++)
                p[j] += __shfl_xor_sync(0xffffffffu, p[j], off);
        float m = -1e30f;
#pragma unroll
        for (int j = 0; j < 10; j++) { p[j] += bs[j]; m = fmaxf(m, p[j]); }
        float s = 0.f;
#pragma unroll
        for (int j = 0; j < 10; j++) s += expf(p[j] - m);
        float lse = m + logf(s);
        if (l < 10) J.out[(size_t)i * 10 + l] = p[l] - lse;
    }
}

// ---------------- host orchestration ------------------------------------------------
extern "C" void kernel_launch(void* const* d_in, const int* in_sizes, int n_in,
                              void* d_out, int out_size) {
    const float* x      = (const float*)d_in[0];
    const int*   ei     = (const int*)  d_in[1];
    const int*   perm   = (const int*)  d_in[2];
    const float* W_feat = (const float*)d_in[3];
    const float* b_feat = (const float*)d_in[4];
    const float* W_convs= (const float*)d_in[5];
    const float* b_convs= (const float*)d_in[6];
    const float* W_ea   = (const float*)d_in[7];
    const float* b_ea   = (const float*)d_in[8];
    const float* W_na   = (const float*)d_in[9];
    const float* b_na   = (const float*)d_in[10];
    const float* W_ctx  = (const float*)d_in[11];
    const float* b_ctx  = (const float*)d_in[12];
    const float* W_obj  = (const float*)d_in[13];
    const float* b_obj  = (const float*)d_in[14];
    const float* W_fc1  = (const float*)d_in[15];
    const float* b_fc1  = (const float*)d_in[16];
    const float* W_fc2  = (const float*)d_in[17];
    const float* b_fc2  = (const float*)d_in[18];

    int N = in_sizes[0] / HD;
    int E = in_sizes[1] / 2;
    const int* row = ei;
    const int* col = ei + E;
    float* out = (float*)d_out;

    // one-time side stream + events (created on first (non-capture) call)
    static cudaStream_t sB = nullptr;
    static cudaEvent_t ev0, evCSR, ev1, evAE;
    if (!sB) {
        cudaStreamCreateWithFlags(&sB, cudaStreamNonBlocking);
        cudaEventCreateWithFlags(&ev0,   cudaEventDisableTiming);
        cudaEventCreateWithFlags(&evCSR, cudaEventDisableTiming);
        cudaEventCreateWithFlags(&ev1,   cudaEventDisableTiming);
        cudaEventCreateWithFlags(&evAE,  cudaEventDisableTiming);
    }

    float* Bbase = nullptr;
    cudaGetSymbolAddress((void**)&Bbase, g_B);
    float* B0 = Bbase + 0 * (size_t)MAXN * HD;
    float* B1 = Bbase + 1 * (size_t)MAXN * HD;
    float* B2 = Bbase + 2 * (size_t)MAXN * HD;
    float* B3 = Bbase + 3 * (size_t)MAXN * HD;
    float* B4 = Bbase + 4 * (size_t)MAXN * HD;
    float* B5 = Bbase + 5 * (size_t)MAXN * HD;
    __half* H1 = (__half*)B1;
    __half* H5 = (__half*)B5;
    float *degup, *degcp, *degop, *statsp;
    int *cnt2p;
    cudaGetSymbolAddress((void**)&degup,  g_degu);
    cudaGetSymbolAddress((void**)&degcp,  g_degc);
    cudaGetSymbolAddress((void**)&degop,  g_dego);
    cudaGetSymbolAddress((void**)&statsp, g_stats);
    cudaGetSymbolAddress((void**)&cnt2p,  g_cnt2);
    auto S = [&](int i) { return statsp + i * HD; };
    auto Q = [&](int i) { return statsp + (NSLOT + i) * HD; };

    const int gemm_smem = 2 * 128 * AS * (int)sizeof(__half);
    cudaFuncSetAttribute(k_gemm_tc, cudaFuncAttributeMaxDynamicSharedMemorySize, gemm_smem);

    int gbGemm = (N + 127) / 128;
    int gbE    = (E + 255) / 256;
    int nb     = (N + 1023) / 1024;
    float invN = 1.f / (float)N;

    auto gemm1 = [&](const float* X, float* Y, const float* W, const float* b,
                     int sin, int sout, int relu, int outHalf) {
        GJobs js{};
        js.j[0] = {X, Y, W, b, S(sin), Q(sin),
                   sout >= 0 ? S(sout) : nullptr, sout >= 0 ? Q(sout) : nullptr};
        k_gemm_tc<<<dim3(gbGemm, 1), 512, gemm_smem>>>(js, N, relu, outHalf, invN);
    };

    // ---- fork: CSR build on side stream, stats+GEMM0+conv1-GEMM on main ----
    cudaEventRecord(ev0, 0);
    cudaStreamWaitEvent(sB, ev0, 0);

    cudaMemsetAsync(cnt2p, 0, 2 * (size_t)MAXN * sizeof(int), sB);
    k_hist<<<gbE, 256, 0, sB>>>(row, col, E);
    k_scan1<<<nb, 1024, 0, sB>>>(N);
    k_scanfin<<<nb, 1024, 0, sB>>>(N, nb);
    k_fillcsr<<<gbE, 256, 0, sB>>>(row, col, E);
    cudaEventRecord(evCSR, sB);

    // main: zero stats slots, stats(x), gemm0, conv1 gemm
    cudaMemsetAsync(statsp, 0, 2 * NSLOT * HD * sizeof(float), 0);
    k_stats<<<512, 256>>>(x, N, S(0), Q(0));
    gemm1(x, B2, W_feat, b_feat, 0, 1, 1, 0);
    gemm1(B2, (float*)H1, W_convs + 0 * HD * HD, nullptr, 1, -1, 0, 1);

    // join: CSR needed from here on
    cudaStreamWaitEvent(0, evCSR, 0);
    k_gather<<<1024, 256>>>(H1, B0, degup, b_convs + 0 * HD, N, S(2), Q(2));
    // conv2: B0 -> B2
    gemm1(B0, (float*)H1, W_convs + 1 * HD * HD, nullptr, 2, -1, 0, 1);
    k_gather<<<1024, 256>>>(H1, B2, degup, b_convs + 1 * HD, N, S(3), Q(3));
    // conv3: B2 -> B0
    gemm1(B2, (float*)H1, W_convs + 2 * HD * HD, nullptr, 3, -1, 0, 1);
    k_gather<<<1024, 256>>>(H1, B0, degup, b_convs + 2 * HD, N, nullptr, nullptr);

    // attention node projections
    k_att_node<<<256, 256>>>(B0, W_na, b_na, W_ea, B2, B3, N, S(4), Q(4), S(5), Q(5));

    // fork: att_edge on side stream, ctx/obj GEMM pair on main
    cudaEventRecord(ev1, 0);
    cudaStreamWaitEvent(sB, ev1, 0);
    k_att_edge<<<gbE, 256, 0, sB>>>(row, col, b_ea, E);
    cudaEventRecord(evAE, sB);

    {
        GJobs js{};
        js.j[0] = {B2, (float*)H1, W_ctx, nullptr, S(4), Q(4), nullptr, nullptr};
        js.j[1] = {B3, (float*)H5, W_obj, nullptr, S(5), Q(5), nullptr, nullptr};
        k_gemm_tc<<<dim3(gbGemm, 2), 512, gemm_smem>>>(js, N, 0, 1, invN);
    }
    cudaStreamWaitEvent(0, evAE, 0);
    // merged weighted gather (rsqrt inline): xc2=B4 (s6), xo2=B3 (s7)
    k_gather2<<<1024, 256>>>(H1, H5, B4, B3, degcp, degop, b_ctx, b_obj, N,
                             S(6), Q(6), S(7), Q(7));

    // permadd: z = B4[perm] + B3 -> B1 (s11)
    k_permadd_stats<<<256, 256>>>(B4, B3, perm, B1, N, S(11), Q(11));

    // batched readout fc1
    {
        GJobs js{};
        js.j[0] = {B4, B0, W_fc1 + 0 * HD * HD, b_fc1 + 0 * HD, S(6),  Q(6),  S(8),  Q(8)};
        js.j[1] = {B3, B5, W_fc1 + 1 * HD * HD, b_fc1 + 1 * HD, S(7),  Q(7),  S(9),  Q(9)};
        js.j[2] = {B1, B2, W_fc1 + 2 * HD * HD, b_fc1 + 2 * HD, S(11), Q(11), S(10), Q(10)};
        k_gemm_tc<<<dim3(gbGemm, 3), 512, gemm_smem>>>(js, N, 1, 0, invN);
    }
    // batched lsm
    {
        LJobs js{};
        js.j[0] = {B0, out,                      W_fc2 + 0 * HD * 10, b_fc2 + 0 * 10, S(8),  Q(8)};
        js.j[1] = {B5, out + (size_t)N * 10,     W_fc2 + 1 * HD * 10, b_fc2 + 1 * 10, S(9),  Q(9)};
        js.j[2] = {B2, out + (size_t)2 * N * 10, W_fc2 + 2 * HD * 10, b_fc2 + 2 * 10, S(10), Q(10)};
        k_gemm2_lsm<<<dim3(512, 3), 256>>>(js, N, invN);
    }
}

// round 9
// speedup vs baseline: 4.0247x; 1.0416x over previous
#include <cuda_runtime.h>
#include <cuda_fp16.h>

#define HD   128
#define HD4  32
#define MAXN 50000
#define MAXE 800000
#define AS   136   // smem stride in halves
#define BS   136
#define NSLOT 12

// ---------------- scratch ------------------------------------------------------
static __device__ float  g_B[6][(size_t)MAXN * HD];   // viewed as __half buffers
static __device__ float4 g_eanode[MAXN];
static __device__ float  g_att0[MAXE];
static __device__ float  g_att1[MAXE];
static __device__ float  g_degu[MAXN];
static __device__ float  g_degc[MAXN];
static __device__ float  g_dego[MAXN];
static __device__ float  g_stats[2 * NSLOT * HD];
// CSR
static __device__ int    g_cnt2[2 * MAXN];
static __device__ int    g_rowptr[MAXN + 1];
static __device__ int    g_cursor[MAXN];
static __device__ int    g_er[MAXE];
static __device__ int    g_ee[MAXE];
static __device__ int    g_bsum[64];

struct GJob {
    const void* X; __half* Y; const float* W; const float* b;
    const float* sSin; const float* sQin; float* sSout; float* sQout;
};
struct GJobs { GJob j[3]; };
struct LJob {
    const __half* Z; float* out; const float* W; const float* b;
    const float* sSin; const float* sQin;
};
struct LJobs { LJob j[3]; };

__device__ __forceinline__ unsigned s2u(const void* p) {
    return (unsigned)__cvta_generic_to_shared(p);
}
__device__ __forceinline__ void ldsm_x4(unsigned* a, unsigned addr) {
    asm volatile("ldmatrix.sync.aligned.m8n8.x4.shared.b16 {%0,%1,%2,%3}, [%4];"
                 : "=r"(a[0]), "=r"(a[1]), "=r"(a[2]), "=r"(a[3]) : "r"(addr));
}
__device__ __forceinline__ void ldsm_x2t(unsigned* b, unsigned addr) {
    asm volatile("ldmatrix.sync.aligned.m8n8.x2.trans.shared.b16 {%0,%1}, [%2];"
                 : "=r"(b[0]), "=r"(b[1]) : "r"(addr));
}
__device__ __forceinline__ void mma_f16(float* c, const unsigned* a, const unsigned* b) {
    asm volatile(
        "mma.sync.aligned.m16n8k16.row.col.f32.f16.f16.f32 "
        "{%0,%1,%2,%3}, {%4,%5,%6,%7}, {%8,%9}, {%0,%1,%2,%3};"
        : "+f"(c[0]), "+f"(c[1]), "+f"(c[2]), "+f"(c[3])
        : "r"(a[0]), "r"(a[1]), "r"(a[2]), "r"(a[3]), "r"(b[0]), "r"(b[1]));
}
__device__ __forceinline__ void fma8(float* a, uint4 u, float nn) {
    __half2* h = (__half2*)&u;
#pragma unroll
    for (int j = 0; j < 4; j++) {
        float2 f = __half22float2(h[j]);
        a[2*j]   += f.x * nn;
        a[2*j+1] += f.y * nn;
    }
}
__device__ __forceinline__ uint2 pack4(float a, float b, float c, float d) {
    __half2 h0 = __floats2half2_rn(a, b), h1 = __floats2half2_rn(c, d);
    uint2 r; r.x = *(unsigned*)&h0; r.y = *(unsigned*)&h1; return r;
}
__device__ __forceinline__ float4 unpack4(uint2 u) {
    float2 f0 = __half22float2(*(__half2*)&u.x);
    float2 f1 = __half22float2(*(__half2*)&u.y);
    return make_float4(f0.x, f0.y, f1.x, f1.y);
}

// ---------------- stats on fp32 input x ------------------------------------------
__global__ void k_stats(const float* __restrict__ X, int N,
                        float* __restrict__ sS, float* __restrict__ sQ) {
    __shared__ float ss[HD], sq[HD];
    int t = threadIdx.x;
    if (t < HD) { ss[t] = 0.f; sq[t] = 0.f; }
    __syncthreads();
    int total  = N * HD4;
    int stride = blockDim.x * gridDim.x;
    int idx    = blockIdx.x * blockDim.x + t;
    int fb     = (idx & 31) * 4;
    float a0=0,a1=0,a2=0,a3=0,q0=0,q1=0,q2=0,q3=0;
    for (; idx < total; idx += stride) {
        float4 v = ((const float4*)X)[idx];
        a0 += v.x; q0 += v.x * v.x;
        a1 += v.y; q1 += v.y * v.y;
        a2 += v.z; q2 += v.z * v.z;
        a3 += v.w; q3 += v.w * v.w;
    }
    atomicAdd(&ss[fb+0], a0); atomicAdd(&sq[fb+0], q0);
    atomicAdd(&ss[fb+1], a1); atomicAdd(&sq[fb+1], q1);
    atomicAdd(&ss[fb+2], a2); atomicAdd(&sq[fb+2], q2);
    atomicAdd(&ss[fb+3], a3); atomicAdd(&sq[fb+3], q3);
    __syncthreads();
    if (t < HD) { atomicAdd(&sS[t], ss[t]); atomicAdd(&sQ[t], sq[t]); }
}

// ---------------- fp16 tensor-core GEMM, inline BN fold, batched, fp16 I/O -------
__global__ void __launch_bounds__(512) k_gemm_tc(GJobs jobs, int N, int doRelu,
                                                 int inHalf, float invN) {
    extern __shared__ __half sh[];
    __half* Ah = sh;
    __half* Bh = sh + 128 * AS;
    __shared__ float ssum[HD], ssq[HD], scaleSh[HD], tshSh[HD], biasSh[HD];
    __shared__ float bpart[4][HD];
    const GJob J = jobs.j[blockIdx.y];
    int t = threadIdx.x;
    if (t < HD) {
        ssum[t] = 0.f; ssq[t] = 0.f;
        float mu  = J.sSin[t] * invN;
        float var = fmaxf(J.sQin[t] * invN - mu * mu, 0.f);
        float rs  = rsqrtf(var + 1e-5f);
        scaleSh[t] = rs;
        tshSh[t]   = 1e-4f / rs - mu;
        biasSh[t]  = J.b ? J.b[t] : 0.f;
    }
    __syncthreads();
    int base = blockIdx.x * 128;
    if (inHalf) {
        const __half* Xh = (const __half*)J.X;
#pragma unroll
        for (int i = t; i < 2048; i += 512) {      // 128 rows x 16 uint4 (8 halves)
            int r = i >> 4, c = i & 15, gr = base + r;
            uint4 v = make_uint4(0u, 0u, 0u, 0u);
            if (gr < N) v = ((const uint4*)Xh)[(size_t)gr * 16 + c];
            *(uint4*)&Ah[r * AS + c * 8] = v;
        }
    } else {
        const float* Xf = (const float*)J.X;
#pragma unroll
        for (int i = t; i < 4096; i += 512) {
            int r = i >> 5, c = i & 31, gr = base + r;
            float4 v = make_float4(0.f, 0.f, 0.f, 0.f);
            if (gr < N) v = ((const float4*)Xf)[(size_t)gr * 32 + c];
            __half2* dst = (__half2*)&Ah[r * AS + c * 4];
            dst[0] = __floats2half2_rn(v.x, v.y);
            dst[1] = __floats2half2_rn(v.z, v.w);
        }
    }
#pragma unroll
    for (int i = t; i < 4096; i += 512) {
        int r = i >> 5, c = i & 31;
        float4 v = ((const float4*)J.W)[i];
        float s = scaleSh[r];
        __half2* dst = (__half2*)&Bh[r * BS + c * 4];
        dst[0] = __floats2half2_rn(v.x * s, v.y * s);
        dst[1] = __floats2half2_rn(v.z * s, v.w * s);
    }
    __syncthreads();

    {
        int j = t & 127, q = t >> 7;
        float part = 0.f;
        int k0 = q * 32;
#pragma unroll
        for (int k = 0; k < 32; k++)
            part += tshSh[k0 + k] * __half2float(Bh[(k0 + k) * BS + j]);
        bpart[q][j] = part;
    }
    __syncthreads();
    if (t < HD) biasSh[t] += bpart[0][t] + bpart[1][t] + bpart[2][t] + bpart[3][t];
    __syncthreads();

    int lane = t & 31, g = lane >> 2, tg = lane & 3, w = t >> 5;
    int rwb = (w & 3) * 32;
    int cwb = (w >> 2) * 32;

    int m8 = lane >> 3, lr = lane & 7;
    int arowOff = (m8 & 1) * 8 + lr;
    int acolOff = (m8 >> 1) * 8;
    unsigned aBase = s2u(Ah);
    unsigned bBase = s2u(Bh);
    int bk = lane & 15;

    float acc[2][4][4];
#pragma unroll
    for (int m = 0; m < 2; m++)
#pragma unroll
        for (int nt = 0; nt < 4; nt++)
#pragma unroll
            for (int j = 0; j < 4; j++) acc[m][nt][j] = 0.f;

    unsigned aA[8], bA[8], aB[8], bB[8];

#define LDFRAG(K0, AA, BB)                                                      \
    {                                                                           \
        _Pragma("unroll")                                                       \
        for (int m = 0; m < 2; m++) {                                           \
            int arow = rwb + m * 16 + arowOff;                                  \
            ldsm_x4(AA + m * 4, aBase + (arow * AS + (K0) + acolOff) * 2);      \
        }                                                                       \
        _Pragma("unroll")                                                       \
        for (int nt = 0; nt < 4; nt++) {                                        \
            ldsm_x2t(BB + nt * 2, bBase + (((K0) + bk) * BS + cwb + nt * 8) * 2);\
        }                                                                       \
    }

    LDFRAG(0, aA, bA);
#pragma unroll
    for (int ks = 0; ks < 8; ks += 2) {
        if (ks + 1 < 8) LDFRAG((ks + 1) * 16, aB, bB);
#pragma unroll
        for (int m = 0; m < 2; m++)
#pragma unroll
            for (int nt = 0; nt < 4; nt++)
                mma_f16(acc[m][nt], aA + m * 4, bA + nt * 2);
        if (ks + 2 < 8) LDFRAG((ks + 2) * 16, aA, bA);
#pragma unroll
        for (int m = 0; m < 2; m++)
#pragma unroll
            for (int nt = 0; nt < 4; nt++)
                mma_f16(acc[m][nt], aB + m * 4, bB + nt * 2);
    }
#undef LDFRAG

    float ls[4][2], lq[4][2];
#pragma unroll
    for (int nt = 0; nt < 4; nt++) { ls[nt][0]=0.f; ls[nt][1]=0.f; lq[nt][0]=0.f; lq[nt][1]=0.f; }

#pragma unroll
    for (int nt = 0; nt < 4; nt++) {
        int col = cwb + nt * 8 + 2 * tg;
        float bx = biasSh[col], by = biasSh[col + 1];
#pragma unroll
        for (int m = 0; m < 2; m++) {
            int r0 = base + rwb + m * 16 + g;
            int r1 = r0 + 8;
            float y00 = acc[m][nt][0] + bx, y01 = acc[m][nt][1] + by;
            float y10 = acc[m][nt][2] + bx, y11 = acc[m][nt][3] + by;
            if (doRelu) {
                y00 = fmaxf(y00, 0.f); y01 = fmaxf(y01, 0.f);
                y10 = fmaxf(y10, 0.f); y11 = fmaxf(y11, 0.f);
            }
            if (r0 < N) {
                ((__half2*)J.Y)[(size_t)r0 * 64 + (col >> 1)] = __floats2half2_rn(y00, y01);
                ls[nt][0] += y00; lq[nt][0] += y00 * y00;
                ls[nt][1] += y01; lq[nt][1] += y01 * y01;
            }
            if (r1 < N) {
                ((__half2*)J.Y)[(size_t)r1 * 64 + (col >> 1)] = __floats2half2_rn(y10, y11);
                ls[nt][0] += y10; lq[nt][0] += y10 * y10;
                ls[nt][1] += y11; lq[nt][1] += y11 * y11;
            }
        }
    }

    if (J.sSout) {
#pragma unroll
        for (int off = 4; off <= 16; off <<= 1)
#pragma unroll
            for (int nt = 0; nt < 4; nt++)
#pragma unroll
                for (int j = 0; j < 2; j++) {
                    ls[nt][j] += __shfl_xor_sync(0xffffffffu, ls[nt][j], off);
                    lq[nt][j] += __shfl_xor_sync(0xffffffffu, lq[nt][j], off);
                }
        if (g == 0) {
#pragma unroll
            for (int nt = 0; nt < 4; nt++)
#pragma unroll
                for (int j = 0; j < 2; j++) {
                    int col = cwb + nt * 8 + 2 * tg + j;
                    atomicAdd(&ssum[col], ls[nt][j]);
                    atomicAdd(&ssq[col],  lq[nt][j]);
                }
        }
        __syncthreads();
        if (t < HD) { atomicAdd(&J.sSout[t], ssum[t]); atomicAdd(&J.sQout[t], ssq[t]); }
    }
}

// ---------------- CSR build ------------------------------------------------------
__global__ void k_hist(const int* __restrict__ row, const int* __restrict__ col, int E) {
    int e = blockIdx.x * blockDim.x + threadIdx.x;
    if (e < E) {
        atomicAdd(&g_cnt2[col[e]], 1);
        atomicAdd(&g_cnt2[MAXN + row[e]], 1);
    }
}

__global__ void __launch_bounds__(1024) k_scan1(int N) {
    __shared__ int wsum[32];
    int t = threadIdx.x;
    int idx = blockIdx.x * 1024 + t;
    int v = (idx < N) ? g_cnt2[idx] : 0;
    int x = v;
#pragma unroll
    for (int off = 1; off < 32; off <<= 1) {
        int y = __shfl_up_sync(0xffffffffu, x, off);
        if ((t & 31) >= off) x += y;
    }
    if ((t & 31) == 31) wsum[t >> 5] = x;
    __syncthreads();
    if (t < 32) {
        int y = wsum[t];
#pragma unroll
        for (int off = 1; off < 32; off <<= 1) {
            int z = __shfl_up_sync(0xffffffffu, y, off);
            if (t >= off) y += z;
        }
        wsum[t] = y;
    }
    __syncthreads();
    int winc = (t >= 32) ? wsum[(t >> 5) - 1] : 0;
    int incl = x + winc;
    if (idx < N) g_rowptr[idx] = incl - v;
    if (t == 1023) g_bsum[blockIdx.x] = incl;
}

__global__ void __launch_bounds__(1024) k_scanfin(int N, int nb) {
    __shared__ int s[64];
    int t = threadIdx.x;
    if (t < 64) s[t] = (t < nb) ? g_bsum[t] : 0;
    __syncthreads();
    for (int off = 1; off < 64; off <<= 1) {
        int a = (t < 64 && t >= off) ? s[t - off] : 0;
        __syncthreads();
        if (t < 64) s[t] += a;
        __syncthreads();
    }
    int boff = s[blockIdx.x] - g_bsum[blockIdx.x];
    int idx = blockIdx.x * 1024 + t;
    if (idx < N) {
        int r = g_rowptr[idx] + boff;
        g_rowptr[idx] = r;
        g_cursor[idx] = r;
        g_degu[idx] = rsqrtf((float)g_cnt2[MAXN + idx] + 1.f);
        g_degc[idx] = 1.f;
        g_dego[idx] = 1.f;
    }
    if (blockIdx.x == 0 && t == 0) g_rowptr[N] = s[63];
}

__global__ void k_fillcsr(const int* __restrict__ row, const int* __restrict__ col, int E) {
    int e = blockIdx.x * blockDim.x + threadIdx.x;
    if (e >= E) return;
    int c = col[e];
    int p = atomicAdd(&g_cursor[c], 1);
    g_er[p] = row[e];
    g_ee[p] = e;
}

// ---------------- CSR gathers (fp16 in AND out), half-warp edge pairing ---------
__global__ void __launch_bounds__(256) k_gather(const __half* __restrict__ lin,
                                                __half* __restrict__ out,
                                                const float* __restrict__ dinv,
                                                const float* __restrict__ b, int N,
                                                float* __restrict__ sS,
                                                float* __restrict__ sQ) {
    __shared__ float ssum[HD], ssq[HD];
    int t = threadIdx.x;
    if (t < HD) { ssum[t] = 0.f; ssq[t] = 0.f; }
    __syncthreads();
    int lane = t & 31, hw = lane >> 4, hl = lane & 15;
    int warpId = (blockIdx.x * blockDim.x + t) >> 5;
    int nW = (blockDim.x * gridDim.x) >> 5;
    float4 bb0 = ((const float4*)b)[hl * 2 + 0];
    float4 bb1 = ((const float4*)b)[hl * 2 + 1];
    float st[8] = {0,0,0,0,0,0,0,0}, qt[8] = {0,0,0,0,0,0,0,0};
    for (int i = warpId; i < N; i += nW) {
        int start = g_rowptr[i], end = g_rowptr[i + 1];
        float di = dinv[i];
        float a[8] = {0,0,0,0,0,0,0,0};
        if (hw == 0) {
            uint4 u = __ldg((const uint4*)(lin + (size_t)i * HD) + hl);
            fma8(a, u, di * di);
        }
        int j0 = start;
        for (; j0 + 32 <= end; j0 += 32) {
            int r = g_er[j0 + lane];
            float dr = dinv[r];
#pragma unroll
            for (int k = 0; k < 16; k++) {
                int src = 2 * k + hw;
                int   rr = __shfl_sync(0xffffffffu, r, src);
                float nn = __shfl_sync(0xffffffffu, dr, src) * di;
                uint4 u = __ldg((const uint4*)(lin + (size_t)rr * HD) + hl);
                fma8(a, u, nn);
            }
        }
        if (j0 < end) {
            int cnt = end - j0;
            int r = 0; float dr = 0.f;
            if (lane < cnt) { r = g_er[j0 + lane]; dr = dinv[r]; }
            int pairs = (cnt + 1) >> 1;
            for (int k = 0; k < pairs; k++) {
                int src = 2 * k + hw;
                int   rr = __shfl_sync(0xffffffffu, r, src);
                float nn = __shfl_sync(0xffffffffu, dr, src) * di;
                if (src < cnt) {
                    uint4 u = __ldg((const uint4*)(lin + (size_t)rr * HD) + hl);
                    fma8(a, u, nn);
                }
            }
        }
#pragma unroll
        for (int j = 0; j < 8; j++)
            a[j] += __shfl_xor_sync(0xffffffffu, a[j], 16);
        if (hw == 0) {
            a[0] = fmaxf(a[0] + bb0.x, 0.f); a[1] = fmaxf(a[1] + bb0.y, 0.f);
            a[2] = fmaxf(a[2] + bb0.z, 0.f); a[3] = fmaxf(a[3] + bb0.w, 0.f);
            a[4] = fmaxf(a[4] + bb1.x, 0.f); a[5] = fmaxf(a[5] + bb1.y, 0.f);
            a[6] = fmaxf(a[6] + bb1.z, 0.f); a[7] = fmaxf(a[7] + bb1.w, 0.f);
            uint2 p0 = pack4(a[0], a[1], a[2], a[3]);
            uint2 p1 = pack4(a[4], a[5], a[6], a[7]);
            ((uint4*)(out + (size_t)i * HD))[hl] = make_uint4(p0.x, p0.y, p1.x, p1.y);
#pragma unroll
            for (int j = 0; j < 8; j++) { st[j] += a[j]; qt[j] += a[j] * a[j]; }
        }
    }
    if (sS) {
        if (hw == 0) {
#pragma unroll
            for (int j = 0; j < 8; j++) {
                atomicAdd(&ssum[hl * 8 + j], st[j]);
                atomicAdd(&ssq[hl * 8 + j],  qt[j]);
            }
        }
        __syncthreads();
        if (t < HD) { atomicAdd(&sS[t], ssum[t]); atomicAdd(&sQ[t], ssq[t]); }
    }
}

__global__ void __launch_bounds__(256) k_gather2(const __half* __restrict__ linC,
                                                 const __half* __restrict__ linO,
                                                 __half* __restrict__ outC,
                                                 __half* __restrict__ outO,
                                                 const float* __restrict__ dc,
                                                 const float* __restrict__ dd,
                                                 const float* __restrict__ bc,
                                                 const float* __restrict__ bo, int N,
                                                 float* sSc, float* sQc,
                                                 float* sSo, float* sQo) {
    __shared__ float red[4][HD];
    int t = threadIdx.x;
    for (int i = t; i < 4 * HD; i += blockDim.x) ((float*)red)[i] = 0.f;
    __syncthreads();
    int lane = t & 31, hw = lane >> 4, hl = lane & 15;
    int warpId = (blockIdx.x * blockDim.x + t) >> 5;
    int nW = (blockDim.x * gridDim.x) >> 5;
    float4 bc0 = ((const float4*)bc)[hl * 2 + 0];
    float4 bc1 = ((const float4*)bc)[hl * 2 + 1];
    float4 bo0 = ((const float4*)bo)[hl * 2 + 0];
    float4 bo1 = ((const float4*)bo)[hl * 2 + 1];
    float stc[8] = {0,0,0,0,0,0,0,0}, qtc[8] = {0,0,0,0,0,0,0,0};
    float sto[8] = {0,0,0,0,0,0,0,0}, qto[8] = {0,0,0,0,0,0,0,0};
    for (int i = warpId; i < N; i += nW) {
        int start = g_rowptr[i], end = g_rowptr[i + 1];
        float dci = rsqrtf(dc[i]), doi = rsqrtf(dd[i]);
        float aC[8] = {0,0,0,0,0,0,0,0}, aO[8] = {0,0,0,0,0,0,0,0};
        if (hw == 0) {
            uint4 u = __ldg((const uint4*)(linC + (size_t)i * HD) + hl);
            fma8(aC, u, dci * dci);
        } else {
            uint4 u = __ldg((const uint4*)(linO + (size_t)i * HD) + hl);
            fma8(aO, u, doi * doi);
        }
        int j0 = start;
        for (; j0 + 32 <= end; j0 += 32) {
            int jj = j0 + lane;
            int r = g_er[jj];
            int e = g_ee[jj];
            float wc = rsqrtf(dc[r]) * g_att0[e];
            float wo = rsqrtf(dd[r]) * g_att1[e];
#pragma unroll
            for (int k = 0; k < 16; k++) {
                int src = 2 * k + hw;
                int   rr = __shfl_sync(0xffffffffu, r, src);
                float nc = __shfl_sync(0xffffffffu, wc, src) * dci;
                float no = __shfl_sync(0xffffffffu, wo, src) * doi;
                uint4 uC = __ldg((const uint4*)(linC + (size_t)rr * HD) + hl);
                uint4 uO = __ldg((const uint4*)(linO + (size_t)rr * HD) + hl);
                fma8(aC, uC, nc);
                fma8(aO, uO, no);
            }
        }
        if (j0 < end) {
            int cnt = end - j0;
            int r = 0; float wc = 0.f, wo = 0.f;
            if (lane < cnt) {
                int jj = j0 + lane;
                r = g_er[jj];
                int e = g_ee[jj];
                wc = rsqrtf(dc[r]) * g_att0[e];
                wo = rsqrtf(dd[r]) * g_att1[e];
            }
            int pairs = (cnt + 1) >> 1;
            for (int k = 0; k < pairs; k++) {
                int src = 2 * k + hw;
                int   rr = __shfl_sync(0xffffffffu, r, src);
                float nc = __shfl_sync(0xffffffffu, wc, src) * dci;
                float no = __shfl_sync(0xffffffffu, wo, src) * doi;
                if (src < cnt) {
                    uint4 uC = __ldg((const uint4*)(linC + (size_t)rr * HD) + hl);
                    uint4 uO = __ldg((const uint4*)(linO + (size_t)rr * HD) + hl);
                    fma8(aC, uC, nc);
                    fma8(aO, uO, no);
                }
            }
        }
#pragma unroll
        for (int j = 0; j < 8; j++) {
            aC[j] += __shfl_xor_sync(0xffffffffu, aC[j], 16);
            aO[j] += __shfl_xor_sync(0xffffffffu, aO[j], 16);
        }
        if (hw == 0) {
            aC[0] = fmaxf(aC[0] + bc0.x, 0.f); aC[1] = fmaxf(aC[1] + bc0.y, 0.f);
            aC[2] = fmaxf(aC[2] + bc0.z, 0.f); aC[3] = fmaxf(aC[3] + bc0.w, 0.f);
            aC[4] = fmaxf(aC[4] + bc1.x, 0.f); aC[5] = fmaxf(aC[5] + bc1.y, 0.f);
            aC[6] = fmaxf(aC[6] + bc1.z, 0.f); aC[7] = fmaxf(aC[7] + bc1.w, 0.f);
            aO[0] = fmaxf(aO[0] + bo0.x, 0.f); aO[1] = fmaxf(aO[1] + bo0.y, 0.f);
            aO[2] = fmaxf(aO[2] + bo0.z, 0.f); aO[3] = fmaxf(aO[3] + bo0.w, 0.f);
            aO[4] = fmaxf(aO[4] + bo1.x, 0.f); aO[5] = fmaxf(aO[5] + bo1.y, 0.f);
            aO[6] = fmaxf(aO[6] + bo1.z, 0.f); aO[7] = fmaxf(aO[7] + bo1.w, 0.f);
            uint2 c0 = pack4(aC[0], aC[1], aC[2], aC[3]);
            uint2 c1 = pack4(aC[4], aC[5], aC[6], aC[7]);
            uint2 o0 = pack4(aO[0], aO[1], aO[2], aO[3]);
            uint2 o1 = pack4(aO[4], aO[5], aO[6], aO[7]);
            ((uint4*)(outC + (size_t)i * HD))[hl] = make_uint4(c0.x, c0.y, c1.x, c1.y);
            ((uint4*)(outO + (size_t)i * HD))[hl] = make_uint4(o0.x, o0.y, o1.x, o1.y);
#pragma unroll
            for (int j = 0; j < 8; j++) {
                stc[j] += aC[j]; qtc[j] += aC[j] * aC[j];
                sto[j] += aO[j]; qto[j] += aO[j] * aO[j];
            }
        }
    }
    if (hw == 0) {
#pragma unroll
        for (int j = 0; j < 8; j++) {
            atomicAdd(&red[0][hl * 8 + j], stc[j]);
            atomicAdd(&red[1][hl * 8 + j], qtc[j]);
            atomicAdd(&red[2][hl * 8 + j], sto[j]);
            atomicAdd(&red[3][hl * 8 + j], qto[j]);
        }
    }
    __syncthreads();
    if (t < HD) {
        atomicAdd(&sSc[t], red[0][t]); atomicAdd(&sQc[t], red[1][t]);
        atomicAdd(&sSo[t], red[2][t]); atomicAdd(&sQo[t], red[3][t]);
    }
}

// ---------------- attention (fp16 h in, fp16 xc/xo out) --------------------------
__global__ void k_att_node(const __half* __restrict__ h,
                           const float* __restrict__ Wna, const float* __restrict__ bna,
                           const float* __restrict__ Wea,
                           __half* __restrict__ xc, __half* __restrict__ xo, int N,
                           float* sSc, float* sQc, float* sSo, float* sQo) {
    __shared__ float Wc[HD * 6];
    __shared__ float red[4][HD];
    int t = threadIdx.x;
    for (int i = t; i < HD * 6; i += blockDim.x) {
        int k = i / 6, j = i % 6;
        float v;
        if (j < 2)      v = Wna[k * 2 + j];
        else if (j < 4) v = Wea[k * 2 + (j - 2)];
        else            v = Wea[(HD + k) * 2 + (j - 4)];
        Wc[i] = v;
    }
    for (int i = t; i < 4 * HD; i += blockDim.x) ((float*)red)[i] = 0.f;
    __syncthreads();
    int warps = (blockDim.x * gridDim.x) >> 5;
    int gw = (blockIdx.x * blockDim.x + t) >> 5;
    int l  = t & 31;
    float b0 = bna[0], b1 = bna[1];
    float sc[4]={0,0,0,0}, qc[4]={0,0,0,0}, so[4]={0,0,0,0}, qo[4]={0,0,0,0};
    for (int i = gw; i < N; i += warps) {
        float4 hv = unpack4(((const uint2*)(h + (size_t)i * HD))[l]);
        float p[6];
#pragma unroll
        for (int j = 0; j < 6; j++) {
            p[j] = hv.x * Wc[(4*l+0)*6 + j] + hv.y * Wc[(4*l+1)*6 + j]
                 + hv.z * Wc[(4*l+2)*6 + j] + hv.w * Wc[(4*l+3)*6 + j];
        }
#pragma unroll
        for (int off = 16; off; off >>= 1)
#pragma unroll
            for (int j = 0; j < 6; j++)
                p[j] += __shfl_xor_sync(0xffffffffu, p[j], off);
        float l0 = p[0] + b0, l1 = p[1] + b1;
        float m  = fmaxf(l0, l1);
        float e0 = expf(l0 - m), e1 = expf(l1 - m);
        float inv = 1.f / (e0 + e1);
        float a0 = e0 * inv, a1 = e1 * inv;
        float4 vc = make_float4(hv.x*a0, hv.y*a0, hv.z*a0, hv.w*a0);
        float4 vo = make_float4(hv.x*a1, hv.y*a1, hv.z*a1, hv.w*a1);
        ((uint2*)(xc + (size_t)i * HD))[l] = pack4(vc.x, vc.y, vc.z, vc.w);
        ((uint2*)(xo + (size_t)i * HD))[l] = pack4(vo.x, vo.y, vo.z, vo.w);
        sc[0]+=vc.x; qc[0]+=vc.x*vc.x; sc[1]+=vc.y; qc[1]+=vc.y*vc.y;
        sc[2]+=vc.z; qc[2]+=vc.z*vc.z; sc[3]+=vc.w; qc[3]+=vc.w*vc.w;
        so[0]+=vo.x; qo[0]+=vo.x*vo.x; so[1]+=vo.y; qo[1]+=vo.y*vo.y;
        so[2]+=vo.z; qo[2]+=vo.z*vo.z; so[3]+=vo.w; qo[3]+=vo.w*vo.w;
        if (l == 0) g_eanode[i] = make_float4(p[2], p[3], p[4], p[5]);
    }
#pragma unroll
    for (int j = 0; j < 4; j++) {
        atomicAdd(&red[0][l*4+j], sc[j]);
        atomicAdd(&red[1][l*4+j], qc[j]);
        atomicAdd(&red[2][l*4+j], so[j]);
        atomicAdd(&red[3][l*4+j], qo[j]);
    }
    __syncthreads();
    if (t < HD) {
        atomicAdd(&sSc[t], red[0][t]); atomicAdd(&sQc[t], red[1][t]);
        atomicAdd(&sSo[t], red[2][t]); atomicAdd(&sQo[t], red[3][t]);
    }
}

__global__ void k_att_edge(const int* __restrict__ row, const int* __restrict__ col,
                           const float* __restrict__ bea, int E) {
    int e = blockIdx.x * blockDim.x + threadIdx.x;
    if (e >= E) return;
    int r = row[e], c = col[e];
    float4 tr = g_eanode[r], tc = g_eanode[c];
    float l0 = tr.x + tc.z + bea[0];
    float l1 = tr.y + tc.w + bea[1];
    float m  = fmaxf(l0, l1);
    float e0 = expf(l0 - m), e1 = expf(l1 - m);
    float inv = 1.f / (e0 + e1);
    float a0 = e0 * inv, a1 = e1 * inv;
    g_att0[e] = a0; g_att1[e] = a1;
    atomicAdd(&g_degc[r], a0);
    atomicAdd(&g_dego[r], a1);
}

__global__ void k_permadd_stats(const __half* __restrict__ xc, const __half* __restrict__ xo,
                                const int* __restrict__ perm, __half* __restrict__ z, int N,
                                float* __restrict__ sS, float* __restrict__ sQ) {
    __shared__ float ssum[HD], ssq[HD];
    int t = threadIdx.x;
    if (t < HD) { ssum[t] = 0.f; ssq[t] = 0.f; }
    __syncthreads();
    int total  = N * HD4;
    int stride = blockDim.x * gridDim.x;
    int idx    = blockIdx.x * blockDim.x + t;
    int fb     = (idx & 31) * 4;
    float a0=0,a1=0,a2=0,a3=0,q0=0,q1=0,q2=0,q3=0;
    for (; idx < total; idx += stride) {
        int i = idx >> 5, l = idx & 31;
        int p = perm[i];
        float4 a = unpack4(((const uint2*)(xc + (size_t)p * HD))[l]);
        float4 b = unpack4(((const uint2*)xo)[idx]);
        a.x += b.x; a.y += b.y; a.z += b.z; a.w += b.w;
        ((uint2*)z)[idx] = pack4(a.x, a.y, a.z, a.w);
        a0 += a.x; q0 += a.x*a.x; a1 += a.y; q1 += a.y*a.y;
        a2 += a.z; q2 += a.z*a.z; a3 += a.w; q3 += a.w*a.w;
    }
    atomicAdd(&ssum[fb+0], a0); atomicAdd(&ssq[fb+0], q0);
    atomicAdd(&ssum[fb+1], a1); atomicAdd(&ssq[fb+1], q1);
    atomicAdd(&ssum[fb+2], a2); atomicAdd(&ssq[fb+2], q2);
    atomicAdd(&ssum[fb+3], a3); atomicAdd(&ssq[fb+3], q3);
    __syncthreads();
    if (t < HD) { atomicAdd(&sS[t], ssum[t]); atomicAdd(&sQ[t], ssq[t]); }
}

// ---------------- [N,128]x[128,10] + log_softmax (fp16 Z), batched --------------
__global__ void k_gemm2_lsm(LJobs jobs, int N, float invN) {
    __shared__ float Ws[HD * 10];
    __shared__ float bs[10];
    __shared__ float scaleSh[HD], tshSh[HD];
    const LJob J = jobs.j[blockIdx.y];
    int t = threadIdx.x;
    if (t < HD) {
        float mu  = J.sSin[t] * invN;
        float var = fmaxf(J.sQin[t] * invN - mu * mu, 0.f);
        float rs  = rsqrtf(var + 1e-5f);
        scaleSh[t] = rs;
        tshSh[t]   = 1e-4f / rs - mu;
    }
    __syncthreads();
    for (int i = t; i < HD * 10; i += blockDim.x)
        Ws[i] = scaleSh[i / 10] * J.W[i];
    __syncthreads();
    if (t < 160) {
        int j = t / 16, seg = t % 16;
        float part = 0.f;
#pragma unroll
        for (int k = 0; k < 8; k++) {
            int kk = seg * 8 + k;
            part += tshSh[kk] * Ws[kk * 10 + j];
        }
#pragma unroll
        for (int off = 8; off; off >>= 1)
            part += __shfl_down_sync(0xffffffffu, part, off, 16);
        if (seg == 0) bs[j] = J.b[j] + part;
    }
    __syncthreads();
    int warps = (blockDim.x * gridDim.x) >> 5;
    int gw = (blockIdx.x * blockDim.x + t) >> 5;
    int l  = t & 31;
    for (int i = gw; i < N; i += warps) {
        float4 z = unpack4(((const uint2*)(J.Z + (size_t)i * HD))[l]);
        float p[10];
#pragma unroll
        for (int j = 0; j < 10; j++) {
            p[j] = z.x * Ws[(4*l+0)*10 + j] + z.y * Ws[(4*l+1)*10 + j]
                 + z.z * Ws[(4*l+2)*10 + j] + z.w * Ws[(4*l+3)*10 + j];
        }
#pragma unroll
        for (int off = 16; off; off >>= 1)
#pragma unroll
            for (int j = 0; j < 10; j++)
                p[j] += __shfl_xor_sync(0xffffffffu, p[j], off);
        float m = -1e30f;
#pragma unroll
        for (int j = 0; j < 10; j++) { p[j] += bs[j]; m = fmaxf(m, p[j]); }
        float s = 0.f;
#pragma unroll
        for (int j = 0; j < 10; j++) s += expf(p[j] - m);
        float lse = m + logf(s);
        if (l < 10) J.out[(size_t)i * 10 + l] = p[l] - lse;
    }
}

// ---------------- host orchestration ------------------------------------------------
extern "C" void kernel_launch(void* const* d_in, const int* in_sizes, int n_in,
                              void* d_out, int out_size) {
    const float* x      = (const float*)d_in[0];
    const int*   ei     = (const int*)  d_in[1];
    const int*   perm   = (const int*)  d_in[2];
    const float* W_feat = (const float*)d_in[3];
    const float* b_feat = (const float*)d_in[4];
    const float* W_convs= (const float*)d_in[5];
    const float* b_convs= (const float*)d_in[6];
    const float* W_ea   = (const float*)d_in[7];
    const float* b_ea   = (const float*)d_in[8];
    const float* W_na   = (const float*)d_in[9];
    const float* b_na   = (const float*)d_in[10];
    const float* W_ctx  = (const float*)d_in[11];
    const float* b_ctx  = (const float*)d_in[12];
    const float* W_obj  = (const float*)d_in[13];
    const float* b_obj  = (const float*)d_in[14];
    const float* W_fc1  = (const float*)d_in[15];
    const float* b_fc1  = (const float*)d_in[16];
    const float* W_fc2  = (const float*)d_in[17];
    const float* b_fc2  = (const float*)d_in[18];

    int N = in_sizes[0] / HD;
    int E = in_sizes[1] / 2;
    const int* row = ei;
    const int* col = ei + E;
    float* out = (float*)d_out;

    static cudaStream_t sB = nullptr;
    static cudaEvent_t ev0, evCSR, ev1, evAE;
    if (!sB) {
        cudaStreamCreateWithFlags(&sB, cudaStreamNonBlocking);
        cudaEventCreateWithFlags(&ev0,   cudaEventDisableTiming);
        cudaEventCreateWithFlags(&evCSR, cudaEventDisableTiming);
        cudaEventCreateWithFlags(&ev1,   cudaEventDisableTiming);
        cudaEventCreateWithFlags(&evAE,  cudaEventDisableTiming);
    }

    float* Bbase = nullptr;
    cudaGetSymbolAddress((void**)&Bbase, g_B);
    __half* H0 = (__half*)(Bbase + 0 * (size_t)MAXN * HD);
    __half* H1 = (__half*)(Bbase + 1 * (size_t)MAXN * HD);
    __half* H2 = (__half*)(Bbase + 2 * (size_t)MAXN * HD);
    __half* H3 = (__half*)(Bbase + 3 * (size_t)MAXN * HD);
    __half* H4 = (__half*)(Bbase + 4 * (size_t)MAXN * HD);
    __half* H5 = (__half*)(Bbase + 5 * (size_t)MAXN * HD);
    float *degup, *degcp, *degop, *statsp;
    int *cnt2p;
    cudaGetSymbolAddress((void**)&degup,  g_degu);
    cudaGetSymbolAddress((void**)&degcp,  g_degc);
    cudaGetSymbolAddress((void**)&degop,  g_dego);
    cudaGetSymbolAddress((void**)&statsp, g_stats);
    cudaGetSymbolAddress((void**)&cnt2p,  g_cnt2);
    auto S = [&](int i) { return statsp + i * HD; };
    auto Q = [&](int i) { return statsp + (NSLOT + i) * HD; };

    const int gemm_smem = 2 * 128 * AS * (int)sizeof(__half);
    cudaFuncSetAttribute(k_gemm_tc, cudaFuncAttributeMaxDynamicSharedMemorySize, gemm_smem);

    int gbGemm = (N + 127) / 128;
    int gbE    = (E + 255) / 256;
    int nb     = (N + 1023) / 1024;
    float invN = 1.f / (float)N;

    auto gemm1 = [&](const void* X, __half* Y, const float* W, const float* b,
                     int sin, int sout, int relu, int inHalf) {
        GJobs js{};
        js.j[0] = {X, Y, W, b, S(sin), Q(sin),
                   sout >= 0 ? S(sout) : nullptr, sout >= 0 ? Q(sout) : nullptr};
        k_gemm_tc<<<dim3(gbGemm, 1), 512, gemm_smem>>>(js, N, relu, inHalf, invN);
    };

    // ---- fork: CSR build on side stream ----
    cudaEventRecord(ev0, 0);
    cudaStreamWaitEvent(sB, ev0, 0);
    cudaMemsetAsync(cnt2p, 0, 2 * (size_t)MAXN * sizeof(int), sB);
    k_hist<<<gbE, 256, 0, sB>>>(row, col, E);
    k_scan1<<<nb, 1024, 0, sB>>>(N);
    k_scanfin<<<nb, 1024, 0, sB>>>(N, nb);
    k_fillcsr<<<gbE, 256, 0, sB>>>(row, col, E);
    cudaEventRecord(evCSR, sB);

    // main
    cudaMemsetAsync(statsp, 0, 2 * NSLOT * HD * sizeof(float), 0);
    k_stats<<<512, 256>>>(x, N, S(0), Q(0));
    gemm1(x, H2, W_feat, b_feat, 0, 1, 1, 0);
    gemm1(H2, H1, W_convs + 0 * HD * HD, nullptr, 1, -1, 0, 1);

    cudaStreamWaitEvent(0, evCSR, 0);
    k_gather<<<1024, 256>>>(H1, H0, degup, b_convs + 0 * HD, N, S(2), Q(2));
    gemm1(H0, H1, W_convs + 1 * HD * HD, nullptr, 2, -1, 0, 1);
    k_gather<<<1024, 256>>>(H1, H2, degup, b_convs + 1 * HD, N, S(3), Q(3));
    gemm1(H2, H1, W_convs + 2 * HD * HD, nullptr, 3, -1, 0, 1);
    k_gather<<<1024, 256>>>(H1, H0, degup, b_convs + 2 * HD, N, nullptr, nullptr);

    // attention
    k_att_node<<<256, 256>>>(H0, W_na, b_na, W_ea, H2, H3, N, S(4), Q(4), S(5), Q(5));

    cudaEventRecord(ev1, 0);
    cudaStreamWaitEvent(sB, ev1, 0);
    k_att_edge<<<gbE, 256, 0, sB>>>(row, col, b_ea, E);
    cudaEventRecord(evAE, sB);

    {
        GJobs js{};
        js.j[0] = {H2, H1, W_ctx, nullptr, S(4), Q(4), nullptr, nullptr};
        js.j[1] = {H3, H5, W_obj, nullptr, S(5), Q(5), nullptr, nullptr};
        k_gemm_tc<<<dim3(gbGemm, 2), 512, gemm_smem>>>(js, N, 0, 1, invN);
    }
    cudaStreamWaitEvent(0, evAE, 0);
    k_gather2<<<1024, 256>>>(H1, H5, H4, H3, degcp, degop, b_ctx, b_obj, N,
                             S(6), Q(6), S(7), Q(7));

    k_permadd_stats<<<256, 256>>>(H4, H3, perm, H1, N, S(11), Q(11));

    {
        GJobs js{};
        js.j[0] = {H4, H0, W_fc1 + 0 * HD * HD, b_fc1 + 0 * HD, S(6),  Q(6),  S(8),  Q(8)};
        js.j[1] = {H3, H5, W_fc1 + 1 * HD * HD, b_fc1 + 1 * HD, S(7),  Q(7),  S(9),  Q(9)};
        js.j[2] = {H1, H2, W_fc1 + 2 * HD * HD, b_fc1 + 2 * HD, S(11), Q(11), S(10), Q(10)};
        k_gemm_tc<<<dim3(gbGemm, 3), 512, gemm_smem>>>(js, N, 1, 1, invN);
    }
    {
        LJobs js{};
        js.j[0] = {H0, out,                      W_fc2 + 0 * HD * 10, b_fc2 + 0 * 10, S(8),  Q(8)};
        js.j[1] = {H5, out + (size_t)N * 10,     W_fc2 + 1 * HD * 10, b_fc2 + 1 * 10, S(9),  Q(9)};
        js.j[2] = {H2, out + (size_t)2 * N * 10, W_fc2 + 2 * HD * 10, b_fc2 + 2 * 10, S(10), Q(10)};
        k_gemm2_lsm<<<dim3(512, 3), 256>>>(js, N, invN);
    }
}